// round 9
// baseline (speedup 1.0000x reference)
#include <cuda_runtime.h>
#include <cuda_bf16.h>
#include <cstdint>
#include <cstddef>

// ---------------------------------------------------------------------------
// Hyena operator: B=2, L=4096, D=1024, ORDER=2, OD=3072
// Round 7: 2-CTA/SM GEMM pipelines (2-stage cp.async), filter path as GEMM,
// 1024-thread FFTs. hfft placed as launch #4 for profiler visibility.
// ---------------------------------------------------------------------------

#define LSEQ 4096
#define NF   8192
#define DDIM 1024
#define ODIM 3072
#define BSZ  2
#define NPAIR 512
#define FFT_THREADS 1024
#define PADI(i) ((i) + ((i) >> 5))
#define SM_HALF 8448
#define FFT_SMEM (2 * SM_HALF * 4)

// Scratch (device .bss — allocation-free)
__device__ float  g_res[(size_t)BSZ * ODIM * LSEQ];
__device__ float  g_cv [(size_t)BSZ * ODIM * LSEQ];
__device__ float  g_h  [(size_t)2   * DDIM * LSEQ];
__device__ float  g_sact[(size_t)LSEQ * 64];
__device__ float2 g_A  [(size_t)2 * NPAIR * NF];
__device__ float2 g_B  [(size_t)2 * NPAIR * NF];
__device__ float2 g_tw [NF];
__device__ unsigned short g_refl[NF];
// packed bf16 hi/lo operands (uint32 = 2 bf16)
__device__ uint32_t g_wh[(size_t)ODIM * DDIM / 2];
__device__ uint32_t g_wl[(size_t)ODIM * DDIM / 2];
__device__ uint32_t g_uh[(size_t)BSZ * LSEQ * DDIM / 2];
__device__ uint32_t g_ul[(size_t)BSZ * LSEQ * DDIM / 2];
__device__ uint32_t g_oh[(size_t)DDIM * DDIM / 2];
__device__ uint32_t g_ol[(size_t)DDIM * DDIM / 2];
__device__ uint32_t g_vh[(size_t)BSZ * DDIM * LSEQ / 2];
__device__ uint32_t g_vl[(size_t)BSZ * DDIM * LSEQ / 2];

// ---------------------------------------------------------------------------
__device__ __forceinline__ uint32_t smem_u32(const void* p) {
    uint32_t a;
    asm("{ .reg .u64 t; cvta.to.shared.u64 t, %1; cvt.u32.u64 %0, t; }" : "=r"(a) : "l"(p));
    return a;
}

#define LDSM_X4(r0, r1, r2, r3, addr) \
    asm volatile("ldmatrix.sync.aligned.m8n8.x4.shared.b16 {%0,%1,%2,%3}, [%4];" \
                 : "=r"(r0), "=r"(r1), "=r"(r2), "=r"(r3) : "r"(addr))
#define LDSM_X4_T(r0, r1, r2, r3, addr) \
    asm volatile("ldmatrix.sync.aligned.m8n8.x4.trans.shared.b16 {%0,%1,%2,%3}, [%4];" \
                 : "=r"(r0), "=r"(r1), "=r"(r2), "=r"(r3) : "r"(addr))
#define LDSM_X2(r0, r1, addr) \
    asm volatile("ldmatrix.sync.aligned.m8n8.x2.shared.b16 {%0,%1}, [%2];" \
                 : "=r"(r0), "=r"(r1) : "r"(addr))
#define CP_ASYNC16(dst, src) \
    asm volatile("cp.async.cg.shared.global [%0], [%1], 16;" :: "r"(dst), "l"(src))
#define CP_COMMIT() asm volatile("cp.async.commit_group;" ::: "memory")
#define CP_WAIT1()  asm volatile("cp.async.wait_group 1;" ::: "memory")

__device__ __forceinline__ void mma_bf16(float* c, const uint32_t* a, const uint32_t* b) {
    asm volatile(
        "mma.sync.aligned.m16n8k16.row.col.f32.bf16.bf16.f32 "
        "{%0,%1,%2,%3}, {%4,%5,%6,%7}, {%8,%9}, {%0,%1,%2,%3};"
        : "+f"(c[0]), "+f"(c[1]), "+f"(c[2]), "+f"(c[3])
        : "r"(a[0]), "r"(a[1]), "r"(a[2]), "r"(a[3]), "r"(b[0]), "r"(b[1]));
}

__device__ __forceinline__ uint32_t pack_hi(float x, float y) {
    __nv_bfloat16 hx = __float2bfloat16(x);
    __nv_bfloat16 hy = __float2bfloat16(y);
    return (uint32_t)__bfloat16_as_ushort(hx) | ((uint32_t)__bfloat16_as_ushort(hy) << 16);
}
__device__ __forceinline__ uint32_t pack_lo(float x, float y) {
    __nv_bfloat16 hx = __float2bfloat16(x);
    __nv_bfloat16 hy = __float2bfloat16(y);
    __nv_bfloat16 lx = __float2bfloat16(x - __bfloat162float(hx));
    __nv_bfloat16 ly = __float2bfloat16(y - __bfloat162float(hy));
    return (uint32_t)__bfloat16_as_ushort(lx) | ((uint32_t)__bfloat16_as_ushort(ly) << 16);
}

// fp32 -> packed bf16 hi/lo
__global__ void cvt_split(const float* __restrict__ src, uint32_t* __restrict__ hi,
                          uint32_t* __restrict__ lo, int n2) {
    int i = blockIdx.x * 256 + threadIdx.x;
    if (i < n2) {
        float2 v = ((const float2*)src)[i];
        hi[i] = pack_hi(v.x, v.y);
        lo[i] = pack_lo(v.x, v.y);
    }
}

// ---------------------------------------------------------------------------
// gemm_in: g_res[b,od,l] = sum_d w_in[od,d]*u[b,l,d] + b_in[od]
// CTA 128x128, 8 warps (2x4), BK=32, 2-stage cp.async, 2 CTAs/SM.
#define GI_STAGE 40960
#define GI_SMEM  (2 * GI_STAGE)

__global__ __launch_bounds__(256, 2) void gemm_in_mma(const float* __restrict__ bias)
{
    extern __shared__ char smem[];
    const uint32_t sb = smem_u32(smem);
    const int tid  = threadIdx.x;
    const int lane = tid & 31;
    const int wid  = tid >> 5;
    const int warp_m = wid >> 2;
    const int warp_n = wid & 3;

    const int b  = blockIdx.z;
    const int m0 = blockIdx.y * 128;   // od
    const int n0 = blockIdx.x * 128;   // l
    float* C = g_res + (size_t)b * ODIM * LSEQ;

    const int tile = tid >> 6;
    const int tloc = tid & 63;
    const char* gbase;
    if      (tile == 0) gbase = (const char*)g_wh + (size_t)m0 * 2048;
    else if (tile == 1) gbase = (const char*)g_wl + (size_t)m0 * 2048;
    else if (tile == 2) gbase = (const char*)g_uh + (size_t)(b * LSEQ + n0) * 2048;
    else                gbase = (const char*)g_ul + (size_t)(b * LSEQ + n0) * 2048;

    float acc[4][4][4];
    #pragma unroll
    for (int i = 0; i < 4; i++)
        #pragma unroll
        for (int j = 0; j < 4; j++)
            #pragma unroll
            for (int r = 0; r < 4; r++) acc[i][j][r] = 0.0f;

    const int a_off = ((lane & 7) + ((lane & 8) ? 8 : 0)) * 80 + ((lane & 16) ? 16 : 0);
    const int b_off = (lane & 7) * 80 + ((lane & 8) ? 16 : 0);

    #pragma unroll
    for (int p = 0; p < 2; p++) {
        #pragma unroll
        for (int o = 0; o < 8; o++) {
            int idx = tloc + o * 64, row = idx >> 2, c = idx & 3;
            uint32_t dst = sb + p * GI_STAGE + tile * 10240 + row * 80 + c * 16;
            CP_ASYNC16(dst, gbase + (size_t)row * 2048 + p * 64 + c * 16);
        }
        CP_COMMIT();
    }

    for (int ch = 0; ch < 32; ch++) {
        CP_WAIT1();
        __syncthreads();
        const uint32_t sbase = sb + (ch & 1) * GI_STAGE;

        #pragma unroll
        for (int k16 = 0; k16 < 2; k16++) {
            uint32_t bh[4][2], bl[4][2];
            #pragma unroll
            for (int j = 0; j < 4; j++) {
                uint32_t rb = sbase + 20480 + (warp_n * 32 + j * 8) * 80 + k16 * 32 + b_off;
                LDSM_X2(bh[j][0], bh[j][1], rb);
                LDSM_X2(bl[j][0], bl[j][1], rb + 10240);
            }
            #pragma unroll
            for (int i = 0; i < 4; i++) {
                uint32_t ah[4], al[4];
                uint32_t ra = sbase + (warp_m * 64 + i * 16) * 80 + k16 * 32 + a_off;
                LDSM_X4(ah[0], ah[1], ah[2], ah[3], ra);
                LDSM_X4(al[0], al[1], al[2], al[3], ra + 10240);
                #pragma unroll
                for (int j = 0; j < 4; j++) {
                    mma_bf16(acc[i][j], ah, bh[j]);
                    mma_bf16(acc[i][j], ah, bl[j]);
                    mma_bf16(acc[i][j], al, bh[j]);
                }
            }
        }

        __syncthreads();
        if (ch + 2 < 32) {
            #pragma unroll
            for (int o = 0; o < 8; o++) {
                int idx = tloc + o * 64, row = idx >> 2, c = idx & 3;
                uint32_t dst = sb + (ch & 1) * GI_STAGE + tile * 10240 + row * 80 + c * 16;
                CP_ASYNC16(dst, gbase + (size_t)row * 2048 + (ch + 2) * 64 + c * 16);
            }
        }
        CP_COMMIT();
    }

    const int g = lane >> 2;
    const int t = lane & 3;
    #pragma unroll
    for (int i = 0; i < 4; i++) {
        int od0 = m0 + warp_m * 64 + i * 16 + g;
        float bv0 = bias[od0];
        float bv1 = bias[od0 + 8];
        #pragma unroll
        for (int j = 0; j < 4; j++) {
            int l = n0 + warp_n * 32 + j * 8 + t * 2;
            *(float2*)&C[(size_t)od0 * LSEQ + l] =
                make_float2(acc[i][j][0] + bv0, acc[i][j][1] + bv0);
            *(float2*)&C[(size_t)(od0 + 8) * LSEQ + l] =
                make_float2(acc[i][j][2] + bv1, acc[i][j][3] + bv1);
        }
    }
}

// ---------------------------------------------------------------------------
// gemm_out: out[b,l,e] = sum_d v[b,d,l]*w_out[e,d] + b_out[e]
#define GO_A_LO  8704
#define GO_B_HI  17408
#define GO_B_LO  27648
#define GO_STAGE 37888
#define GO_SMEM  (2 * GO_STAGE)

__global__ __launch_bounds__(256, 2) void gemm_out_mma(const float* __restrict__ bias,
                                                       float* __restrict__ O)
{
    extern __shared__ char smem[];
    const uint32_t sb = smem_u32(smem);
    const int tid  = threadIdx.x;
    const int lane = tid & 31;
    const int wid  = tid >> 5;
    const int warp_m = wid >> 2;
    const int warp_n = wid & 3;

    const int b  = blockIdx.z;
    const int m0 = blockIdx.y * 128;   // l
    const int n0 = blockIdx.x * 128;   // e
    float* C = O + (size_t)b * LSEQ * DDIM;

    const int tile = tid >> 6;     // 0:v_hi 1:v_lo 2:wo_hi 3:wo_lo
    const int tloc = tid & 63;
    const char* gbase;
    if      (tile == 0) gbase = (const char*)g_vh + (size_t)(b * DDIM) * 8192 + (size_t)m0 * 2;
    else if (tile == 1) gbase = (const char*)g_vl + (size_t)(b * DDIM) * 8192 + (size_t)m0 * 2;
    else if (tile == 2) gbase = (const char*)g_oh + (size_t)n0 * 2048;
    else                gbase = (const char*)g_ol + (size_t)n0 * 2048;

    float acc[4][4][4];
    #pragma unroll
    for (int i = 0; i < 4; i++)
        #pragma unroll
        for (int j = 0; j < 4; j++)
            #pragma unroll
            for (int r = 0; r < 4; r++) acc[i][j][r] = 0.0f;

    const int at_off = ((lane & 7) + ((lane & 16) ? 8 : 0)) * 272 + ((lane & 8) ? 16 : 0);
    const int b_off  = (lane & 7) * 80 + ((lane & 8) ? 16 : 0);

    #pragma unroll
    for (int p = 0; p < 2; p++) {
        if (tile < 2) {
            #pragma unroll
            for (int o = 0; o < 8; o++) {
                int idx = tloc + o * 64, row = idx >> 4, c = idx & 15;
                uint32_t dst = sb + p * GO_STAGE + tile * GO_A_LO + row * 272 + c * 16;
                CP_ASYNC16(dst, gbase + (size_t)(p * 32 + row) * 8192 + c * 16);
            }
        } else {
            #pragma unroll
            for (int o = 0; o < 8; o++) {
                int idx = tloc + o * 64, row = idx >> 2, c = idx & 3;
                uint32_t dst = sb + p * GO_STAGE + GO_B_HI + (tile - 2) * 10240 + row * 80 + c * 16;
                CP_ASYNC16(dst, gbase + (size_t)row * 2048 + p * 64 + c * 16);
            }
        }
        CP_COMMIT();
    }

    for (int ch = 0; ch < 32; ch++) {
        CP_WAIT1();
        __syncthreads();
        const uint32_t sbase = sb + (ch & 1) * GO_STAGE;

        #pragma unroll
        for (int k16 = 0; k16 < 2; k16++) {
            uint32_t bh[4][2], bl[4][2];
            #pragma unroll
            for (int j = 0; j < 4; j++) {
                uint32_t rb = sbase + GO_B_HI + (warp_n * 32 + j * 8) * 80 + k16 * 32 + b_off;
                LDSM_X2(bh[j][0], bh[j][1], rb);
                LDSM_X2(bl[j][0], bl[j][1], rb + 10240);
            }
            #pragma unroll
            for (int i = 0; i < 4; i++) {
                uint32_t ah[4], al[4];
                uint32_t ra = sbase + k16 * 16 * 272 + (warp_m * 64 + i * 16) * 2 + at_off;
                LDSM_X4_T(ah[0], ah[1], ah[2], ah[3], ra);
                LDSM_X4_T(al[0], al[1], al[2], al[3], ra + GO_A_LO);
                #pragma unroll
                for (int j = 0; j < 4; j++) {
                    mma_bf16(acc[i][j], ah, bh[j]);
                    mma_bf16(acc[i][j], ah, bl[j]);
                    mma_bf16(acc[i][j], al, bh[j]);
                }
            }
        }

        __syncthreads();
        if (ch + 2 < 32) {
            if (tile < 2) {
                #pragma unroll
                for (int o = 0; o < 8; o++) {
                    int idx = tloc + o * 64, row = idx >> 4, c = idx & 15;
                    uint32_t dst = sb + (ch & 1) * GO_STAGE + tile * GO_A_LO + row * 272 + c * 16;
                    CP_ASYNC16(dst, gbase + (size_t)((ch + 2) * 32 + row) * 8192 + c * 16);
                }
            } else {
                #pragma unroll
                for (int o = 0; o < 8; o++) {
                    int idx = tloc + o * 64, row = idx >> 2, c = idx & 3;
                    uint32_t dst = sb + (ch & 1) * GO_STAGE + GO_B_HI + (tile - 2) * 10240 + row * 80 + c * 16;
                    CP_ASYNC16(dst, gbase + (size_t)row * 2048 + (ch + 2) * 64 + c * 16);
                }
            }
        }
        CP_COMMIT();
    }

    const int g = lane >> 2;
    const int t = lane & 3;
    #pragma unroll
    for (int j = 0; j < 4; j++) {
        int e = n0 + warp_n * 32 + j * 8 + t * 2;
        float bb0 = bias[e];
        float bb1 = bias[e + 1];
        #pragma unroll
        for (int i = 0; i < 4; i++) {
            int l = m0 + warp_m * 64 + i * 16 + g;
            *(float2*)&C[(size_t)l * DDIM + e] =
                make_float2(acc[i][j][0] + bb0, acc[i][j][1] + bb1);
            *(float2*)&C[(size_t)(l + 8) * DDIM + e] =
                make_float2(acc[i][j][2] + bb0, acc[i][j][3] + bb1);
        }
    }
}

// ---------------------------------------------------------------------------
// digit-reversed slot <-> frequency maps (DIF ordering of this implementation)
__device__ __forceinline__ int slot_to_freq(int p) {
    int k = 0;
    k |= ((p >> 12) & 1) << 0;
    k |= ((p >> 10) & 1) << 1;
    k |= ((p >> 11) & 1) << 2;
    k |= ((p >>  8) & 1) << 3;
    k |= ((p >>  9) & 1) << 4;
    k |= ((p >>  6) & 1) << 5;
    k |= ((p >>  7) & 1) << 6;
    k |= ((p >>  4) & 1) << 7;
    k |= ((p >>  5) & 1) << 8;
    k |= ((p >>  2) & 1) << 9;
    k |= ((p >>  3) & 1) << 10;
    k |= ((p >>  0) & 1) << 11;
    k |= ((p >>  1) & 1) << 12;
    return k;
}
__device__ __forceinline__ int freq_to_slot(int k) {
    int p = 0;
    p |= ((k >>  0) & 1) << 12;
    p |= ((k >>  1) & 1) << 10;
    p |= ((k >>  2) & 1) << 11;
    p |= ((k >>  3) & 1) << 8;
    p |= ((k >>  4) & 1) << 9;
    p |= ((k >>  5) & 1) << 6;
    p |= ((k >>  6) & 1) << 7;
    p |= ((k >>  7) & 1) << 4;
    p |= ((k >>  8) & 1) << 5;
    p |= ((k >>  9) & 1) << 2;
    p |= ((k >> 10) & 1) << 3;
    p |= ((k >> 11) & 1) << 0;
    p |= ((k >> 12) & 1) << 1;
    return p;
}

__global__ void init_kernel() {
    int i = blockIdx.x * blockDim.x + threadIdx.x;
    if (i < NF) {
        double ang = -2.0 * 3.141592653589793238462643 * (double)i / (double)NF;
        g_tw[i] = make_float2((float)cos(ang), (float)sin(ang));
        int k  = slot_to_freq(i);
        int kp = (NF - k) & (NF - 1);
        g_refl[i] = (unsigned short)freq_to_slot(kp);
    }
}

// ---------------------------------------------------------------------------
// Filter path: sact[l][u] = sin(FREQ * (pe(l) . w1[u] + b1[u]))
__global__ __launch_bounds__(256) void sact_kernel(
    const float* __restrict__ w1, const float* __restrict__ b1)
{
    int idx = blockIdx.x * 256 + threadIdx.x;   // l*64 + u
    int l = idx >> 6;
    int u = idx & 63;
    float t = (float)l * (1.0f / (float)(LSEQ - 1));
    float z = b1[u];
    #pragma unroll
    for (int j = 0; j < 33; j++) z += sinf(t * (float)j * 10.0f) * w1[u * 33 + j];
    g_sact[idx] = sinf(10.0f * z);
}

// filter GEMM: g_h[o][l] = ((sum_k w2[o,k]*sact[l,k] + b2[o]) * exp(-exp(fd[o])*t_l)
//                           + fb[o]) / L.   Tile 128(o) x 128(l), K=64.
__global__ __launch_bounds__(256) void filter_gemm(
    const float* __restrict__ w2, const float* __restrict__ b2,
    const float* __restrict__ fb, const float* __restrict__ fd)
{
    extern __shared__ float fsm[];
    float (*As)[128] = (float(*)[128])fsm;              // [k][o]
    float (*Bs)[128] = (float(*)[128])(fsm + 64 * 128); // [k][l]
    const int o0 = blockIdx.y * 128;
    const int l0 = blockIdx.x * 128;
    const int tid = threadIdx.x;
    const int tm = tid >> 4;       // o micro
    const int tn = tid & 15;       // l micro
    const int lrow = tid >> 1;
    const int lk   = (tid & 1) * 32;

    #pragma unroll
    for (int f = 0; f < 8; f++) {
        float4 a = *(const float4*)&w2[(size_t)(o0 + lrow) * 64 + lk + f * 4];
        As[lk + f * 4 + 0][lrow] = a.x; As[lk + f * 4 + 1][lrow] = a.y;
        As[lk + f * 4 + 2][lrow] = a.z; As[lk + f * 4 + 3][lrow] = a.w;
        float4 s = *(const float4*)&g_sact[(size_t)(l0 + lrow) * 64 + lk + f * 4];
        Bs[lk + f * 4 + 0][lrow] = s.x; Bs[lk + f * 4 + 1][lrow] = s.y;
        Bs[lk + f * 4 + 2][lrow] = s.z; Bs[lk + f * 4 + 3][lrow] = s.w;
    }
    __syncthreads();

    float acc[8][8];
    #pragma unroll
    for (int i = 0; i < 8; i++)
        #pragma unroll
        for (int j = 0; j < 8; j++) acc[i][j] = 0.0f;

    #pragma unroll
    for (int k = 0; k < 64; k++) {
        float4 ra0 = *(const float4*)&As[k][tm * 8];
        float4 ra1 = *(const float4*)&As[k][tm * 8 + 4];
        float4 rb0 = *(const float4*)&Bs[k][tn * 8];
        float4 rb1 = *(const float4*)&Bs[k][tn * 8 + 4];
        float ra[8] = {ra0.x, ra0.y, ra0.z, ra0.w, ra1.x, ra1.y, ra1.z, ra1.w};
        float rb[8] = {rb0.x, rb0.y, rb0.z, rb0.w, rb1.x, rb1.y, rb1.z, rb1.w};
        #pragma unroll
        for (int i = 0; i < 8; i++)
            #pragma unroll
            for (int j = 0; j < 8; j++) acc[i][j] += ra[i] * rb[j];
    }

    #pragma unroll
    for (int i = 0; i < 8; i++) {
        int o = o0 + tm * 8 + i;
        float ed  = expf(fd[o]);
        float bb  = b2[o];
        float fbo = fb[o];
        float v[8];
        #pragma unroll
        for (int j = 0; j < 8; j++) {
            int l = l0 + tn * 8 + j;
            float t = (float)l * (1.0f / (float)(LSEQ - 1));
            v[j] = ((acc[i][j] + bb) * expf(-ed * t) + fbo) * (1.0f / (float)LSEQ);
        }
        *(float4*)&g_h[(size_t)o * LSEQ + l0 + tn * 8]     = make_float4(v[0], v[1], v[2], v[3]);
        *(float4*)&g_h[(size_t)o * LSEQ + l0 + tn * 8 + 4] = make_float4(v[4], v[5], v[6], v[7]);
    }
}

// ---------------------------------------------------------------------------
// FFT pieces (8192-pt, 1024 threads, split re/im padded smem)
__device__ __forceinline__ void fft_fwd_zp(float* __restrict__ SR, float* __restrict__ SI) {
    #pragma unroll
    for (int jj = 0; jj < 4096 / FFT_THREADS; jj++) {
        int j  = threadIdx.x + jj * FFT_THREADS;
        int i0 = PADI(j), i1 = PADI(j + 4096);
        float ar = SR[i0], ai = SI[i0];
        float2 w = g_tw[j];
        SR[i1] = ar * w.x - ai * w.y;
        SI[i1] = ar * w.y + ai * w.x;
    }
    __syncthreads();
    #pragma unroll
    for (int st = 0; st < 6; st++) {
        const int lm  = 10 - 2 * st;
        const int m   = 1 << lm;
        const int str = 2048 >> lm;
        #pragma unroll
        for (int jj = 0; jj < 2048 / FFT_THREADS; jj++) {
            int t = threadIdx.x + jj * FFT_THREADS;
            int q = t & (m - 1);
            int base = ((t >> lm) << (lm + 2)) | q;
            int i0 = PADI(base), i1 = PADI(base + m),
                i2 = PADI(base + 2 * m), i3 = PADI(base + 3 * m);
            float x0r = SR[i0], x0i = SI[i0];
            float x1r = SR[i1], x1i = SI[i1];
            float x2r = SR[i2], x2i = SI[i2];
            float x3r = SR[i3], x3i = SI[i3];
            float2 w1 = g_tw[q * str];
            float2 w2 = g_tw[2 * q * str];
            float2 w3 = g_tw[3 * q * str];
            float t0r = x0r + x2r, t0i = x0i + x2i;
            float t1r = x1r + x3r, t1i = x1i + x3i;
            float t2r = x0r - x2r, t2i = x0i - x2i;
            float t3r = x1i - x3i, t3i = x3r - x1r;
            SR[i0] = t0r + t1r; SI[i0] = t0i + t1i;
            float ur = t2r + t3r, ui = t2i + t3i;
            SR[i1] = ur * w1.x - ui * w1.y; SI[i1] = ur * w1.y + ui * w1.x;
            ur = t0r - t1r; ui = t0i - t1i;
            SR[i2] = ur * w2.x - ui * w2.y; SI[i2] = ur * w2.y + ui * w2.x;
            ur = t2r - t3r; ui = t2i - t3i;
            SR[i3] = ur * w3.x - ui * w3.y; SI[i3] = ur * w3.y + ui * w3.x;
        }
        __syncthreads();
    }
}

__device__ __forceinline__ void fft_inv_half(float* __restrict__ SR, float* __restrict__ SI) {
    #pragma unroll
    for (int st = 0; st < 6; st++) {
        const int lm  = 2 * st;
        const int m   = 1 << lm;
        const int str = 2048 >> lm;
        #pragma unroll
        for (int jj = 0; jj < 2048 / FFT_THREADS; jj++) {
            int t = threadIdx.x + jj * FFT_THREADS;
            int q = t & (m - 1);
            int base = ((t >> lm) << (lm + 2)) | q;
            int i0 = PADI(base), i1 = PADI(base + m),
                i2 = PADI(base + 2 * m), i3 = PADI(base + 3 * m);
            float u0r = SR[i0], u0i = SI[i0];
            float u1r = SR[i1], u1i = SI[i1];
            float u2r = SR[i2], u2i = SI[i2];
            float u3r = SR[i3], u3i = SI[i3];
            float2 w1 = g_tw[q * str];
            float2 w2 = g_tw[2 * q * str];
            float2 w3 = g_tw[3 * q * str];
            float c1r = u1r * w1.x + u1i * w1.y, c1i = u1i * w1.x - u1r * w1.y;
            float c2r = u2r * w2.x + u2i * w2.y, c2i = u2i * w2.x - u2r * w2.y;
            float c3r = u3r * w3.x + u3i * w3.y, c3i = u3i * w3.x - u3r * w3.y;
            float s0r = u0r + c2r, s0i = u0i + c2i;
            float s1r = u0r - c2r, s1i = u0i - c2i;
            float s2r = c1r + c3r, s2i = c1i + c3i;
            float s3r = c1r - c3r, s3i = c1i - c3i;
            SR[i0] = s0r + s2r; SI[i0] = s0i + s2i;
            SR[i2] = s0r - s2r; SI[i2] = s0i - s2i;
            SR[i1] = s1r - s3i; SI[i1] = s1i + s3r;
            SR[i3] = s1r + s3i; SI[i3] = s1i - s3r;
        }
        __syncthreads();
    }
    #pragma unroll
    for (int jj = 0; jj < 4096 / FFT_THREADS; jj++) {
        int j  = threadIdx.x + jj * FFT_THREADS;
        int i0 = PADI(j), i1 = PADI(j + 4096);
        float2 w = g_tw[j];
        float br = SR[i1], bi = SI[i1];
        float tr = br * w.x + bi * w.y;
        float ti = bi * w.x - br * w.y;
        SR[i0] += tr; SI[i0] += ti;
    }
    __syncthreads();
}

// ---------------------------------------------------------------------------
__global__ __launch_bounds__(FFT_THREADS) void hfft_kernel() {
    extern __shared__ float sm[];
    float* SR = sm;
    float* SI = sm + SM_HALF;
    const int c = blockIdx.x;
    const int n = c >> 9;
    const int dpair = c & (NPAIR - 1);
    const float* h0 = g_h + ((size_t)n * DDIM + 2 * dpair)     * LSEQ;
    const float* h1 = g_h + ((size_t)n * DDIM + 2 * dpair + 1) * LSEQ;

    for (int i = threadIdx.x; i < LSEQ; i += FFT_THREADS) {
        SR[PADI(i)] = h0[i]; SI[PADI(i)] = h1[i];
    }
    __syncthreads();
    fft_fwd_zp(SR, SI);

    float2* Ao = g_A + (size_t)c * NF;
    float2* Bo = g_B + (size_t)c * NF;
    for (int p = threadIdx.x; p < NF; p += FFT_THREADS) {
        int q = g_refl[p];
        float zpr = SR[PADI(p)], zpi = SI[PADI(p)];
        float zqr = SR[PADI(q)], zqi = SI[PADI(q)];
        float g0r = 0.5f * (zpr + zqr), g0i = 0.5f * (zpi - zqi);
        float g1r = 0.5f * (zpi + zqi), g1i = 0.5f * (zqr - zpr);
        Ao[p] = make_float2(0.5f * (g0r + g1r), 0.5f * (g0i + g1i));
        Bo[p] = make_float2(0.5f * (g0r - g1r), 0.5f * (g0i - g1i));
    }
}

// ---------------------------------------------------------------------------
__global__ __launch_bounds__(FFT_THREADS) void fftconv_kernel() {
    extern __shared__ float sm[];
    float* SR = sm;
    float* SI = sm + SM_HALF;
    const int c = blockIdx.x;
    const int b = c >> 9;
    const int dpair = c & (NPAIR - 1);
    const int ch0 = 2 * dpair, ch1 = ch0 + 1;
    const float inv = 1.0f / (float)NF;

    const float* v0 = &g_cv[((size_t)(b * 3 + 2) * DDIM + ch0) * LSEQ];
    const float* v1 = &g_cv[((size_t)(b * 3 + 2) * DDIM + ch1) * LSEQ];

    for (int i = threadIdx.x; i < LSEQ; i += FFT_THREADS) {
        SR[PADI(i)] = v0[i]; SI[PADI(i)] = v1[i];
    }
    __syncthreads();

    #pragma unroll 1
    for (int n = 0; n < 2; n++) {
        fft_fwd_zp(SR, SI);

        const float2* Ap = g_A + ((size_t)n * NPAIR + dpair) * NF;
        const float2* Bp = g_B + ((size_t)n * NPAIR + dpair) * NF;
        #pragma unroll
        for (int jj = 0; jj < NF / FFT_THREADS; jj++) {
            int p = threadIdx.x + jj * FFT_THREADS;
            int q = g_refl[p];
            if (q < p) continue;
            int ip = PADI(p), iq = PADI(q);
            float zr = SR[ip], zi = SI[ip];
            float wr = SR[iq], wi = SI[iq];
            float2 a  = Ap[p];
            float2 bb = Bp[p];
            float ypr = a.x * zr - a.y * zi + bb.x * wr + bb.y * wi;
            float ypi = a.x * zi + a.y * zr + bb.y * wr - bb.x * wi;
            float yqr = a.x * wr + a.y * wi + bb.x * zr - bb.y * zi;
            float yqi = a.x * wi - a.y * wr - bb.x * zi - bb.y * zr;
            SR[ip] = ypr; SI[ip] = ypi;
            SR[iq] = yqr; SI[iq] = yqi;
        }
        __syncthreads();

        fft_inv_half(SR, SI);

        if (n == 0) {
            const float* xa = &g_cv[((size_t)(b * 3 + 0) * DDIM + ch0) * LSEQ];
            const float* xb = &g_cv[((size_t)(b * 3 + 0) * DDIM + ch1) * LSEQ];
            for (int l = threadIdx.x; l < LSEQ; l += FFT_THREADS) {
                int ip = PADI(l);
                SR[ip] = SR[ip] * inv * xa[l];
                SI[ip] = SI[ip] * inv * xb[l];
            }
            __syncthreads();
        } else {
            const float* xa = &g_cv[((size_t)(b * 3 + 1) * DDIM + ch0) * LSEQ];
            const float* xb = &g_cv[((size_t)(b * 3 + 1) * DDIM + ch1) * LSEQ];
            uint32_t* vh0 = g_vh + ((size_t)(b * DDIM + ch0)) * (LSEQ / 2);
            uint32_t* vl0 = g_vl + ((size_t)(b * DDIM + ch0)) * (LSEQ / 2);
            uint32_t* vh1 = g_vh + ((size_t)(b * DDIM + ch1)) * (LSEQ / 2);
            uint32_t* vl1 = g_vl + ((size_t)(b * DDIM + ch1)) * (LSEQ / 2);
            for (int l2 = threadIdx.x; l2 < LSEQ / 2; l2 += FFT_THREADS) {
                int l = 2 * l2;
                float y0a = SR[PADI(l)]     * inv * xa[l];
                float y0b = SR[PADI(l + 1)] * inv * xa[l + 1];
                float y1a = SI[PADI(l)]     * inv * xb[l];
                float y1b = SI[PADI(l + 1)] * inv * xb[l + 1];
                vh0[l2] = pack_hi(y0a, y0b); vl0[l2] = pack_lo(y0a, y0b);
                vh1[l2] = pack_hi(y1a, y1b); vl1[l2] = pack_lo(y1a, y1b);
            }
        }
    }
}

// ---------------------------------------------------------------------------
__global__ void conv3_kernel(const float* __restrict__ cw, const float* __restrict__ cb) {
    const int row = blockIdx.y;            // b*3072 + od
    const int od  = row % ODIM;
    const int l   = blockIdx.x * 256 + threadIdx.x;
    const float* r = g_res + (size_t)row * LSEQ;
    float left  = (l > 0)        ? r[l - 1] : 0.0f;
    float mid   = r[l];
    float right = (l < LSEQ - 1) ? r[l + 1] : 0.0f;
    float w0 = cw[od * 3], w1 = cw[od * 3 + 1], w2 = cw[od * 3 + 2];
    g_cv[(size_t)row * LSEQ + l] = w0 * left + w1 * mid + w2 * right + cb[od];
}

// ---------------------------------------------------------------------------
extern "C" void kernel_launch(void* const* d_in, const int* in_sizes, int n_in,
                              void* d_out, int out_size)
{
    const float* u          = (const float*)d_in[0];
    const float* w_in       = (const float*)d_in[1];
    const float* b_in       = (const float*)d_in[2];
    const float* conv_w     = (const float*)d_in[3];
    const float* conv_b     = (const float*)d_in[4];
    const float* w1         = (const float*)d_in[5];
    const float* b1         = (const float*)d_in[6];
    const float* w2         = (const float*)d_in[7];
    const float* b2         = (const float*)d_in[8];
    const float* filt_bias  = (const float*)d_in[9];
    const float* filt_decay = (const float*)d_in[10];
    const float* w_out      = (const float*)d_in[11];
    const float* b_out      = (const float*)d_in[12];
    float* out = (float*)d_out;

    static bool attr_set = false;
    if (!attr_set) {
        cudaFuncSetAttribute(hfft_kernel,    cudaFuncAttributeMaxDynamicSharedMemorySize, FFT_SMEM);
        cudaFuncSetAttribute(fftconv_kernel, cudaFuncAttributeMaxDynamicSharedMemorySize, FFT_SMEM);
        cudaFuncSetAttribute(gemm_in_mma,    cudaFuncAttributeMaxDynamicSharedMemorySize, GI_SMEM);
        cudaFuncSetAttribute(gemm_out_mma,   cudaFuncAttributeMaxDynamicSharedMemorySize, GO_SMEM);
        cudaFuncSetAttribute(filter_gemm,    cudaFuncAttributeMaxDynamicSharedMemorySize, 65536);
        attr_set = true;
    }

    uint32_t *p_wh, *p_wl, *p_uh, *p_ul, *p_oh, *p_ol;
    cudaGetSymbolAddress((void**)&p_wh, g_wh);
    cudaGetSymbolAddress((void**)&p_wl, g_wl);
    cudaGetSymbolAddress((void**)&p_uh, g_uh);
    cudaGetSymbolAddress((void**)&p_ul, g_ul);
    cudaGetSymbolAddress((void**)&p_oh, g_oh);
    cudaGetSymbolAddress((void**)&p_ol, g_ol);

    // Filter path first (hfft is launch #4 for the profiler window)
    init_kernel<<<32, 256>>>();
    sact_kernel<<<LSEQ * 64 / 256, 256>>>(w1, b1);
    filter_gemm<<<dim3(LSEQ / 128, 2 * DDIM / 128), 256, 65536>>>(w2, b2, filt_bias, filt_decay);
    hfft_kernel<<<2 * NPAIR, FFT_THREADS, FFT_SMEM>>>();

    // Operand conversions
    cvt_split<<<(ODIM * DDIM / 2 + 255) / 256, 256>>>(w_in, p_wh, p_wl, ODIM * DDIM / 2);
    cvt_split<<<(BSZ * LSEQ * DDIM / 2 + 255) / 256, 256>>>(u, p_uh, p_ul, BSZ * LSEQ * DDIM / 2);
    cvt_split<<<(DDIM * DDIM / 2 + 255) / 256, 256>>>(w_out, p_oh, p_ol, DDIM * DDIM / 2);

    // Main path
    gemm_in_mma<<<dim3(LSEQ / 128, ODIM / 128, BSZ), 256, GI_SMEM>>>(b_in);
    conv3_kernel<<<dim3(LSEQ / 256, BSZ * ODIM), 256>>>(conv_w, conv_b);
    fftconv_kernel<<<BSZ * NPAIR, FFT_THREADS, FFT_SMEM>>>();
    gemm_out_mma<<<dim3(DDIM / 128, LSEQ / 128, BSZ), 256, GO_SMEM>>>(b_out, out);
}

// round 10
// speedup vs baseline: 1.1170x; 1.1170x over previous
#include <cuda_runtime.h>
#include <cuda_bf16.h>
#include <cstdint>
#include <cstddef>

// ---------------------------------------------------------------------------
// Hyena operator: B=2, L=4096, D=1024, ORDER=2, OD=3072
// Round 10: radix-8 FFT (5 smem passes per transform), conv3 fused into
// fftconv, hfft half-stores, gemm_in in profiled slot #4.
// ---------------------------------------------------------------------------

#define LSEQ 4096
#define NF   8192
#define DDIM 1024
#define ODIM 3072
#define BSZ  2
#define NPAIR 512
#define FFT_THREADS 512
#define PADI(i) ((i) + ((i) >> 5))
#define SM_HALF 8448
#define FFT_SMEM (2 * SM_HALF * 4)

// Scratch (device .bss — allocation-free)
__device__ float  g_res[(size_t)BSZ * ODIM * LSEQ];
__device__ float  g_h  [(size_t)2   * DDIM * LSEQ];
__device__ float  g_sact[(size_t)LSEQ * 64];
__device__ float2 g_A  [(size_t)2 * NPAIR * NF];
__device__ float2 g_B  [(size_t)2 * NPAIR * NF];
__device__ float2 g_tw [NF];
__device__ unsigned short g_refl[NF];
// packed bf16 hi/lo operands (uint32 = 2 bf16)
__device__ uint32_t g_wh[(size_t)ODIM * DDIM / 2];
__device__ uint32_t g_wl[(size_t)ODIM * DDIM / 2];
__device__ uint32_t g_uh[(size_t)BSZ * LSEQ * DDIM / 2];
__device__ uint32_t g_ul[(size_t)BSZ * LSEQ * DDIM / 2];
__device__ uint32_t g_oh[(size_t)DDIM * DDIM / 2];
__device__ uint32_t g_ol[(size_t)DDIM * DDIM / 2];
__device__ uint32_t g_vh[(size_t)BSZ * DDIM * LSEQ / 2];
__device__ uint32_t g_vl[(size_t)BSZ * DDIM * LSEQ / 2];

// ---------------------------------------------------------------------------
__device__ __forceinline__ uint32_t smem_u32(const void* p) {
    uint32_t a;
    asm("{ .reg .u64 t; cvta.to.shared.u64 t, %1; cvt.u32.u64 %0, t; }" : "=r"(a) : "l"(p));
    return a;
}

#define LDSM_X4(r0, r1, r2, r3, addr) \
    asm volatile("ldmatrix.sync.aligned.m8n8.x4.shared.b16 {%0,%1,%2,%3}, [%4];" \
                 : "=r"(r0), "=r"(r1), "=r"(r2), "=r"(r3) : "r"(addr))
#define LDSM_X4_T(r0, r1, r2, r3, addr) \
    asm volatile("ldmatrix.sync.aligned.m8n8.x4.trans.shared.b16 {%0,%1,%2,%3}, [%4];" \
                 : "=r"(r0), "=r"(r1), "=r"(r2), "=r"(r3) : "r"(addr))
#define LDSM_X2(r0, r1, addr) \
    asm volatile("ldmatrix.sync.aligned.m8n8.x2.shared.b16 {%0,%1}, [%2];" \
                 : "=r"(r0), "=r"(r1) : "r"(addr))
#define CP_ASYNC16(dst, src) \
    asm volatile("cp.async.cg.shared.global [%0], [%1], 16;" :: "r"(dst), "l"(src))
#define CP_COMMIT() asm volatile("cp.async.commit_group;" ::: "memory")
#define CP_WAIT1()  asm volatile("cp.async.wait_group 1;" ::: "memory")

__device__ __forceinline__ void mma_bf16(float* c, const uint32_t* a, const uint32_t* b) {
    asm volatile(
        "mma.sync.aligned.m16n8k16.row.col.f32.bf16.bf16.f32 "
        "{%0,%1,%2,%3}, {%4,%5,%6,%7}, {%8,%9}, {%0,%1,%2,%3};"
        : "+f"(c[0]), "+f"(c[1]), "+f"(c[2]), "+f"(c[3])
        : "r"(a[0]), "r"(a[1]), "r"(a[2]), "r"(a[3]), "r"(b[0]), "r"(b[1]));
}

__device__ __forceinline__ uint32_t pack_hi(float x, float y) {
    __nv_bfloat16 hx = __float2bfloat16(x);
    __nv_bfloat16 hy = __float2bfloat16(y);
    return (uint32_t)__bfloat16_as_ushort(hx) | ((uint32_t)__bfloat16_as_ushort(hy) << 16);
}
__device__ __forceinline__ uint32_t pack_lo(float x, float y) {
    __nv_bfloat16 hx = __float2bfloat16(x);
    __nv_bfloat16 hy = __float2bfloat16(y);
    __nv_bfloat16 lx = __float2bfloat16(x - __bfloat162float(hx));
    __nv_bfloat16 ly = __float2bfloat16(y - __bfloat162float(hy));
    return (uint32_t)__bfloat16_as_ushort(lx) | ((uint32_t)__bfloat16_as_ushort(ly) << 16);
}

// fp32 -> packed bf16 hi/lo
__global__ void cvt_split(const float* __restrict__ src, uint32_t* __restrict__ hi,
                          uint32_t* __restrict__ lo, int n2) {
    int i = blockIdx.x * 256 + threadIdx.x;
    if (i < n2) {
        float2 v = ((const float2*)src)[i];
        hi[i] = pack_hi(v.x, v.y);
        lo[i] = pack_lo(v.x, v.y);
    }
}

// ---------------------------------------------------------------------------
// gemm_in: g_res[b,od,l] = sum_d w_in[od,d]*u[b,l,d] + b_in[od]
#define GI_STAGE 40960
#define GI_SMEM  (2 * GI_STAGE)

__global__ __launch_bounds__(256, 2) void gemm_in_mma(const float* __restrict__ bias)
{
    extern __shared__ char smem[];
    const uint32_t sb = smem_u32(smem);
    const int tid  = threadIdx.x;
    const int lane = tid & 31;
    const int wid  = tid >> 5;
    const int warp_m = wid >> 2;
    const int warp_n = wid & 3;

    const int b  = blockIdx.z;
    const int m0 = blockIdx.y * 128;   // od
    const int n0 = blockIdx.x * 128;   // l
    float* C = g_res + (size_t)b * ODIM * LSEQ;

    const int tile = tid >> 6;
    const int tloc = tid & 63;
    const char* gbase;
    if      (tile == 0) gbase = (const char*)g_wh + (size_t)m0 * 2048;
    else if (tile == 1) gbase = (const char*)g_wl + (size_t)m0 * 2048;
    else if (tile == 2) gbase = (const char*)g_uh + (size_t)(b * LSEQ + n0) * 2048;
    else                gbase = (const char*)g_ul + (size_t)(b * LSEQ + n0) * 2048;

    float acc[4][4][4];
    #pragma unroll
    for (int i = 0; i < 4; i++)
        #pragma unroll
        for (int j = 0; j < 4; j++)
            #pragma unroll
            for (int r = 0; r < 4; r++) acc[i][j][r] = 0.0f;

    const int a_off = ((lane & 7) + ((lane & 8) ? 8 : 0)) * 80 + ((lane & 16) ? 16 : 0);
    const int b_off = (lane & 7) * 80 + ((lane & 8) ? 16 : 0);

    #pragma unroll
    for (int p = 0; p < 2; p++) {
        #pragma unroll
        for (int o = 0; o < 8; o++) {
            int idx = tloc + o * 64, row = idx >> 2, c = idx & 3;
            uint32_t dst = sb + p * GI_STAGE + tile * 10240 + row * 80 + c * 16;
            CP_ASYNC16(dst, gbase + (size_t)row * 2048 + p * 64 + c * 16);
        }
        CP_COMMIT();
    }

    for (int ch = 0; ch < 32; ch++) {
        CP_WAIT1();
        __syncthreads();
        const uint32_t sbase = sb + (ch & 1) * GI_STAGE;

        #pragma unroll
        for (int k16 = 0; k16 < 2; k16++) {
            uint32_t bh[4][2], bl[4][2];
            #pragma unroll
            for (int j = 0; j < 4; j++) {
                uint32_t rb = sbase + 20480 + (warp_n * 32 + j * 8) * 80 + k16 * 32 + b_off;
                LDSM_X2(bh[j][0], bh[j][1], rb);
                LDSM_X2(bl[j][0], bl[j][1], rb + 10240);
            }
            #pragma unroll
            for (int i = 0; i < 4; i++) {
                uint32_t ah[4], al[4];
                uint32_t ra = sbase + (warp_m * 64 + i * 16) * 80 + k16 * 32 + a_off;
                LDSM_X4(ah[0], ah[1], ah[2], ah[3], ra);
                LDSM_X4(al[0], al[1], al[2], al[3], ra + 10240);
                #pragma unroll
                for (int j = 0; j < 4; j++) {
                    mma_bf16(acc[i][j], ah, bh[j]);
                    mma_bf16(acc[i][j], ah, bl[j]);
                    mma_bf16(acc[i][j], al, bh[j]);
                }
            }
        }

        __syncthreads();
        if (ch + 2 < 32) {
            #pragma unroll
            for (int o = 0; o < 8; o++) {
                int idx = tloc + o * 64, row = idx >> 2, c = idx & 3;
                uint32_t dst = sb + (ch & 1) * GI_STAGE + tile * 10240 + row * 80 + c * 16;
                CP_ASYNC16(dst, gbase + (size_t)row * 2048 + (ch + 2) * 64 + c * 16);
            }
        }
        CP_COMMIT();
    }

    const int g = lane >> 2;
    const int t = lane & 3;
    #pragma unroll
    for (int i = 0; i < 4; i++) {
        int od0 = m0 + warp_m * 64 + i * 16 + g;
        float bv0 = bias[od0];
        float bv1 = bias[od0 + 8];
        #pragma unroll
        for (int j = 0; j < 4; j++) {
            int l = n0 + warp_n * 32 + j * 8 + t * 2;
            *(float2*)&C[(size_t)od0 * LSEQ + l] =
                make_float2(acc[i][j][0] + bv0, acc[i][j][1] + bv0);
            *(float2*)&C[(size_t)(od0 + 8) * LSEQ + l] =
                make_float2(acc[i][j][2] + bv1, acc[i][j][3] + bv1);
        }
    }
}

// ---------------------------------------------------------------------------
// gemm_out: out[b,l,e] = sum_d v[b,d,l]*w_out[e,d] + b_out[e]
#define GO_A_LO  8704
#define GO_B_HI  17408
#define GO_B_LO  27648
#define GO_STAGE 37888
#define GO_SMEM  (2 * GO_STAGE)

__global__ __launch_bounds__(256, 2) void gemm_out_mma(const float* __restrict__ bias,
                                                       float* __restrict__ O)
{
    extern __shared__ char smem[];
    const uint32_t sb = smem_u32(smem);
    const int tid  = threadIdx.x;
    const int lane = tid & 31;
    const int wid  = tid >> 5;
    const int warp_m = wid >> 2;
    const int warp_n = wid & 3;

    const int b  = blockIdx.z;
    const int m0 = blockIdx.y * 128;   // l
    const int n0 = blockIdx.x * 128;   // e
    float* C = O + (size_t)b * LSEQ * DDIM;

    const int tile = tid >> 6;
    const int tloc = tid & 63;
    const char* gbase;
    if      (tile == 0) gbase = (const char*)g_vh + (size_t)(b * DDIM) * 8192 + (size_t)m0 * 2;
    else if (tile == 1) gbase = (const char*)g_vl + (size_t)(b * DDIM) * 8192 + (size_t)m0 * 2;
    else if (tile == 2) gbase = (const char*)g_oh + (size_t)n0 * 2048;
    else                gbase = (const char*)g_ol + (size_t)n0 * 2048;

    float acc[4][4][4];
    #pragma unroll
    for (int i = 0; i < 4; i++)
        #pragma unroll
        for (int j = 0; j < 4; j++)
            #pragma unroll
            for (int r = 0; r < 4; r++) acc[i][j][r] = 0.0f;

    const int at_off = ((lane & 7) + ((lane & 16) ? 8 : 0)) * 272 + ((lane & 8) ? 16 : 0);
    const int b_off  = (lane & 7) * 80 + ((lane & 8) ? 16 : 0);

    #pragma unroll
    for (int p = 0; p < 2; p++) {
        if (tile < 2) {
            #pragma unroll
            for (int o = 0; o < 8; o++) {
                int idx = tloc + o * 64, row = idx >> 4, c = idx & 15;
                uint32_t dst = sb + p * GO_STAGE + tile * GO_A_LO + row * 272 + c * 16;
                CP_ASYNC16(dst, gbase + (size_t)(p * 32 + row) * 8192 + c * 16);
            }
        } else {
            #pragma unroll
            for (int o = 0; o < 8; o++) {
                int idx = tloc + o * 64, row = idx >> 2, c = idx & 3;
                uint32_t dst = sb + p * GO_STAGE + GO_B_HI + (tile - 2) * 10240 + row * 80 + c * 16;
                CP_ASYNC16(dst, gbase + (size_t)row * 2048 + p * 64 + c * 16);
            }
        }
        CP_COMMIT();
    }

    for (int ch = 0; ch < 32; ch++) {
        CP_WAIT1();
        __syncthreads();
        const uint32_t sbase = sb + (ch & 1) * GO_STAGE;

        #pragma unroll
        for (int k16 = 0; k16 < 2; k16++) {
            uint32_t bh[4][2], bl[4][2];
            #pragma unroll
            for (int j = 0; j < 4; j++) {
                uint32_t rb = sbase + GO_B_HI + (warp_n * 32 + j * 8) * 80 + k16 * 32 + b_off;
                LDSM_X2(bh[j][0], bh[j][1], rb);
                LDSM_X2(bl[j][0], bl[j][1], rb + 10240);
            }
            #pragma unroll
            for (int i = 0; i < 4; i++) {
                uint32_t ah[4], al[4];
                uint32_t ra = sbase + k16 * 16 * 272 + (warp_m * 64 + i * 16) * 2 + at_off;
                LDSM_X4_T(ah[0], ah[1], ah[2], ah[3], ra);
                LDSM_X4_T(al[0], al[1], al[2], al[3], ra + GO_A_LO);
                #pragma unroll
                for (int j = 0; j < 4; j++) {
                    mma_bf16(acc[i][j], ah, bh[j]);
                    mma_bf16(acc[i][j], ah, bl[j]);
                    mma_bf16(acc[i][j], al, bh[j]);
                }
            }
        }

        __syncthreads();
        if (ch + 2 < 32) {
            if (tile < 2) {
                #pragma unroll
                for (int o = 0; o < 8; o++) {
                    int idx = tloc + o * 64, row = idx >> 4, c = idx & 15;
                    uint32_t dst = sb + (ch & 1) * GO_STAGE + tile * GO_A_LO + row * 272 + c * 16;
                    CP_ASYNC16(dst, gbase + (size_t)((ch + 2) * 32 + row) * 8192 + c * 16);
                }
            } else {
                #pragma unroll
                for (int o = 0; o < 8; o++) {
                    int idx = tloc + o * 64, row = idx >> 2, c = idx & 3;
                    uint32_t dst = sb + (ch & 1) * GO_STAGE + GO_B_HI + (tile - 2) * 10240 + row * 80 + c * 16;
                    CP_ASYNC16(dst, gbase + (size_t)row * 2048 + (ch + 2) * 64 + c * 16);
                }
            }
        }
        CP_COMMIT();
    }

    const int g = lane >> 2;
    const int t = lane & 3;
    #pragma unroll
    for (int j = 0; j < 4; j++) {
        int e = n0 + warp_n * 32 + j * 8 + t * 2;
        float bb0 = bias[e];
        float bb1 = bias[e + 1];
        #pragma unroll
        for (int i = 0; i < 4; i++) {
            int l = m0 + warp_m * 64 + i * 16 + g;
            *(float2*)&C[(size_t)l * DDIM + e] =
                make_float2(acc[i][j][0] + bb0, acc[i][j][1] + bb1);
            *(float2*)&C[(size_t)(l + 8) * DDIM + e] =
                make_float2(acc[i][j][2] + bb0, acc[i][j][3] + bb1);
        }
    }
}

// ---------------------------------------------------------------------------
// Mixed-radix [2,8,8,8,8] digit maps. Butterfly output j = frequency digit j,
// so slot = k0*4096 + d1*512 + d2*64 + d3*8 + d4 (little-endian digits).
__device__ __forceinline__ int freq_to_slot(int k) {
    return (k & 1) * 4096 + ((k >> 1) & 7) * 512 + ((k >> 4) & 7) * 64
         + ((k >> 7) & 7) * 8 + ((k >> 10) & 7);
}
__device__ __forceinline__ int slot_to_freq(int p) {
    return ((p >> 12) & 1) | (((p >> 9) & 7) << 1) | (((p >> 6) & 7) << 4)
         | (((p >> 3) & 7) << 7) | ((p & 7) << 10);
}

__global__ void init_kernel() {
    int i = blockIdx.x * blockDim.x + threadIdx.x;
    if (i < NF) {
        double ang = -2.0 * 3.141592653589793238462643 * (double)i / (double)NF;
        g_tw[i] = make_float2((float)cos(ang), (float)sin(ang));
        int k  = slot_to_freq(i);
        int kp = (NF - k) & (NF - 1);
        g_refl[i] = (unsigned short)freq_to_slot(kp);
    }
}

// ---------------------------------------------------------------------------
// Filter path
__global__ __launch_bounds__(256) void sact_kernel(
    const float* __restrict__ w1, const float* __restrict__ b1)
{
    int idx = blockIdx.x * 256 + threadIdx.x;   // l*64 + u
    int l = idx >> 6;
    int u = idx & 63;
    float t = (float)l * (1.0f / (float)(LSEQ - 1));
    float z = b1[u];
    #pragma unroll
    for (int j = 0; j < 33; j++) z += sinf(t * (float)j * 10.0f) * w1[u * 33 + j];
    g_sact[idx] = sinf(10.0f * z);
}

__global__ __launch_bounds__(256) void filter_gemm(
    const float* __restrict__ w2, const float* __restrict__ b2,
    const float* __restrict__ fb, const float* __restrict__ fd)
{
    extern __shared__ float fsm[];
    float (*As)[128] = (float(*)[128])fsm;
    float (*Bs)[128] = (float(*)[128])(fsm + 64 * 128);
    const int o0 = blockIdx.y * 128;
    const int l0 = blockIdx.x * 128;
    const int tid = threadIdx.x;
    const int tm = tid >> 4;
    const int tn = tid & 15;
    const int lrow = tid >> 1;
    const int lk   = (tid & 1) * 32;

    #pragma unroll
    for (int f = 0; f < 8; f++) {
        float4 a = *(const float4*)&w2[(size_t)(o0 + lrow) * 64 + lk + f * 4];
        As[lk + f * 4 + 0][lrow] = a.x; As[lk + f * 4 + 1][lrow] = a.y;
        As[lk + f * 4 + 2][lrow] = a.z; As[lk + f * 4 + 3][lrow] = a.w;
        float4 s = *(const float4*)&g_sact[(size_t)(l0 + lrow) * 64 + lk + f * 4];
        Bs[lk + f * 4 + 0][lrow] = s.x; Bs[lk + f * 4 + 1][lrow] = s.y;
        Bs[lk + f * 4 + 2][lrow] = s.z; Bs[lk + f * 4 + 3][lrow] = s.w;
    }
    __syncthreads();

    float acc[8][8];
    #pragma unroll
    for (int i = 0; i < 8; i++)
        #pragma unroll
        for (int j = 0; j < 8; j++) acc[i][j] = 0.0f;

    #pragma unroll
    for (int k = 0; k < 64; k++) {
        float4 ra0 = *(const float4*)&As[k][tm * 8];
        float4 ra1 = *(const float4*)&As[k][tm * 8 + 4];
        float4 rb0 = *(const float4*)&Bs[k][tn * 8];
        float4 rb1 = *(const float4*)&Bs[k][tn * 8 + 4];
        float ra[8] = {ra0.x, ra0.y, ra0.z, ra0.w, ra1.x, ra1.y, ra1.z, ra1.w};
        float rb[8] = {rb0.x, rb0.y, rb0.z, rb0.w, rb1.x, rb1.y, rb1.z, rb1.w};
        #pragma unroll
        for (int i = 0; i < 8; i++)
            #pragma unroll
            for (int j = 0; j < 8; j++) acc[i][j] += ra[i] * rb[j];
    }

    #pragma unroll
    for (int i = 0; i < 8; i++) {
        int o = o0 + tm * 8 + i;
        float ed  = expf(fd[o]);
        float bb  = b2[o];
        float fbo = fb[o];
        float v[8];
        #pragma unroll
        for (int j = 0; j < 8; j++) {
            int l = l0 + tn * 8 + j;
            float t = (float)l * (1.0f / (float)(LSEQ - 1));
            v[j] = ((acc[i][j] + bb) * expf(-ed * t) + fbo) * (1.0f / (float)LSEQ);
        }
        *(float4*)&g_h[(size_t)o * LSEQ + l0 + tn * 8]     = make_float4(v[0], v[1], v[2], v[3]);
        *(float4*)&g_h[(size_t)o * LSEQ + l0 + tn * 8 + 4] = make_float4(v[4], v[5], v[6], v[7]);
    }
}

// ---------------------------------------------------------------------------
// FFT: 8192-pt, 512 threads, split re/im padded smem, mixed radix [2,8,8,8,8].
#define FFT_C 0.70710678118654752f

// Forward, zero-padded upper half: radix-2 then 4 radix-8 DIF stages.
__device__ __forceinline__ void fft_fwd_zp(float* __restrict__ SR, float* __restrict__ SI) {
    #pragma unroll
    for (int jj = 0; jj < 8; jj++) {
        int j  = threadIdx.x + jj * FFT_THREADS;
        int i0 = PADI(j), i1 = PADI(j + 4096);
        float ar = SR[i0], ai = SI[i0];
        float2 w = g_tw[j];
        SR[i1] = ar * w.x - ai * w.y;
        SI[i1] = ar * w.y + ai * w.x;
    }
    __syncthreads();
    #pragma unroll
    for (int s = 0; s < 4; s++) {
        const int lm  = 9 - 3 * s;          // 9,6,3,0
        const int m   = 1 << lm;
        const int str = 1024 >> lm;
        #pragma unroll
        for (int jj = 0; jj < 2; jj++) {
            int t = threadIdx.x + jj * FFT_THREADS;
            int q = t & (m - 1);
            int base = ((t >> lm) << (lm + 3)) | q;
            int p0 = PADI(base), p1 = PADI(base + m), p2 = PADI(base + 2 * m),
                p3 = PADI(base + 3 * m), p4 = PADI(base + 4 * m), p5 = PADI(base + 5 * m),
                p6 = PADI(base + 6 * m), p7 = PADI(base + 7 * m);
            float x0r = SR[p0], x0i = SI[p0];
            float x1r = SR[p1], x1i = SI[p1];
            float x2r = SR[p2], x2i = SI[p2];
            float x3r = SR[p3], x3i = SI[p3];
            float x4r = SR[p4], x4i = SI[p4];
            float x5r = SR[p5], x5i = SI[p5];
            float x6r = SR[p6], x6i = SI[p6];
            float x7r = SR[p7], x7i = SI[p7];
            // even/odd split
            float a0r = x0r + x4r, a0i = x0i + x4i;
            float a1r = x1r + x5r, a1i = x1i + x5i;
            float a2r = x2r + x6r, a2i = x2i + x6i;
            float a3r = x3r + x7r, a3i = x3i + x7i;
            float b0r = x0r - x4r, b0i = x0i - x4i;
            float b1r = x1r - x5r, b1i = x1i - x5i;
            float b2r = x2r - x6r, b2i = x2i - x6i;
            float b3r = x3r - x7r, b3i = x3i - x7i;
            // odd twiddles W8^n
            float u1r =  FFT_C * (b1r + b1i), u1i = FFT_C * (b1i - b1r);
            float u2r =  b2i,                 u2i = -b2r;
            float u3r = -FFT_C * (b3r - b3i), u3i = -FFT_C * (b3r + b3i);
            // DFT4(a) -> X0,X2,X4,X6
            float t0r = a0r + a2r, t0i = a0i + a2i;
            float t1r = a1r + a3r, t1i = a1i + a3i;
            float t2r = a0r - a2r, t2i = a0i - a2i;
            float t3r = a1i - a3i, t3i = a3r - a1r;
            float X0r = t0r + t1r, X0i = t0i + t1i;
            float X2r = t2r + t3r, X2i = t2i + t3i;
            float X4r = t0r - t1r, X4i = t0i - t1i;
            float X6r = t2r - t3r, X6i = t2i - t3i;
            // DFT4(b0,u1,u2,u3) -> X1,X3,X5,X7
            float s0r = b0r + u2r, s0i = b0i + u2i;
            float s1r = u1r + u3r, s1i = u1i + u3i;
            float s2r = b0r - u2r, s2i = b0i - u2i;
            float s3r = u1i - u3i, s3i = u3r - u1r;
            float X1r = s0r + s1r, X1i = s0i + s1i;
            float X3r = s2r + s3r, X3i = s2i + s3i;
            float X5r = s0r - s1r, X5i = s0i - s1i;
            float X7r = s2r - s3r, X7i = s2i - s3i;
            SR[p0] = X0r; SI[p0] = X0i;
            if (lm > 0) {
                int tb = q * str;
                float2 w1 = g_tw[tb],     w2 = g_tw[2 * tb], w3 = g_tw[3 * tb];
                float2 w4 = g_tw[4 * tb], w5 = g_tw[5 * tb], w6 = g_tw[6 * tb];
                float2 w7 = g_tw[7 * tb];
                SR[p1] = X1r * w1.x - X1i * w1.y; SI[p1] = X1r * w1.y + X1i * w1.x;
                SR[p2] = X2r * w2.x - X2i * w2.y; SI[p2] = X2r * w2.y + X2i * w2.x;
                SR[p3] = X3r * w3.x - X3i * w3.y; SI[p3] = X3r * w3.y + X3i * w3.x;
                SR[p4] = X4r * w4.x - X4i * w4.y; SI[p4] = X4r * w4.y + X4i * w4.x;
                SR[p5] = X5r * w5.x - X5i * w5.y; SI[p5] = X5r * w5.y + X5i * w5.x;
                SR[p6] = X6r * w6.x - X6i * w6.y; SI[p6] = X6r * w6.y + X6i * w6.x;
                SR[p7] = X7r * w7.x - X7i * w7.y; SI[p7] = X7r * w7.y + X7i * w7.x;
            } else {
                SR[p1] = X1r; SI[p1] = X1i;
                SR[p2] = X2r; SI[p2] = X2i;
                SR[p3] = X3r; SI[p3] = X3i;
                SR[p4] = X4r; SI[p4] = X4i;
                SR[p5] = X5r; SI[p5] = X5i;
                SR[p6] = X6r; SI[p6] = X6i;
                SR[p7] = X7r; SI[p7] = X7i;
            }
        }
        __syncthreads();
    }
}

// Inverse (unnormalized, x8192): 4 radix-8 DIT stages then half-output radix-2.
__device__ __forceinline__ void fft_inv_half(float* __restrict__ SR, float* __restrict__ SI) {
    #pragma unroll
    for (int s = 0; s < 4; s++) {
        const int lm  = 3 * s;              // 0,3,6,9
        const int m   = 1 << lm;
        const int str = 1024 >> lm;
        #pragma unroll
        for (int jj = 0; jj < 2; jj++) {
            int t = threadIdx.x + jj * FFT_THREADS;
            int q = t & (m - 1);
            int base = ((t >> lm) << (lm + 3)) | q;
            int p0 = PADI(base), p1 = PADI(base + m), p2 = PADI(base + 2 * m),
                p3 = PADI(base + 3 * m), p4 = PADI(base + 4 * m), p5 = PADI(base + 5 * m),
                p6 = PADI(base + 6 * m), p7 = PADI(base + 7 * m);
            float y0r = SR[p0], y0i = SI[p0];
            float y1r = SR[p1], y1i = SI[p1];
            float y2r = SR[p2], y2i = SI[p2];
            float y3r = SR[p3], y3i = SI[p3];
            float y4r = SR[p4], y4i = SI[p4];
            float y5r = SR[p5], y5i = SI[p5];
            float y6r = SR[p6], y6i = SI[p6];
            float y7r = SR[p7], y7i = SI[p7];
            if (lm > 0) {
                int tb = q * str;
                float2 w1 = g_tw[tb],     w2 = g_tw[2 * tb], w3 = g_tw[3 * tb];
                float2 w4 = g_tw[4 * tb], w5 = g_tw[5 * tb], w6 = g_tw[6 * tb];
                float2 w7 = g_tw[7 * tb];
                float cr;
                cr = y1r * w1.x + y1i * w1.y; y1i = y1i * w1.x - y1r * w1.y; y1r = cr;
                cr = y2r * w2.x + y2i * w2.y; y2i = y2i * w2.x - y2r * w2.y; y2r = cr;
                cr = y3r * w3.x + y3i * w3.y; y3i = y3i * w3.x - y3r * w3.y; y3r = cr;
                cr = y4r * w4.x + y4i * w4.y; y4i = y4i * w4.x - y4r * w4.y; y4r = cr;
                cr = y5r * w5.x + y5i * w5.y; y5i = y5i * w5.x - y5r * w5.y; y5r = cr;
                cr = y6r * w6.x + y6i * w6.y; y6i = y6i * w6.x - y6r * w6.y; y6r = cr;
                cr = y7r * w7.x + y7i * w7.y; y7i = y7i * w7.x - y7r * w7.y; y7r = cr;
            }
            // IDFT4(even: y0,y2,y4,y6) -> a0..a3
            float t0r = y0r + y4r, t0i = y0i + y4i;
            float t1r = y2r + y6r, t1i = y2i + y6i;
            float t2r = y0r - y4r, t2i = y0i - y4i;
            float t3r = y6i - y2i, t3i = y2r - y6r;   // +i(y2-y6)
            float a0r = t0r + t1r, a0i = t0i + t1i;
            float a1r = t2r + t3r, a1i = t2i + t3i;
            float a2r = t0r - t1r, a2i = t0i - t1i;
            float a3r = t2r - t3r, a3i = t2i - t3i;
            // IDFT4(odd: y1,y3,y5,y7) -> d0..d3
            float s0r = y1r + y5r, s0i = y1i + y5i;
            float s1r = y3r + y7r, s1i = y3i + y7i;
            float s2r = y1r - y5r, s2i = y1i - y5i;
            float s3r = y7i - y3i, s3i = y3r - y7r;
            float d0r = s0r + s1r, d0i = s0i + s1i;
            float d1r = s2r + s3r, d1i = s2i + s3i;
            float d2r = s0r - s1r, d2i = s0i - s1i;
            float d3r = s2r - s3r, d3i = s2i - s3i;
            // e_n = d_n * exp(+i pi n / 4)
            float e1r =  FFT_C * (d1r - d1i), e1i = FFT_C * (d1r + d1i);
            float e2r = -d2i,                 e2i = d2r;
            float e3r = -FFT_C * (d3r + d3i), e3i = FFT_C * (d3r - d3i);
            SR[p0] = a0r + d0r; SI[p0] = a0i + d0i;
            SR[p4] = a0r - d0r; SI[p4] = a0i - d0i;
            SR[p1] = a1r + e1r; SI[p1] = a1i + e1i;
            SR[p5] = a1r - e1r; SI[p5] = a1i - e1i;
            SR[p2] = a2r + e2r; SI[p2] = a2i + e2i;
            SR[p6] = a2r - e2r; SI[p6] = a2i - e2i;
            SR[p3] = a3r + e3r; SI[p3] = a3i + e3i;
            SR[p7] = a3r - e3r; SI[p7] = a3i - e3i;
        }
        __syncthreads();
    }
    // final radix-2, lower half outputs only
    #pragma unroll
    for (int jj = 0; jj < 8; jj++) {
        int j  = threadIdx.x + jj * FFT_THREADS;
        int i0 = PADI(j), i1 = PADI(j + 4096);
        float2 w = g_tw[j];
        float br = SR[i1], bi = SI[i1];
        float tr = br * w.x + bi * w.y;
        float ti = bi * w.x - br * w.y;
        SR[i0] += tr; SI[i0] += ti;
    }
    __syncthreads();
}

// ---------------------------------------------------------------------------
__global__ __launch_bounds__(FFT_THREADS) void hfft_kernel() {
    extern __shared__ float sm[];
    float* SR = sm;
    float* SI = sm + SM_HALF;
    const int c = blockIdx.x;
    const int n = c >> 9;
    const int dpair = c & (NPAIR - 1);
    const float* h0 = g_h + ((size_t)n * DDIM + 2 * dpair)     * LSEQ;
    const float* h1 = g_h + ((size_t)n * DDIM + 2 * dpair + 1) * LSEQ;

    for (int i = threadIdx.x; i < LSEQ; i += FFT_THREADS) {
        SR[PADI(i)] = h0[i]; SI[PADI(i)] = h1[i];
    }
    __syncthreads();
    fft_fwd_zp(SR, SI);

    float2* Ao = g_A + (size_t)c * NF;
    float2* Bo = g_B + (size_t)c * NF;
    for (int p = threadIdx.x; p < NF; p += FFT_THREADS) {
        int q = g_refl[p];
        if (q < p) continue;    // fftconv only reads slots with q >= p
        float zpr = SR[PADI(p)], zpi = SI[PADI(p)];
        float zqr = SR[PADI(q)], zqi = SI[PADI(q)];
        float g0r = 0.5f * (zpr + zqr), g0i = 0.5f * (zpi - zqi);
        float g1r = 0.5f * (zpi + zqi), g1i = 0.5f * (zqr - zpr);
        Ao[p] = make_float2(0.5f * (g0r + g1r), 0.5f * (g0i + g1i));
        Bo[p] = make_float2(0.5f * (g0r - g1r), 0.5f * (g0i - g1i));
    }
}

// ---------------------------------------------------------------------------
// Depthwise conv3 applied on the fly from g_res rows.
__device__ __forceinline__ float conv3_at(const float* __restrict__ r, int l,
                                          float w0, float w1, float w2, float cb) {
    float left  = (l > 0)        ? r[l - 1] : 0.0f;
    float right = (l < LSEQ - 1) ? r[l + 1] : 0.0f;
    return w0 * left + w1 * r[l] + w2 * right + cb;
}

__global__ __launch_bounds__(FFT_THREADS) void fftconv_kernel(
    const float* __restrict__ cw, const float* __restrict__ cbv)
{
    extern __shared__ float sm[];
    float* SR = sm;
    float* SI = sm + SM_HALF;
    const int c = blockIdx.x;
    const int b = c >> 9;
    const int dpair = c & (NPAIR - 1);
    const int ch0 = 2 * dpair, ch1 = ch0 + 1;
    const float inv = 1.0f / (float)NF;

    // v = conv3(res row (b,2,ch)) — ORDER slot 2
    {
        const float* r2a = g_res + ((size_t)(b * 3 + 2) * DDIM + ch0) * LSEQ;
        const float* r2b = g_res + ((size_t)(b * 3 + 2) * DDIM + ch1) * LSEQ;
        const int oa = 2 * DDIM + ch0, ob = 2 * DDIM + ch1;
        float w0a = cw[oa * 3], w1a = cw[oa * 3 + 1], w2a = cw[oa * 3 + 2], cba = cbv[oa];
        float w0b = cw[ob * 3], w1b = cw[ob * 3 + 1], w2b = cw[ob * 3 + 2], cbb = cbv[ob];
        for (int i = threadIdx.x; i < LSEQ; i += FFT_THREADS) {
            SR[PADI(i)] = conv3_at(r2a, i, w0a, w1a, w2a, cba);
            SI[PADI(i)] = conv3_at(r2b, i, w0b, w1b, w2b, cbb);
        }
    }
    __syncthreads();

    #pragma unroll 1
    for (int n = 0; n < 2; n++) {
        fft_fwd_zp(SR, SI);

        const float2* Ap = g_A + ((size_t)n * NPAIR + dpair) * NF;
        const float2* Bp = g_B + ((size_t)n * NPAIR + dpair) * NF;
        #pragma unroll
        for (int jj = 0; jj < NF / FFT_THREADS; jj++) {
            int p = threadIdx.x + jj * FFT_THREADS;
            int q = g_refl[p];
            if (q < p) continue;
            int ip = PADI(p), iq = PADI(q);
            float zr = SR[ip], zi = SI[ip];
            float wr = SR[iq], wi = SI[iq];
            float2 a  = Ap[p];
            float2 bb = Bp[p];
            float ypr = a.x * zr - a.y * zi + bb.x * wr + bb.y * wi;
            float ypi = a.x * zi + a.y * zr + bb.y * wr - bb.x * wi;
            float yqr = a.x * wr + a.y * wi + bb.x * zr - bb.y * zi;
            float yqi = a.x * wi - a.y * wr - bb.x * zi - bb.y * zr;
            SR[ip] = ypr; SI[ip] = ypi;
            SR[iq] = yqr; SI[iq] = yqi;
        }
        __syncthreads();

        fft_inv_half(SR, SI);

        const float* rna = g_res + ((size_t)(b * 3 + n) * DDIM + ch0) * LSEQ;
        const float* rnb = g_res + ((size_t)(b * 3 + n) * DDIM + ch1) * LSEQ;
        const int oa = n * DDIM + ch0, ob = n * DDIM + ch1;
        float w0a = cw[oa * 3], w1a = cw[oa * 3 + 1], w2a = cw[oa * 3 + 2], cba = cbv[oa];
        float w0b = cw[ob * 3], w1b = cw[ob * 3 + 1], w2b = cw[ob * 3 + 2], cbb = cbv[ob];

        if (n == 0) {
            for (int l = threadIdx.x; l < LSEQ; l += FFT_THREADS) {
                int ip = PADI(l);
                SR[ip] = SR[ip] * inv * conv3_at(rna, l, w0a, w1a, w2a, cba);
                SI[ip] = SI[ip] * inv * conv3_at(rnb, l, w0b, w1b, w2b, cbb);
            }
            __syncthreads();
        } else {
            uint32_t* vh0 = g_vh + ((size_t)(b * DDIM + ch0)) * (LSEQ / 2);
            uint32_t* vl0 = g_vl + ((size_t)(b * DDIM + ch0)) * (LSEQ / 2);
            uint32_t* vh1 = g_vh + ((size_t)(b * DDIM + ch1)) * (LSEQ / 2);
            uint32_t* vl1 = g_vl + ((size_t)(b * DDIM + ch1)) * (LSEQ / 2);
            for (int l2 = threadIdx.x; l2 < LSEQ / 2; l2 += FFT_THREADS) {
                int l = 2 * l2;
                float y0a = SR[PADI(l)]     * inv * conv3_at(rna, l,     w0a, w1a, w2a, cba);
                float y0b = SR[PADI(l + 1)] * inv * conv3_at(rna, l + 1, w0a, w1a, w2a, cba);
                float y1a = SI[PADI(l)]     * inv * conv3_at(rnb, l,     w0b, w1b, w2b, cbb);
                float y1b = SI[PADI(l + 1)] * inv * conv3_at(rnb, l + 1, w0b, w1b, w2b, cbb);
                vh0[l2] = pack_hi(y0a, y0b); vl0[l2] = pack_lo(y0a, y0b);
                vh1[l2] = pack_hi(y1a, y1b); vl1[l2] = pack_lo(y1a, y1b);
            }
        }
    }
}

// ---------------------------------------------------------------------------
extern "C" void kernel_launch(void* const* d_in, const int* in_sizes, int n_in,
                              void* d_out, int out_size)
{
    const float* u          = (const float*)d_in[0];
    const float* w_in       = (const float*)d_in[1];
    const float* b_in       = (const float*)d_in[2];
    const float* conv_w     = (const float*)d_in[3];
    const float* conv_b     = (const float*)d_in[4];
    const float* w1         = (const float*)d_in[5];
    const float* b1         = (const float*)d_in[6];
    const float* w2         = (const float*)d_in[7];
    const float* b2         = (const float*)d_in[8];
    const float* filt_bias  = (const float*)d_in[9];
    const float* filt_decay = (const float*)d_in[10];
    const float* w_out      = (const float*)d_in[11];
    const float* b_out      = (const float*)d_in[12];
    float* out = (float*)d_out;

    static bool attr_set = false;
    if (!attr_set) {
        cudaFuncSetAttribute(hfft_kernel,    cudaFuncAttributeMaxDynamicSharedMemorySize, FFT_SMEM);
        cudaFuncSetAttribute(fftconv_kernel, cudaFuncAttributeMaxDynamicSharedMemorySize, FFT_SMEM);
        cudaFuncSetAttribute(gemm_in_mma,    cudaFuncAttributeMaxDynamicSharedMemorySize, GI_SMEM);
        cudaFuncSetAttribute(gemm_out_mma,   cudaFuncAttributeMaxDynamicSharedMemorySize, GO_SMEM);
        cudaFuncSetAttribute(filter_gemm,    cudaFuncAttributeMaxDynamicSharedMemorySize, 65536);
        attr_set = true;
    }

    uint32_t *p_wh, *p_wl, *p_uh, *p_ul, *p_oh, *p_ol;
    cudaGetSymbolAddress((void**)&p_wh, g_wh);
    cudaGetSymbolAddress((void**)&p_wl, g_wl);
    cudaGetSymbolAddress((void**)&p_uh, g_uh);
    cudaGetSymbolAddress((void**)&p_ul, g_ul);
    cudaGetSymbolAddress((void**)&p_oh, g_oh);
    cudaGetSymbolAddress((void**)&p_ol, g_ol);

    // gemm_in in the profiled slot (#4)
    cvt_split<<<(ODIM * DDIM / 2 + 255) / 256, 256>>>(w_in, p_wh, p_wl, ODIM * DDIM / 2);   // 1
    cvt_split<<<(BSZ * LSEQ * DDIM / 2 + 255) / 256, 256>>>(u, p_uh, p_ul, BSZ * LSEQ * DDIM / 2); // 2
    init_kernel<<<32, 256>>>();                                                              // 3
    gemm_in_mma<<<dim3(LSEQ / 128, ODIM / 128, BSZ), 256, GI_SMEM>>>(b_in);                  // 4

    // Filter path
    sact_kernel<<<LSEQ * 64 / 256, 256>>>(w1, b1);                                           // 5
    filter_gemm<<<dim3(LSEQ / 128, 2 * DDIM / 128), 256, 65536>>>(w2, b2, filt_bias, filt_decay); // 6
    hfft_kernel<<<2 * NPAIR, FFT_THREADS, FFT_SMEM>>>();                                     // 7
    cvt_split<<<(DDIM * DDIM / 2 + 255) / 256, 256>>>(w_out, p_oh, p_ol, DDIM * DDIM / 2);   // 8

    // Main path
    fftconv_kernel<<<BSZ * NPAIR, FFT_THREADS, FFT_SMEM>>>(conv_w, conv_b);                  // 9
    gemm_out_mma<<<dim3(DDIM / 128, LSEQ / 128, BSZ), 256, GO_SMEM>>>(b_out, out);           // 10
}

// round 11
// speedup vs baseline: 1.2155x; 1.0882x over previous
#include <cuda_runtime.h>
#include <cuda_bf16.h>
#include <cstdint>
#include <cstddef>

// ---------------------------------------------------------------------------
// Hyena operator: B=2, L=4096, D=1024, ORDER=2, OD=3072
// Round 11: 3-stage single-barrier GEMM pipelines with packed+swizzled smem
// (64B rows, XOR segment swizzle) -> 2 CTAs/SM retained with 96KB/CTA.
// FFT path unchanged from R10 (radix-8, conv3 fused).
// ---------------------------------------------------------------------------

#define LSEQ 4096
#define NF   8192
#define DDIM 1024
#define ODIM 3072
#define BSZ  2
#define NPAIR 512
#define FFT_THREADS 512
#define PADI(i) ((i) + ((i) >> 5))
#define SM_HALF 8448
#define FFT_SMEM (2 * SM_HALF * 4)

// Scratch (device .bss — allocation-free)
__device__ float  g_res[(size_t)BSZ * ODIM * LSEQ];
__device__ float  g_h  [(size_t)2   * DDIM * LSEQ];
__device__ float  g_sact[(size_t)LSEQ * 64];
__device__ float2 g_A  [(size_t)2 * NPAIR * NF];
__device__ float2 g_B  [(size_t)2 * NPAIR * NF];
__device__ float2 g_tw [NF];
__device__ unsigned short g_refl[NF];
// packed bf16 hi/lo operands (uint32 = 2 bf16)
__device__ uint32_t g_wh[(size_t)ODIM * DDIM / 2];
__device__ uint32_t g_wl[(size_t)ODIM * DDIM / 2];
__device__ uint32_t g_uh[(size_t)BSZ * LSEQ * DDIM / 2];
__device__ uint32_t g_ul[(size_t)BSZ * LSEQ * DDIM / 2];
__device__ uint32_t g_oh[(size_t)DDIM * DDIM / 2];
__device__ uint32_t g_ol[(size_t)DDIM * DDIM / 2];
__device__ uint32_t g_vh[(size_t)BSZ * DDIM * LSEQ / 2];
__device__ uint32_t g_vl[(size_t)BSZ * DDIM * LSEQ / 2];

// ---------------------------------------------------------------------------
__device__ __forceinline__ uint32_t smem_u32(const void* p) {
    uint32_t a;
    asm("{ .reg .u64 t; cvta.to.shared.u64 t, %1; cvt.u32.u64 %0, t; }" : "=r"(a) : "l"(p));
    return a;
}

#define LDSM_X4(r0, r1, r2, r3, addr) \
    asm volatile("ldmatrix.sync.aligned.m8n8.x4.shared.b16 {%0,%1,%2,%3}, [%4];" \
                 : "=r"(r0), "=r"(r1), "=r"(r2), "=r"(r3) : "r"(addr))
#define LDSM_X4_T(r0, r1, r2, r3, addr) \
    asm volatile("ldmatrix.sync.aligned.m8n8.x4.trans.shared.b16 {%0,%1,%2,%3}, [%4];" \
                 : "=r"(r0), "=r"(r1), "=r"(r2), "=r"(r3) : "r"(addr))
#define LDSM_X2(r0, r1, addr) \
    asm volatile("ldmatrix.sync.aligned.m8n8.x2.shared.b16 {%0,%1}, [%2];" \
                 : "=r"(r0), "=r"(r1) : "r"(addr))
#define CP_ASYNC16(dst, src) \
    asm volatile("cp.async.cg.shared.global [%0], [%1], 16;" :: "r"(dst), "l"(src))
#define CP_COMMIT() asm volatile("cp.async.commit_group;" ::: "memory")
#define CP_WAIT1()  asm volatile("cp.async.wait_group 1;" ::: "memory")

__device__ __forceinline__ void mma_bf16(float* c, const uint32_t* a, const uint32_t* b) {
    asm volatile(
        "mma.sync.aligned.m16n8k16.row.col.f32.bf16.bf16.f32 "
        "{%0,%1,%2,%3}, {%4,%5,%6,%7}, {%8,%9}, {%0,%1,%2,%3};"
        : "+f"(c[0]), "+f"(c[1]), "+f"(c[2]), "+f"(c[3])
        : "r"(a[0]), "r"(a[1]), "r"(a[2]), "r"(a[3]), "r"(b[0]), "r"(b[1]));
}

__device__ __forceinline__ uint32_t pack_hi(float x, float y) {
    __nv_bfloat16 hx = __float2bfloat16(x);
    __nv_bfloat16 hy = __float2bfloat16(y);
    return (uint32_t)__bfloat16_as_ushort(hx) | ((uint32_t)__bfloat16_as_ushort(hy) << 16);
}
__device__ __forceinline__ uint32_t pack_lo(float x, float y) {
    __nv_bfloat16 hx = __float2bfloat16(x);
    __nv_bfloat16 hy = __float2bfloat16(y);
    __nv_bfloat16 lx = __float2bfloat16(x - __bfloat162float(hx));
    __nv_bfloat16 ly = __float2bfloat16(y - __bfloat162float(hy));
    return (uint32_t)__bfloat16_as_ushort(lx) | ((uint32_t)__bfloat16_as_ushort(ly) << 16);
}

// fp32 -> packed bf16 hi/lo
__global__ void cvt_split(const float* __restrict__ src, uint32_t* __restrict__ hi,
                          uint32_t* __restrict__ lo, int n2) {
    int i = blockIdx.x * 256 + threadIdx.x;
    if (i < n2) {
        float2 v = ((const float2*)src)[i];
        hi[i] = pack_hi(v.x, v.y);
        lo[i] = pack_lo(v.x, v.y);
    }
}

// ---------------------------------------------------------------------------
// gemm_in: g_res[b,od,l] = sum_d w_in[od,d]*u[b,l,d] + b_in[od]
// CTA 128x128, 8 warps (2x4), BK=32, 3-stage cp.async, swizzled packed smem.
// Tile layout per stage: AHI@0, ALO@8192, BHI@16384, BLO@24576 (each 128x64B,
// segment swizzle seg = c16 ^ ((row>>1)&3)).
#define GI_STAGE 32768
#define GI_SMEM  (3 * GI_STAGE)

__global__ __launch_bounds__(256, 2) void gemm_in_mma(const float* __restrict__ bias)
{
    extern __shared__ char smem[];
    const uint32_t sb = smem_u32(smem);
    const int tid  = threadIdx.x;
    const int lane = tid & 31;
    const int wid  = tid >> 5;
    const int warp_m = wid >> 2;
    const int warp_n = wid & 3;

    const int b  = blockIdx.z;
    const int m0 = blockIdx.y * 128;   // od
    const int n0 = blockIdx.x * 128;   // l
    float* C = g_res + (size_t)b * ODIM * LSEQ;

    const int tile = tid >> 6;
    const int tloc = tid & 63;
    const char* gbase;
    if      (tile == 0) gbase = (const char*)g_wh + (size_t)m0 * 2048;
    else if (tile == 1) gbase = (const char*)g_wl + (size_t)m0 * 2048;
    else if (tile == 2) gbase = (const char*)g_uh + (size_t)(b * LSEQ + n0) * 2048;
    else                gbase = (const char*)g_ul + (size_t)(b * LSEQ + n0) * 2048;

    float acc[4][4][4];
    #pragma unroll
    for (int i = 0; i < 4; i++)
        #pragma unroll
        for (int j = 0; j < 4; j++)
            #pragma unroll
            for (int r = 0; r < 4; r++) acc[i][j][r] = 0.0f;

    // ldmatrix lane-constant address components
    const int ar  = (lane & 7) + ((lane & 8) ? 8 : 0);   // A row within 16
    const int sA  = (ar >> 1) & 3;                       // A swizzle
    const int a16 = (lane & 16) ? 1 : 0;                 // A col16 lsb
    const int br  = lane & 7;                            // B row within 8
    const int sB  = (br >> 1) & 3;
    const int b16 = (lane & 8) ? 1 : 0;

    // store indices (per thread, 8 ops/chunk): row = idx>>2, c = idx&3
    // dst = stage + tile*8192 + row*64 + ((c ^ ((row>>1)&3))<<4)

    // prologue: chunks 0,1 -> stages 0,1
    #pragma unroll
    for (int p = 0; p < 2; p++) {
        #pragma unroll
        for (int o = 0; o < 8; o++) {
            int idx = tloc + o * 64, row = idx >> 2, c = idx & 3;
            uint32_t dst = sb + p * GI_STAGE + tile * 8192 + row * 64
                         + (((c ^ ((row >> 1) & 3))) << 4);
            CP_ASYNC16(dst, gbase + (size_t)row * 2048 + p * 64 + c * 16);
        }
        CP_COMMIT();
    }

    for (int ch = 0; ch < 32; ch++) {
        CP_WAIT1();
        __syncthreads();
        // prefetch chunk ch+2 into stage (ch+2)%3 (freed two iterations ago)
        if (ch + 2 < 32) {
            const int st = (ch + 2) % 3;
            #pragma unroll
            for (int o = 0; o < 8; o++) {
                int idx = tloc + o * 64, row = idx >> 2, c = idx & 3;
                uint32_t dst = sb + st * GI_STAGE + tile * 8192 + row * 64
                             + (((c ^ ((row >> 1) & 3))) << 4);
                CP_ASYNC16(dst, gbase + (size_t)row * 2048 + (ch + 2) * 64 + c * 16);
            }
        }
        CP_COMMIT();

        const uint32_t sbase = sb + (ch % 3) * GI_STAGE;
        #pragma unroll
        for (int k16 = 0; k16 < 2; k16++) {
            uint32_t bh[4][2], bl[4][2];
            #pragma unroll
            for (int j = 0; j < 4; j++) {
                uint32_t rb = sbase + 16384 + (warp_n * 32 + j * 8 + br) * 64
                            + (((k16 * 2 + b16) ^ sB) << 4);
                LDSM_X2(bh[j][0], bh[j][1], rb);
                LDSM_X2(bl[j][0], bl[j][1], rb + 8192);
            }
            #pragma unroll
            for (int i = 0; i < 4; i++) {
                uint32_t ah[4], al[4];
                uint32_t ra = sbase + (warp_m * 64 + i * 16 + ar) * 64
                            + (((k16 * 2 + a16) ^ sA) << 4);
                LDSM_X4(ah[0], ah[1], ah[2], ah[3], ra);
                LDSM_X4(al[0], al[1], al[2], al[3], ra + 8192);
                #pragma unroll
                for (int j = 0; j < 4; j++) {
                    mma_bf16(acc[i][j], ah, bh[j]);
                    mma_bf16(acc[i][j], ah, bl[j]);
                    mma_bf16(acc[i][j], al, bh[j]);
                }
            }
        }
    }

    const int g = lane >> 2;
    const int t = lane & 3;
    #pragma unroll
    for (int i = 0; i < 4; i++) {
        int od0 = m0 + warp_m * 64 + i * 16 + g;
        float bv0 = bias[od0];
        float bv1 = bias[od0 + 8];
        #pragma unroll
        for (int j = 0; j < 4; j++) {
            int l = n0 + warp_n * 32 + j * 8 + t * 2;
            *(float2*)&C[(size_t)od0 * LSEQ + l] =
                make_float2(acc[i][j][0] + bv0, acc[i][j][1] + bv0);
            *(float2*)&C[(size_t)(od0 + 8) * LSEQ + l] =
                make_float2(acc[i][j][2] + bv1, acc[i][j][3] + bv1);
        }
    }
}

// ---------------------------------------------------------------------------
// gemm_out: out[b,l,e] = sum_d v[b,d,l]*w_out[e,d] + b_out[e]
// A = v^T tiles: 32 rows(d) x 256B(l), swizzle seg = c16 ^ (row&7).
// B = w_out rows: 128 x 64B, swizzle as gemm_in.
// Stage: AHI@0, ALO@8192, BHI@16384, BLO@24576.
#define GO_STAGE 32768
#define GO_SMEM  (3 * GO_STAGE)

__global__ __launch_bounds__(256, 2) void gemm_out_mma(const float* __restrict__ bias,
                                                       float* __restrict__ O)
{
    extern __shared__ char smem[];
    const uint32_t sb = smem_u32(smem);
    const int tid  = threadIdx.x;
    const int lane = tid & 31;
    const int wid  = tid >> 5;
    const int warp_m = wid >> 2;
    const int warp_n = wid & 3;

    const int b  = blockIdx.z;
    const int m0 = blockIdx.y * 128;   // l
    const int n0 = blockIdx.x * 128;   // e
    float* C = O + (size_t)b * LSEQ * DDIM;

    const int tile = tid >> 6;     // 0:v_hi 1:v_lo 2:wo_hi 3:wo_lo
    const int tloc = tid & 63;
    const char* gbase;
    if      (tile == 0) gbase = (const char*)g_vh + (size_t)(b * DDIM) * 8192 + (size_t)m0 * 2;
    else if (tile == 1) gbase = (const char*)g_vl + (size_t)(b * DDIM) * 8192 + (size_t)m0 * 2;
    else if (tile == 2) gbase = (const char*)g_oh + (size_t)n0 * 2048;
    else                gbase = (const char*)g_ol + (size_t)n0 * 2048;

    float acc[4][4][4];
    #pragma unroll
    for (int i = 0; i < 4; i++)
        #pragma unroll
        for (int j = 0; j < 4; j++)
            #pragma unroll
            for (int r = 0; r < 4; r++) acc[i][j][r] = 0.0f;

    // lane-constant components
    const int tr  = (lane & 7) + ((lane & 16) ? 8 : 0);  // A(trans) row within 16 (d)
    const int sT  = lane & 7;                            // A swizzle (rowd&7)
    const int t16 = (lane & 8) ? 1 : 0;                  // A col16 lsb
    const int br  = lane & 7;
    const int sB  = (br >> 1) & 3;
    const int b16 = (lane & 8) ? 1 : 0;

    // prologue: chunks 0,1 -> stages 0,1
    #pragma unroll
    for (int p = 0; p < 2; p++) {
        if (tile < 2) {
            #pragma unroll
            for (int o = 0; o < 8; o++) {
                int idx = tloc + o * 64, row = idx >> 4, c16 = idx & 15;
                uint32_t dst = sb + p * GO_STAGE + tile * 8192 + row * 256
                             + (((c16 ^ (row & 7))) << 4);
                CP_ASYNC16(dst, gbase + (size_t)(p * 32 + row) * 8192 + c16 * 16);
            }
        } else {
            #pragma unroll
            for (int o = 0; o < 8; o++) {
                int idx = tloc + o * 64, row = idx >> 2, c = idx & 3;
                uint32_t dst = sb + p * GO_STAGE + (tile - 2) * 8192 + 16384 + row * 64
                             + (((c ^ ((row >> 1) & 3))) << 4);
                CP_ASYNC16(dst, gbase + (size_t)row * 2048 + p * 64 + c * 16);
            }
        }
        CP_COMMIT();
    }

    for (int ch = 0; ch < 32; ch++) {
        CP_WAIT1();
        __syncthreads();
        if (ch + 2 < 32) {
            const int st = (ch + 2) % 3;
            if (tile < 2) {
                #pragma unroll
                for (int o = 0; o < 8; o++) {
                    int idx = tloc + o * 64, row = idx >> 4, c16 = idx & 15;
                    uint32_t dst = sb + st * GO_STAGE + tile * 8192 + row * 256
                                 + (((c16 ^ (row & 7))) << 4);
                    CP_ASYNC16(dst, gbase + (size_t)((ch + 2) * 32 + row) * 8192 + c16 * 16);
                }
            } else {
                #pragma unroll
                for (int o = 0; o < 8; o++) {
                    int idx = tloc + o * 64, row = idx >> 2, c = idx & 3;
                    uint32_t dst = sb + st * GO_STAGE + (tile - 2) * 8192 + 16384 + row * 64
                                 + (((c ^ ((row >> 1) & 3))) << 4);
                    CP_ASYNC16(dst, gbase + (size_t)row * 2048 + (ch + 2) * 64 + c * 16);
                }
            }
        }
        CP_COMMIT();

        const uint32_t sbase = sb + (ch % 3) * GO_STAGE;
        #pragma unroll
        for (int k16 = 0; k16 < 2; k16++) {
            uint32_t bh[4][2], bl[4][2];
            #pragma unroll
            for (int j = 0; j < 4; j++) {
                uint32_t rb = sbase + 16384 + (warp_n * 32 + j * 8 + br) * 64
                            + (((k16 * 2 + b16) ^ sB) << 4);
                LDSM_X2(bh[j][0], bh[j][1], rb);
                LDSM_X2(bl[j][0], bl[j][1], rb + 8192);
            }
            #pragma unroll
            for (int i = 0; i < 4; i++) {
                uint32_t ah[4], al[4];
                int rowd = k16 * 16 + tr;
                uint32_t ra = sbase + rowd * 256
                            + (((warp_m * 8 + i * 2 + t16) ^ sT) << 4);
                LDSM_X4_T(ah[0], ah[1], ah[2], ah[3], ra);
                LDSM_X4_T(al[0], al[1], al[2], al[3], ra + 8192);
                #pragma unroll
                for (int j = 0; j < 4; j++) {
                    mma_bf16(acc[i][j], ah, bh[j]);
                    mma_bf16(acc[i][j], ah, bl[j]);
                    mma_bf16(acc[i][j], al, bh[j]);
                }
            }
        }
    }

    const int g = lane >> 2;
    const int t = lane & 3;
    #pragma unroll
    for (int j = 0; j < 4; j++) {
        int e = n0 + warp_n * 32 + j * 8 + t * 2;
        float bb0 = bias[e];
        float bb1 = bias[e + 1];
        #pragma unroll
        for (int i = 0; i < 4; i++) {
            int l = m0 + warp_m * 64 + i * 16 + g;
            *(float2*)&C[(size_t)l * DDIM + e] =
                make_float2(acc[i][j][0] + bb0, acc[i][j][1] + bb1);
            *(float2*)&C[(size_t)(l + 8) * DDIM + e] =
                make_float2(acc[i][j][2] + bb0, acc[i][j][3] + bb1);
        }
    }
}

// ---------------------------------------------------------------------------
// Mixed-radix [2,8,8,8,8] digit maps.
__device__ __forceinline__ int freq_to_slot(int k) {
    return (k & 1) * 4096 + ((k >> 1) & 7) * 512 + ((k >> 4) & 7) * 64
         + ((k >> 7) & 7) * 8 + ((k >> 10) & 7);
}
__device__ __forceinline__ int slot_to_freq(int p) {
    return ((p >> 12) & 1) | (((p >> 9) & 7) << 1) | (((p >> 6) & 7) << 4)
         | (((p >> 3) & 7) << 7) | ((p & 7) << 10);
}

__global__ void init_kernel() {
    int i = blockIdx.x * blockDim.x + threadIdx.x;
    if (i < NF) {
        double ang = -2.0 * 3.141592653589793238462643 * (double)i / (double)NF;
        g_tw[i] = make_float2((float)cos(ang), (float)sin(ang));
        int k  = slot_to_freq(i);
        int kp = (NF - k) & (NF - 1);
        g_refl[i] = (unsigned short)freq_to_slot(kp);
    }
}

// ---------------------------------------------------------------------------
// Filter path
__global__ __launch_bounds__(256) void sact_kernel(
    const float* __restrict__ w1, const float* __restrict__ b1)
{
    int idx = blockIdx.x * 256 + threadIdx.x;   // l*64 + u
    int l = idx >> 6;
    int u = idx & 63;
    float t = (float)l * (1.0f / (float)(LSEQ - 1));
    float z = b1[u];
    #pragma unroll
    for (int j = 0; j < 33; j++) z += sinf(t * (float)j * 10.0f) * w1[u * 33 + j];
    g_sact[idx] = sinf(10.0f * z);
}

__global__ __launch_bounds__(256) void filter_gemm(
    const float* __restrict__ w2, const float* __restrict__ b2,
    const float* __restrict__ fb, const float* __restrict__ fd)
{
    extern __shared__ float fsm[];
    float (*As)[128] = (float(*)[128])fsm;
    float (*Bs)[128] = (float(*)[128])(fsm + 64 * 128);
    const int o0 = blockIdx.y * 128;
    const int l0 = blockIdx.x * 128;
    const int tid = threadIdx.x;
    const int tm = tid >> 4;
    const int tn = tid & 15;
    const int lrow = tid >> 1;
    const int lk   = (tid & 1) * 32;

    #pragma unroll
    for (int f = 0; f < 8; f++) {
        float4 a = *(const float4*)&w2[(size_t)(o0 + lrow) * 64 + lk + f * 4];
        As[lk + f * 4 + 0][lrow] = a.x; As[lk + f * 4 + 1][lrow] = a.y;
        As[lk + f * 4 + 2][lrow] = a.z; As[lk + f * 4 + 3][lrow] = a.w;
        float4 s = *(const float4*)&g_sact[(size_t)(l0 + lrow) * 64 + lk + f * 4];
        Bs[lk + f * 4 + 0][lrow] = s.x; Bs[lk + f * 4 + 1][lrow] = s.y;
        Bs[lk + f * 4 + 2][lrow] = s.z; Bs[lk + f * 4 + 3][lrow] = s.w;
    }
    __syncthreads();

    float acc[8][8];
    #pragma unroll
    for (int i = 0; i < 8; i++)
        #pragma unroll
        for (int j = 0; j < 8; j++) acc[i][j] = 0.0f;

    #pragma unroll
    for (int k = 0; k < 64; k++) {
        float4 ra0 = *(const float4*)&As[k][tm * 8];
        float4 ra1 = *(const float4*)&As[k][tm * 8 + 4];
        float4 rb0 = *(const float4*)&Bs[k][tn * 8];
        float4 rb1 = *(const float4*)&Bs[k][tn * 8 + 4];
        float ra[8] = {ra0.x, ra0.y, ra0.z, ra0.w, ra1.x, ra1.y, ra1.z, ra1.w};
        float rb[8] = {rb0.x, rb0.y, rb0.z, rb0.w, rb1.x, rb1.y, rb1.z, rb1.w};
        #pragma unroll
        for (int i = 0; i < 8; i++)
            #pragma unroll
            for (int j = 0; j < 8; j++) acc[i][j] += ra[i] * rb[j];
    }

    #pragma unroll
    for (int i = 0; i < 8; i++) {
        int o = o0 + tm * 8 + i;
        float ed  = expf(fd[o]);
        float bb  = b2[o];
        float fbo = fb[o];
        float v[8];
        #pragma unroll
        for (int j = 0; j < 8; j++) {
            int l = l0 + tn * 8 + j;
            float t = (float)l * (1.0f / (float)(LSEQ - 1));
            v[j] = ((acc[i][j] + bb) * expf(-ed * t) + fbo) * (1.0f / (float)LSEQ);
        }
        *(float4*)&g_h[(size_t)o * LSEQ + l0 + tn * 8]     = make_float4(v[0], v[1], v[2], v[3]);
        *(float4*)&g_h[(size_t)o * LSEQ + l0 + tn * 8 + 4] = make_float4(v[4], v[5], v[6], v[7]);
    }
}

// ---------------------------------------------------------------------------
// FFT: 8192-pt, 512 threads, split re/im padded smem, mixed radix [2,8,8,8,8].
#define FFT_C 0.70710678118654752f

__device__ __forceinline__ void fft_fwd_zp(float* __restrict__ SR, float* __restrict__ SI) {
    #pragma unroll
    for (int jj = 0; jj < 8; jj++) {
        int j  = threadIdx.x + jj * FFT_THREADS;
        int i0 = PADI(j), i1 = PADI(j + 4096);
        float ar = SR[i0], ai = SI[i0];
        float2 w = g_tw[j];
        SR[i1] = ar * w.x - ai * w.y;
        SI[i1] = ar * w.y + ai * w.x;
    }
    __syncthreads();
    #pragma unroll
    for (int s = 0; s < 4; s++) {
        const int lm  = 9 - 3 * s;
        const int m   = 1 << lm;
        const int str = 1024 >> lm;
        #pragma unroll
        for (int jj = 0; jj < 2; jj++) {
            int t = threadIdx.x + jj * FFT_THREADS;
            int q = t & (m - 1);
            int base = ((t >> lm) << (lm + 3)) | q;
            int p0 = PADI(base), p1 = PADI(base + m), p2 = PADI(base + 2 * m),
                p3 = PADI(base + 3 * m), p4 = PADI(base + 4 * m), p5 = PADI(base + 5 * m),
                p6 = PADI(base + 6 * m), p7 = PADI(base + 7 * m);
            float x0r = SR[p0], x0i = SI[p0];
            float x1r = SR[p1], x1i = SI[p1];
            float x2r = SR[p2], x2i = SI[p2];
            float x3r = SR[p3], x3i = SI[p3];
            float x4r = SR[p4], x4i = SI[p4];
            float x5r = SR[p5], x5i = SI[p5];
            float x6r = SR[p6], x6i = SI[p6];
            float x7r = SR[p7], x7i = SI[p7];
            float a0r = x0r + x4r, a0i = x0i + x4i;
            float a1r = x1r + x5r, a1i = x1i + x5i;
            float a2r = x2r + x6r, a2i = x2i + x6i;
            float a3r = x3r + x7r, a3i = x3i + x7i;
            float b0r = x0r - x4r, b0i = x0i - x4i;
            float b1r = x1r - x5r, b1i = x1i - x5i;
            float b2r = x2r - x6r, b2i = x2i - x6i;
            float b3r = x3r - x7r, b3i = x3i - x7i;
            float u1r =  FFT_C * (b1r + b1i), u1i = FFT_C * (b1i - b1r);
            float u2r =  b2i,                 u2i = -b2r;
            float u3r = -FFT_C * (b3r - b3i), u3i = -FFT_C * (b3r + b3i);
            float t0r = a0r + a2r, t0i = a0i + a2i;
            float t1r = a1r + a3r, t1i = a1i + a3i;
            float t2r = a0r - a2r, t2i = a0i - a2i;
            float t3r = a1i - a3i, t3i = a3r - a1r;
            float X0r = t0r + t1r, X0i = t0i + t1i;
            float X2r = t2r + t3r, X2i = t2i + t3i;
            float X4r = t0r - t1r, X4i = t0i - t1i;
            float X6r = t2r - t3r, X6i = t2i - t3i;
            float s0r = b0r + u2r, s0i = b0i + u2i;
            float s1r = u1r + u3r, s1i = u1i + u3i;
            float s2r = b0r - u2r, s2i = b0i - u2i;
            float s3r = u1i - u3i, s3i = u3r - u1r;
            float X1r = s0r + s1r, X1i = s0i + s1i;
            float X3r = s2r + s3r, X3i = s2i + s3i;
            float X5r = s0r - s1r, X5i = s0i - s1i;
            float X7r = s2r - s3r, X7i = s2i - s3i;
            SR[p0] = X0r; SI[p0] = X0i;
            if (lm > 0) {
                int tb = q * str;
                float2 w1 = g_tw[tb],     w2 = g_tw[2 * tb], w3 = g_tw[3 * tb];
                float2 w4 = g_tw[4 * tb], w5 = g_tw[5 * tb], w6 = g_tw[6 * tb];
                float2 w7 = g_tw[7 * tb];
                SR[p1] = X1r * w1.x - X1i * w1.y; SI[p1] = X1r * w1.y + X1i * w1.x;
                SR[p2] = X2r * w2.x - X2i * w2.y; SI[p2] = X2r * w2.y + X2i * w2.x;
                SR[p3] = X3r * w3.x - X3i * w3.y; SI[p3] = X3r * w3.y + X3i * w3.x;
                SR[p4] = X4r * w4.x - X4i * w4.y; SI[p4] = X4r * w4.y + X4i * w4.x;
                SR[p5] = X5r * w5.x - X5i * w5.y; SI[p5] = X5r * w5.y + X5i * w5.x;
                SR[p6] = X6r * w6.x - X6i * w6.y; SI[p6] = X6r * w6.y + X6i * w6.x;
                SR[p7] = X7r * w7.x - X7i * w7.y; SI[p7] = X7r * w7.y + X7i * w7.x;
            } else {
                SR[p1] = X1r; SI[p1] = X1i;
                SR[p2] = X2r; SI[p2] = X2i;
                SR[p3] = X3r; SI[p3] = X3i;
                SR[p4] = X4r; SI[p4] = X4i;
                SR[p5] = X5r; SI[p5] = X5i;
                SR[p6] = X6r; SI[p6] = X6i;
                SR[p7] = X7r; SI[p7] = X7i;
            }
        }
        __syncthreads();
    }
}

__device__ __forceinline__ void fft_inv_half(float* __restrict__ SR, float* __restrict__ SI) {
    #pragma unroll
    for (int s = 0; s < 4; s++) {
        const int lm  = 3 * s;
        const int m   = 1 << lm;
        const int str = 1024 >> lm;
        #pragma unroll
        for (int jj = 0; jj < 2; jj++) {
            int t = threadIdx.x + jj * FFT_THREADS;
            int q = t & (m - 1);
            int base = ((t >> lm) << (lm + 3)) | q;
            int p0 = PADI(base), p1 = PADI(base + m), p2 = PADI(base + 2 * m),
                p3 = PADI(base + 3 * m), p4 = PADI(base + 4 * m), p5 = PADI(base + 5 * m),
                p6 = PADI(base + 6 * m), p7 = PADI(base + 7 * m);
            float y0r = SR[p0], y0i = SI[p0];
            float y1r = SR[p1], y1i = SI[p1];
            float y2r = SR[p2], y2i = SI[p2];
            float y3r = SR[p3], y3i = SI[p3];
            float y4r = SR[p4], y4i = SI[p4];
            float y5r = SR[p5], y5i = SI[p5];
            float y6r = SR[p6], y6i = SI[p6];
            float y7r = SR[p7], y7i = SI[p7];
            if (lm > 0) {
                int tb = q * str;
                float2 w1 = g_tw[tb],     w2 = g_tw[2 * tb], w3 = g_tw[3 * tb];
                float2 w4 = g_tw[4 * tb], w5 = g_tw[5 * tb], w6 = g_tw[6 * tb];
                float2 w7 = g_tw[7 * tb];
                float cr;
                cr = y1r * w1.x + y1i * w1.y; y1i = y1i * w1.x - y1r * w1.y; y1r = cr;
                cr = y2r * w2.x + y2i * w2.y; y2i = y2i * w2.x - y2r * w2.y; y2r = cr;
                cr = y3r * w3.x + y3i * w3.y; y3i = y3i * w3.x - y3r * w3.y; y3r = cr;
                cr = y4r * w4.x + y4i * w4.y; y4i = y4i * w4.x - y4r * w4.y; y4r = cr;
                cr = y5r * w5.x + y5i * w5.y; y5i = y5i * w5.x - y5r * w5.y; y5r = cr;
                cr = y6r * w6.x + y6i * w6.y; y6i = y6i * w6.x - y6r * w6.y; y6r = cr;
                cr = y7r * w7.x + y7i * w7.y; y7i = y7i * w7.x - y7r * w7.y; y7r = cr;
            }
            float t0r = y0r + y4r, t0i = y0i + y4i;
            float t1r = y2r + y6r, t1i = y2i + y6i;
            float t2r = y0r - y4r, t2i = y0i - y4i;
            float t3r = y6i - y2i, t3i = y2r - y6r;
            float a0r = t0r + t1r, a0i = t0i + t1i;
            float a1r = t2r + t3r, a1i = t2i + t3i;
            float a2r = t0r - t1r, a2i = t0i - t1i;
            float a3r = t2r - t3r, a3i = t2i - t3i;
            float s0r = y1r + y5r, s0i = y1i + y5i;
            float s1r = y3r + y7r, s1i = y3i + y7i;
            float s2r = y1r - y5r, s2i = y1i - y5i;
            float s3r = y7i - y3i, s3i = y3r - y7r;
            float d0r = s0r + s1r, d0i = s0i + s1i;
            float d1r = s2r + s3r, d1i = s2i + s3i;
            float d2r = s0r - s1r, d2i = s0i - s1i;
            float d3r = s2r - s3r, d3i = s2i - s3i;
            float e1r =  FFT_C * (d1r - d1i), e1i = FFT_C * (d1r + d1i);
            float e2r = -d2i,                 e2i = d2r;
            float e3r = -FFT_C * (d3r + d3i), e3i = FFT_C * (d3r - d3i);
            SR[p0] = a0r + d0r; SI[p0] = a0i + d0i;
            SR[p4] = a0r - d0r; SI[p4] = a0i - d0i;
            SR[p1] = a1r + e1r; SI[p1] = a1i + e1i;
            SR[p5] = a1r - e1r; SI[p5] = a1i - e1i;
            SR[p2] = a2r + e2r; SI[p2] = a2i + e2i;
            SR[p6] = a2r - e2r; SI[p6] = a2i - e2i;
            SR[p3] = a3r + e3r; SI[p3] = a3i + e3i;
            SR[p7] = a3r - e3r; SI[p7] = a3i - e3i;
        }
        __syncthreads();
    }
    #pragma unroll
    for (int jj = 0; jj < 8; jj++) {
        int j  = threadIdx.x + jj * FFT_THREADS;
        int i0 = PADI(j), i1 = PADI(j + 4096);
        float2 w = g_tw[j];
        float br = SR[i1], bi = SI[i1];
        float tr = br * w.x + bi * w.y;
        float ti = bi * w.x - br * w.y;
        SR[i0] += tr; SI[i0] += ti;
    }
    __syncthreads();
}

// ---------------------------------------------------------------------------
__global__ __launch_bounds__(FFT_THREADS) void hfft_kernel() {
    extern __shared__ float sm[];
    float* SR = sm;
    float* SI = sm + SM_HALF;
    const int c = blockIdx.x;
    const int n = c >> 9;
    const int dpair = c & (NPAIR - 1);
    const float* h0 = g_h + ((size_t)n * DDIM + 2 * dpair)     * LSEQ;
    const float* h1 = g_h + ((size_t)n * DDIM + 2 * dpair + 1) * LSEQ;

    for (int i = threadIdx.x; i < LSEQ; i += FFT_THREADS) {
        SR[PADI(i)] = h0[i]; SI[PADI(i)] = h1[i];
    }
    __syncthreads();
    fft_fwd_zp(SR, SI);

    float2* Ao = g_A + (size_t)c * NF;
    float2* Bo = g_B + (size_t)c * NF;
    for (int p = threadIdx.x; p < NF; p += FFT_THREADS) {
        int q = g_refl[p];
        if (q < p) continue;
        float zpr = SR[PADI(p)], zpi = SI[PADI(p)];
        float zqr = SR[PADI(q)], zqi = SI[PADI(q)];
        float g0r = 0.5f * (zpr + zqr), g0i = 0.5f * (zpi - zqi);
        float g1r = 0.5f * (zpi + zqi), g1i = 0.5f * (zqr - zpr);
        Ao[p] = make_float2(0.5f * (g0r + g1r), 0.5f * (g0i + g1i));
        Bo[p] = make_float2(0.5f * (g0r - g1r), 0.5f * (g0i - g1i));
    }
}

// ---------------------------------------------------------------------------
__device__ __forceinline__ float conv3_at(const float* __restrict__ r, int l,
                                          float w0, float w1, float w2, float cb) {
    float left  = (l > 0)        ? r[l - 1] : 0.0f;
    float right = (l < LSEQ - 1) ? r[l + 1] : 0.0f;
    return w0 * left + w1 * r[l] + w2 * right + cb;
}

__global__ __launch_bounds__(FFT_THREADS) void fftconv_kernel(
    const float* __restrict__ cw, const float* __restrict__ cbv)
{
    extern __shared__ float sm[];
    float* SR = sm;
    float* SI = sm + SM_HALF;
    const int c = blockIdx.x;
    const int b = c >> 9;
    const int dpair = c & (NPAIR - 1);
    const int ch0 = 2 * dpair, ch1 = ch0 + 1;
    const float inv = 1.0f / (float)NF;

    {
        const float* r2a = g_res + ((size_t)(b * 3 + 2) * DDIM + ch0) * LSEQ;
        const float* r2b = g_res + ((size_t)(b * 3 + 2) * DDIM + ch1) * LSEQ;
        const int oa = 2 * DDIM + ch0, ob = 2 * DDIM + ch1;
        float w0a = cw[oa * 3], w1a = cw[oa * 3 + 1], w2a = cw[oa * 3 + 2], cba = cbv[oa];
        float w0b = cw[ob * 3], w1b = cw[ob * 3 + 1], w2b = cw[ob * 3 + 2], cbb = cbv[ob];
        for (int i = threadIdx.x; i < LSEQ; i += FFT_THREADS) {
            SR[PADI(i)] = conv3_at(r2a, i, w0a, w1a, w2a, cba);
            SI[PADI(i)] = conv3_at(r2b, i, w0b, w1b, w2b, cbb);
        }
    }
    __syncthreads();

    #pragma unroll 1
    for (int n = 0; n < 2; n++) {
        fft_fwd_zp(SR, SI);

        const float2* Ap = g_A + ((size_t)n * NPAIR + dpair) * NF;
        const float2* Bp = g_B + ((size_t)n * NPAIR + dpair) * NF;
        #pragma unroll
        for (int jj = 0; jj < NF / FFT_THREADS; jj++) {
            int p = threadIdx.x + jj * FFT_THREADS;
            int q = g_refl[p];
            if (q < p) continue;
            int ip = PADI(p), iq = PADI(q);
            float zr = SR[ip], zi = SI[ip];
            float wr = SR[iq], wi = SI[iq];
            float2 a  = Ap[p];
            float2 bb = Bp[p];
            float ypr = a.x * zr - a.y * zi + bb.x * wr + bb.y * wi;
            float ypi = a.x * zi + a.y * zr + bb.y * wr - bb.x * wi;
            float yqr = a.x * wr + a.y * wi + bb.x * zr - bb.y * zi;
            float yqi = a.x * wi - a.y * wr - bb.x * zi - bb.y * zr;
            SR[ip] = ypr; SI[ip] = ypi;
            SR[iq] = yqr; SI[iq] = yqi;
        }
        __syncthreads();

        fft_inv_half(SR, SI);

        const float* rna = g_res + ((size_t)(b * 3 + n) * DDIM + ch0) * LSEQ;
        const float* rnb = g_res + ((size_t)(b * 3 + n) * DDIM + ch1) * LSEQ;
        const int oa = n * DDIM + ch0, ob = n * DDIM + ch1;
        float w0a = cw[oa * 3], w1a = cw[oa * 3 + 1], w2a = cw[oa * 3 + 2], cba = cbv[oa];
        float w0b = cw[ob * 3], w1b = cw[ob * 3 + 1], w2b = cw[ob * 3 + 2], cbb = cbv[ob];

        if (n == 0) {
            for (int l = threadIdx.x; l < LSEQ; l += FFT_THREADS) {
                int ip = PADI(l);
                SR[ip] = SR[ip] * inv * conv3_at(rna, l, w0a, w1a, w2a, cba);
                SI[ip] = SI[ip] * inv * conv3_at(rnb, l, w0b, w1b, w2b, cbb);
            }
            __syncthreads();
        } else {
            uint32_t* vh0 = g_vh + ((size_t)(b * DDIM + ch0)) * (LSEQ / 2);
            uint32_t* vl0 = g_vl + ((size_t)(b * DDIM + ch0)) * (LSEQ / 2);
            uint32_t* vh1 = g_vh + ((size_t)(b * DDIM + ch1)) * (LSEQ / 2);
            uint32_t* vl1 = g_vl + ((size_t)(b * DDIM + ch1)) * (LSEQ / 2);
            for (int l2 = threadIdx.x; l2 < LSEQ / 2; l2 += FFT_THREADS) {
                int l = 2 * l2;
                float y0a = SR[PADI(l)]     * inv * conv3_at(rna, l,     w0a, w1a, w2a, cba);
                float y0b = SR[PADI(l + 1)] * inv * conv3_at(rna, l + 1, w0a, w1a, w2a, cba);
                float y1a = SI[PADI(l)]     * inv * conv3_at(rnb, l,     w0b, w1b, w2b, cbb);
                float y1b = SI[PADI(l + 1)] * inv * conv3_at(rnb, l + 1, w0b, w1b, w2b, cbb);
                vh0[l2] = pack_hi(y0a, y0b); vl0[l2] = pack_lo(y0a, y0b);
                vh1[l2] = pack_hi(y1a, y1b); vl1[l2] = pack_lo(y1a, y1b);
            }
        }
    }
}

// ---------------------------------------------------------------------------
extern "C" void kernel_launch(void* const* d_in, const int* in_sizes, int n_in,
                              void* d_out, int out_size)
{
    const float* u          = (const float*)d_in[0];
    const float* w_in       = (const float*)d_in[1];
    const float* b_in       = (const float*)d_in[2];
    const float* conv_w     = (const float*)d_in[3];
    const float* conv_b     = (const float*)d_in[4];
    const float* w1         = (const float*)d_in[5];
    const float* b1         = (const float*)d_in[6];
    const float* w2         = (const float*)d_in[7];
    const float* b2         = (const float*)d_in[8];
    const float* filt_bias  = (const float*)d_in[9];
    const float* filt_decay = (const float*)d_in[10];
    const float* w_out      = (const float*)d_in[11];
    const float* b_out      = (const float*)d_in[12];
    float* out = (float*)d_out;

    static bool attr_set = false;
    if (!attr_set) {
        cudaFuncSetAttribute(hfft_kernel,    cudaFuncAttributeMaxDynamicSharedMemorySize, FFT_SMEM);
        cudaFuncSetAttribute(fftconv_kernel, cudaFuncAttributeMaxDynamicSharedMemorySize, FFT_SMEM);
        cudaFuncSetAttribute(gemm_in_mma,    cudaFuncAttributeMaxDynamicSharedMemorySize, GI_SMEM);
        cudaFuncSetAttribute(gemm_out_mma,   cudaFuncAttributeMaxDynamicSharedMemorySize, GO_SMEM);
        cudaFuncSetAttribute(filter_gemm,    cudaFuncAttributeMaxDynamicSharedMemorySize, 65536);
        attr_set = true;
    }

    uint32_t *p_wh, *p_wl, *p_uh, *p_ul, *p_oh, *p_ol;
    cudaGetSymbolAddress((void**)&p_wh, g_wh);
    cudaGetSymbolAddress((void**)&p_wl, g_wl);
    cudaGetSymbolAddress((void**)&p_uh, g_uh);
    cudaGetSymbolAddress((void**)&p_ul, g_ul);
    cudaGetSymbolAddress((void**)&p_oh, g_oh);
    cudaGetSymbolAddress((void**)&p_ol, g_ol);

    // gemm_in in the profiled slot (#4)
    cvt_split<<<(ODIM * DDIM / 2 + 255) / 256, 256>>>(w_in, p_wh, p_wl, ODIM * DDIM / 2);   // 1
    cvt_split<<<(BSZ * LSEQ * DDIM / 2 + 255) / 256, 256>>>(u, p_uh, p_ul, BSZ * LSEQ * DDIM / 2); // 2
    init_kernel<<<32, 256>>>();                                                              // 3
    gemm_in_mma<<<dim3(LSEQ / 128, ODIM / 128, BSZ), 256, GI_SMEM>>>(b_in);                  // 4

    // Filter path
    sact_kernel<<<LSEQ * 64 / 256, 256>>>(w1, b1);                                           // 5
    filter_gemm<<<dim3(LSEQ / 128, 2 * DDIM / 128), 256, 65536>>>(w2, b2, filt_bias, filt_decay); // 6
    hfft_kernel<<<2 * NPAIR, FFT_THREADS, FFT_SMEM>>>();                                     // 7
    cvt_split<<<(DDIM * DDIM / 2 + 255) / 256, 256>>>(w_out, p_oh, p_ol, DDIM * DDIM / 2);   // 8

    // Main path
    fftconv_kernel<<<BSZ * NPAIR, FFT_THREADS, FFT_SMEM>>>(conv_w, conv_b);                  // 9
    gemm_out_mma<<<dim3(DDIM / 128, LSEQ / 128, BSZ), 256, GO_SMEM>>>(b_out, out);           // 10
}

// round 12
// speedup vs baseline: 1.2227x; 1.0059x over previous
#include <cuda_runtime.h>
#include <cuda_bf16.h>
#include <cstdint>
#include <cstddef>

// ---------------------------------------------------------------------------
// Hyena operator: B=2, L=4096, D=1024, ORDER=2, OD=3072
// Round 12: k-indexed pair spectrum loops (coalesced, half-size A/B tables),
// fused prep kernel + filter_gemm fused into gemm_in launch (5 launches),
// register double-buffered A fragments in both GEMMs.
// ---------------------------------------------------------------------------

#define LSEQ 4096
#define NF   8192
#define DDIM 1024
#define ODIM 3072
#define BSZ  2
#define NPAIR 512
#define NK    4100            // 4097 used, padded
#define FFT_THREADS 512
#define PADI(i) ((i) + ((i) >> 5))
#define SM_HALF 8448
#define FFT_SMEM (2 * SM_HALF * 4)

// Scratch (device .bss — allocation-free)
__device__ float  g_res[(size_t)BSZ * ODIM * LSEQ];
__device__ float  g_h  [(size_t)2   * DDIM * LSEQ];
__device__ float  g_sact[(size_t)LSEQ * 64];
__device__ float2 g_A  [(size_t)2 * NPAIR * NK];
__device__ float2 g_B  [(size_t)2 * NPAIR * NK];
__device__ float2 g_tw [NF];
// packed bf16 hi/lo operands (uint32 = 2 bf16)
__device__ uint32_t g_wh[(size_t)ODIM * DDIM / 2];
__device__ uint32_t g_wl[(size_t)ODIM * DDIM / 2];
__device__ uint32_t g_uh[(size_t)BSZ * LSEQ * DDIM / 2];
__device__ uint32_t g_ul[(size_t)BSZ * LSEQ * DDIM / 2];
__device__ uint32_t g_oh[(size_t)DDIM * DDIM / 2];
__device__ uint32_t g_ol[(size_t)DDIM * DDIM / 2];
__device__ uint32_t g_vh[(size_t)BSZ * DDIM * LSEQ / 2];
__device__ uint32_t g_vl[(size_t)BSZ * DDIM * LSEQ / 2];

// ---------------------------------------------------------------------------
__device__ __forceinline__ uint32_t smem_u32(const void* p) {
    uint32_t a;
    asm("{ .reg .u64 t; cvta.to.shared.u64 t, %1; cvt.u32.u64 %0, t; }" : "=r"(a) : "l"(p));
    return a;
}

#define LDSM_X4(r0, r1, r2, r3, addr) \
    asm volatile("ldmatrix.sync.aligned.m8n8.x4.shared.b16 {%0,%1,%2,%3}, [%4];" \
                 : "=r"(r0), "=r"(r1), "=r"(r2), "=r"(r3) : "r"(addr))
#define LDSM_X4_T(r0, r1, r2, r3, addr) \
    asm volatile("ldmatrix.sync.aligned.m8n8.x4.trans.shared.b16 {%0,%1,%2,%3}, [%4];" \
                 : "=r"(r0), "=r"(r1), "=r"(r2), "=r"(r3) : "r"(addr))
#define LDSM_X2(r0, r1, addr) \
    asm volatile("ldmatrix.sync.aligned.m8n8.x2.shared.b16 {%0,%1}, [%2];" \
                 : "=r"(r0), "=r"(r1) : "r"(addr))
#define CP_ASYNC16(dst, src) \
    asm volatile("cp.async.cg.shared.global [%0], [%1], 16;" :: "r"(dst), "l"(src))
#define CP_COMMIT() asm volatile("cp.async.commit_group;" ::: "memory")
#define CP_WAIT1()  asm volatile("cp.async.wait_group 1;" ::: "memory")

__device__ __forceinline__ void mma_bf16(float* c, const uint32_t* a, const uint32_t* b) {
    asm volatile(
        "mma.sync.aligned.m16n8k16.row.col.f32.bf16.bf16.f32 "
        "{%0,%1,%2,%3}, {%4,%5,%6,%7}, {%8,%9}, {%0,%1,%2,%3};"
        : "+f"(c[0]), "+f"(c[1]), "+f"(c[2]), "+f"(c[3])
        : "r"(a[0]), "r"(a[1]), "r"(a[2]), "r"(a[3]), "r"(b[0]), "r"(b[1]));
}

__device__ __forceinline__ uint32_t pack_hi(float x, float y) {
    __nv_bfloat16 hx = __float2bfloat16(x);
    __nv_bfloat16 hy = __float2bfloat16(y);
    return (uint32_t)__bfloat16_as_ushort(hx) | ((uint32_t)__bfloat16_as_ushort(hy) << 16);
}
__device__ __forceinline__ uint32_t pack_lo(float x, float y) {
    __nv_bfloat16 hx = __float2bfloat16(x);
    __nv_bfloat16 hy = __float2bfloat16(y);
    __nv_bfloat16 lx = __float2bfloat16(x - __bfloat162float(hx));
    __nv_bfloat16 ly = __float2bfloat16(y - __bfloat162float(hy));
    return (uint32_t)__bfloat16_as_ushort(lx) | ((uint32_t)__bfloat16_as_ushort(ly) << 16);
}

// mixed-radix [2,8,8,8,8] frequency -> slot map (butterfly output digit order)
__device__ __forceinline__ int freq_to_slot(int k) {
    return (k & 1) * 4096 + ((k >> 1) & 7) * 512 + ((k >> 4) & 7) * 64
         + ((k >> 7) & 7) * 8 + ((k >> 10) & 7);
}

// ---------------------------------------------------------------------------
// prep_kernel: sact + 3x cvt_split + twiddles, grid-partitioned.
#define PREP_SACT  1024
#define PREP_WIN   6144
#define PREP_U     16384
#define PREP_WOUT  2048
#define PREP_INIT  32
#define PREP_GRID  (PREP_SACT + PREP_WIN + PREP_U + PREP_WOUT + PREP_INIT)

__global__ __launch_bounds__(256) void prep_kernel(
    const float* __restrict__ w_in, const float* __restrict__ u,
    const float* __restrict__ w_out,
    const float* __restrict__ w1, const float* __restrict__ b1)
{
    const int bid = blockIdx.x;
    const int tid = threadIdx.x;
    if (bid < PREP_SACT) {
        // sact[l][u] = sin(10*(pe(l).w1[u] + b1[u]))
        int idx = bid * 256 + tid;
        int l = idx >> 6;
        int un = idx & 63;
        float t = (float)l * (1.0f / (float)(LSEQ - 1));
        float z = b1[un];
        #pragma unroll
        for (int j = 0; j < 33; j++) z += sinf(t * (float)j * 10.0f) * w1[un * 33 + j];
        g_sact[idx] = sinf(10.0f * z);
    } else if (bid < PREP_SACT + PREP_WIN) {
        int i = (bid - PREP_SACT) * 256 + tid;
        float2 v = ((const float2*)w_in)[i];
        g_wh[i] = pack_hi(v.x, v.y);
        g_wl[i] = pack_lo(v.x, v.y);
    } else if (bid < PREP_SACT + PREP_WIN + PREP_U) {
        int i = (bid - PREP_SACT - PREP_WIN) * 256 + tid;
        float2 v = ((const float2*)u)[i];
        g_uh[i] = pack_hi(v.x, v.y);
        g_ul[i] = pack_lo(v.x, v.y);
    } else if (bid < PREP_SACT + PREP_WIN + PREP_U + PREP_WOUT) {
        int i = (bid - PREP_SACT - PREP_WIN - PREP_U) * 256 + tid;
        float2 v = ((const float2*)w_out)[i];
        g_oh[i] = pack_hi(v.x, v.y);
        g_ol[i] = pack_lo(v.x, v.y);
    } else {
        int i = (bid - PREP_SACT - PREP_WIN - PREP_U - PREP_WOUT) * 256 + tid;
        double ang = -2.0 * 3.141592653589793238462643 * (double)i / (double)NF;
        g_tw[i] = make_float2((float)cos(ang), (float)sin(ang));
    }
}

// ---------------------------------------------------------------------------
// Fused launch: filter_gemm (bid < 512) + gemm_in (bid >= 512).
#define GI_STAGE 32768
#define GI_SMEM  (3 * GI_STAGE)

__device__ void filter_gemm_body(
    char* smem,
    const float* __restrict__ w2, const float* __restrict__ b2,
    const float* __restrict__ fb, const float* __restrict__ fd, int fbid)
{
    float* fsm = (float*)smem;
    float (*As)[128] = (float(*)[128])fsm;
    float (*Bs)[128] = (float(*)[128])(fsm + 64 * 128);
    const int l0 = (fbid & 31) * 128;
    const int o0 = (fbid >> 5) * 128;
    const int tid = threadIdx.x;
    const int tm = tid >> 4;
    const int tn = tid & 15;
    const int lrow = tid >> 1;
    const int lk   = (tid & 1) * 32;

    #pragma unroll
    for (int f = 0; f < 8; f++) {
        float4 a = *(const float4*)&w2[(size_t)(o0 + lrow) * 64 + lk + f * 4];
        As[lk + f * 4 + 0][lrow] = a.x; As[lk + f * 4 + 1][lrow] = a.y;
        As[lk + f * 4 + 2][lrow] = a.z; As[lk + f * 4 + 3][lrow] = a.w;
        float4 s = *(const float4*)&g_sact[(size_t)(l0 + lrow) * 64 + lk + f * 4];
        Bs[lk + f * 4 + 0][lrow] = s.x; Bs[lk + f * 4 + 1][lrow] = s.y;
        Bs[lk + f * 4 + 2][lrow] = s.z; Bs[lk + f * 4 + 3][lrow] = s.w;
    }
    __syncthreads();

    float acc[8][8];
    #pragma unroll
    for (int i = 0; i < 8; i++)
        #pragma unroll
        for (int j = 0; j < 8; j++) acc[i][j] = 0.0f;

    #pragma unroll
    for (int k = 0; k < 64; k++) {
        float4 ra0 = *(const float4*)&As[k][tm * 8];
        float4 ra1 = *(const float4*)&As[k][tm * 8 + 4];
        float4 rb0 = *(const float4*)&Bs[k][tn * 8];
        float4 rb1 = *(const float4*)&Bs[k][tn * 8 + 4];
        float ra[8] = {ra0.x, ra0.y, ra0.z, ra0.w, ra1.x, ra1.y, ra1.z, ra1.w};
        float rb[8] = {rb0.x, rb0.y, rb0.z, rb0.w, rb1.x, rb1.y, rb1.z, rb1.w};
        #pragma unroll
        for (int i = 0; i < 8; i++)
            #pragma unroll
            for (int j = 0; j < 8; j++) acc[i][j] += ra[i] * rb[j];
    }

    #pragma unroll
    for (int i = 0; i < 8; i++) {
        int o = o0 + tm * 8 + i;
        float ed  = expf(fd[o]);
        float bb  = b2[o];
        float fbo = fb[o];
        float v[8];
        #pragma unroll
        for (int j = 0; j < 8; j++) {
            int l = l0 + tn * 8 + j;
            float t = (float)l * (1.0f / (float)(LSEQ - 1));
            v[j] = ((acc[i][j] + bb) * expf(-ed * t) + fbo) * (1.0f / (float)LSEQ);
        }
        *(float4*)&g_h[(size_t)o * LSEQ + l0 + tn * 8]     = make_float4(v[0], v[1], v[2], v[3]);
        *(float4*)&g_h[(size_t)o * LSEQ + l0 + tn * 8 + 4] = make_float4(v[4], v[5], v[6], v[7]);
    }
}

__global__ __launch_bounds__(256, 2) void gemm_in_mma(
    const float* __restrict__ bias,
    const float* __restrict__ w2, const float* __restrict__ b2,
    const float* __restrict__ fb, const float* __restrict__ fd)
{
    extern __shared__ char smem[];
    if (blockIdx.x < 512) {     // filter GEMM CTAs (scheduled first)
        filter_gemm_body(smem, w2, b2, fb, fd, blockIdx.x);
        return;
    }
    const int gb = blockIdx.x - 512;      // 0..1535
    const uint32_t sb = smem_u32(smem);
    const int tid  = threadIdx.x;
    const int lane = tid & 31;
    const int wid  = tid >> 5;
    const int warp_m = wid >> 2;
    const int warp_n = wid & 3;

    const int b   = gb / 768;
    const int rem = gb % 768;
    const int m0  = (rem / 32) * 128;   // od
    const int n0  = (rem % 32) * 128;   // l
    float* C = g_res + (size_t)b * ODIM * LSEQ;

    const int tile = tid >> 6;
    const int tloc = tid & 63;
    const char* gbase;
    if      (tile == 0) gbase = (const char*)g_wh + (size_t)m0 * 2048;
    else if (tile == 1) gbase = (const char*)g_wl + (size_t)m0 * 2048;
    else if (tile == 2) gbase = (const char*)g_uh + (size_t)(b * LSEQ + n0) * 2048;
    else                gbase = (const char*)g_ul + (size_t)(b * LSEQ + n0) * 2048;

    float acc[4][4][4];
    #pragma unroll
    for (int i = 0; i < 4; i++)
        #pragma unroll
        for (int j = 0; j < 4; j++)
            #pragma unroll
            for (int r = 0; r < 4; r++) acc[i][j][r] = 0.0f;

    const int ar  = (lane & 7) + ((lane & 8) ? 8 : 0);
    const int sA  = (ar >> 1) & 3;
    const int a16 = (lane & 16) ? 1 : 0;
    const int br  = lane & 7;
    const int sB  = (br >> 1) & 3;
    const int b16 = (lane & 8) ? 1 : 0;

    #pragma unroll
    for (int p = 0; p < 2; p++) {
        #pragma unroll
        for (int o = 0; o < 8; o++) {
            int idx = tloc + o * 64, row = idx >> 2, c = idx & 3;
            uint32_t dst = sb + p * GI_STAGE + tile * 8192 + row * 64
                         + (((c ^ ((row >> 1) & 3))) << 4);
            CP_ASYNC16(dst, gbase + (size_t)row * 2048 + p * 64 + c * 16);
        }
        CP_COMMIT();
    }

    for (int ch = 0; ch < 32; ch++) {
        CP_WAIT1();
        __syncthreads();
        if (ch + 2 < 32) {
            const int st = (ch + 2) % 3;
            #pragma unroll
            for (int o = 0; o < 8; o++) {
                int idx = tloc + o * 64, row = idx >> 2, c = idx & 3;
                uint32_t dst = sb + st * GI_STAGE + tile * 8192 + row * 64
                             + (((c ^ ((row >> 1) & 3))) << 4);
                CP_ASYNC16(dst, gbase + (size_t)row * 2048 + (ch + 2) * 64 + c * 16);
            }
        }
        CP_COMMIT();

        const uint32_t sbase = sb + (ch % 3) * GI_STAGE;
        #pragma unroll
        for (int k16 = 0; k16 < 2; k16++) {
            uint32_t bh[4][2], bl[4][2];
            #pragma unroll
            for (int j = 0; j < 4; j++) {
                uint32_t rb = sbase + 16384 + (warp_n * 32 + j * 8 + br) * 64
                            + (((k16 * 2 + b16) ^ sB) << 4);
                LDSM_X2(bh[j][0], bh[j][1], rb);
                LDSM_X2(bl[j][0], bl[j][1], rb + 8192);
            }
            // register double-buffered A fragments
            uint32_t ah[2][4], al[2][4];
            {
                uint32_t ra = sbase + (warp_m * 64 + ar) * 64
                            + (((k16 * 2 + a16) ^ sA) << 4);
                LDSM_X4(ah[0][0], ah[0][1], ah[0][2], ah[0][3], ra);
                LDSM_X4(al[0][0], al[0][1], al[0][2], al[0][3], ra + 8192);
            }
            #pragma unroll
            for (int i = 0; i < 4; i++) {
                const int cur = i & 1;
                if (i < 3) {
                    const int nxt = cur ^ 1;
                    uint32_t ra = sbase + (warp_m * 64 + (i + 1) * 16 + ar) * 64
                                + (((k16 * 2 + a16) ^ sA) << 4);
                    LDSM_X4(ah[nxt][0], ah[nxt][1], ah[nxt][2], ah[nxt][3], ra);
                    LDSM_X4(al[nxt][0], al[nxt][1], al[nxt][2], al[nxt][3], ra + 8192);
                }
                #pragma unroll
                for (int j = 0; j < 4; j++) {
                    mma_bf16(acc[i][j], ah[cur], bh[j]);
                    mma_bf16(acc[i][j], ah[cur], bl[j]);
                    mma_bf16(acc[i][j], al[cur], bh[j]);
                }
            }
        }
    }

    const int g = lane >> 2;
    const int t = lane & 3;
    #pragma unroll
    for (int i = 0; i < 4; i++) {
        int od0 = m0 + warp_m * 64 + i * 16 + g;
        float bv0 = bias[od0];
        float bv1 = bias[od0 + 8];
        #pragma unroll
        for (int j = 0; j < 4; j++) {
            int l = n0 + warp_n * 32 + j * 8 + t * 2;
            *(float2*)&C[(size_t)od0 * LSEQ + l] =
                make_float2(acc[i][j][0] + bv0, acc[i][j][1] + bv0);
            *(float2*)&C[(size_t)(od0 + 8) * LSEQ + l] =
                make_float2(acc[i][j][2] + bv1, acc[i][j][3] + bv1);
        }
    }
}

// ---------------------------------------------------------------------------
// gemm_out: out[b,l,e] = sum_d v[b,d,l]*w_out[e,d] + b_out[e]
#define GO_STAGE 32768
#define GO_SMEM  (3 * GO_STAGE)

__global__ __launch_bounds__(256, 2) void gemm_out_mma(const float* __restrict__ bias,
                                                       float* __restrict__ O)
{
    extern __shared__ char smem[];
    const uint32_t sb = smem_u32(smem);
    const int tid  = threadIdx.x;
    const int lane = tid & 31;
    const int wid  = tid >> 5;
    const int warp_m = wid >> 2;
    const int warp_n = wid & 3;

    const int b  = blockIdx.z;
    const int m0 = blockIdx.y * 128;   // l
    const int n0 = blockIdx.x * 128;   // e
    float* C = O + (size_t)b * LSEQ * DDIM;

    const int tile = tid >> 6;
    const int tloc = tid & 63;
    const char* gbase;
    if      (tile == 0) gbase = (const char*)g_vh + (size_t)(b * DDIM) * 8192 + (size_t)m0 * 2;
    else if (tile == 1) gbase = (const char*)g_vl + (size_t)(b * DDIM) * 8192 + (size_t)m0 * 2;
    else if (tile == 2) gbase = (const char*)g_oh + (size_t)n0 * 2048;
    else                gbase = (const char*)g_ol + (size_t)n0 * 2048;

    float acc[4][4][4];
    #pragma unroll
    for (int i = 0; i < 4; i++)
        #pragma unroll
        for (int j = 0; j < 4; j++)
            #pragma unroll
            for (int r = 0; r < 4; r++) acc[i][j][r] = 0.0f;

    const int tr  = (lane & 7) + ((lane & 16) ? 8 : 0);
    const int sT  = lane & 7;
    const int t16 = (lane & 8) ? 1 : 0;
    const int br  = lane & 7;
    const int sB  = (br >> 1) & 3;
    const int b16 = (lane & 8) ? 1 : 0;

    #pragma unroll
    for (int p = 0; p < 2; p++) {
        if (tile < 2) {
            #pragma unroll
            for (int o = 0; o < 8; o++) {
                int idx = tloc + o * 64, row = idx >> 4, c16 = idx & 15;
                uint32_t dst = sb + p * GO_STAGE + tile * 8192 + row * 256
                             + (((c16 ^ (row & 7))) << 4);
                CP_ASYNC16(dst, gbase + (size_t)(p * 32 + row) * 8192 + c16 * 16);
            }
        } else {
            #pragma unroll
            for (int o = 0; o < 8; o++) {
                int idx = tloc + o * 64, row = idx >> 2, c = idx & 3;
                uint32_t dst = sb + p * GO_STAGE + (tile - 2) * 8192 + 16384 + row * 64
                             + (((c ^ ((row >> 1) & 3))) << 4);
                CP_ASYNC16(dst, gbase + (size_t)row * 2048 + p * 64 + c * 16);
            }
        }
        CP_COMMIT();
    }

    for (int ch = 0; ch < 32; ch++) {
        CP_WAIT1();
        __syncthreads();
        if (ch + 2 < 32) {
            const int st = (ch + 2) % 3;
            if (tile < 2) {
                #pragma unroll
                for (int o = 0; o < 8; o++) {
                    int idx = tloc + o * 64, row = idx >> 4, c16 = idx & 15;
                    uint32_t dst = sb + st * GO_STAGE + tile * 8192 + row * 256
                                 + (((c16 ^ (row & 7))) << 4);
                    CP_ASYNC16(dst, gbase + (size_t)((ch + 2) * 32 + row) * 8192 + c16 * 16);
                }
            } else {
                #pragma unroll
                for (int o = 0; o < 8; o++) {
                    int idx = tloc + o * 64, row = idx >> 2, c = idx & 3;
                    uint32_t dst = sb + st * GO_STAGE + (tile - 2) * 8192 + 16384 + row * 64
                                 + (((c ^ ((row >> 1) & 3))) << 4);
                    CP_ASYNC16(dst, gbase + (size_t)row * 2048 + (ch + 2) * 64 + c * 16);
                }
            }
        }
        CP_COMMIT();

        const uint32_t sbase = sb + (ch % 3) * GO_STAGE;
        #pragma unroll
        for (int k16 = 0; k16 < 2; k16++) {
            uint32_t bh[4][2], bl[4][2];
            #pragma unroll
            for (int j = 0; j < 4; j++) {
                uint32_t rb = sbase + 16384 + (warp_n * 32 + j * 8 + br) * 64
                            + (((k16 * 2 + b16) ^ sB) << 4);
                LDSM_X2(bh[j][0], bh[j][1], rb);
                LDSM_X2(bl[j][0], bl[j][1], rb + 8192);
            }
            uint32_t ah[2][4], al[2][4];
            {
                int rowd = k16 * 16 + tr;
                uint32_t ra = sbase + rowd * 256 + (((warp_m * 8 + t16) ^ sT) << 4);
                LDSM_X4_T(ah[0][0], ah[0][1], ah[0][2], ah[0][3], ra);
                LDSM_X4_T(al[0][0], al[0][1], al[0][2], al[0][3], ra + 8192);
            }
            #pragma unroll
            for (int i = 0; i < 4; i++) {
                const int cur = i & 1;
                if (i < 3) {
                    const int nxt = cur ^ 1;
                    int rowd = k16 * 16 + tr;
                    uint32_t ra = sbase + rowd * 256
                                + (((warp_m * 8 + (i + 1) * 2 + t16) ^ sT) << 4);
                    LDSM_X4_T(ah[nxt][0], ah[nxt][1], ah[nxt][2], ah[nxt][3], ra);
                    LDSM_X4_T(al[nxt][0], al[nxt][1], al[nxt][2], al[nxt][3], ra + 8192);
                }
                #pragma unroll
                for (int j = 0; j < 4; j++) {
                    mma_bf16(acc[i][j], ah[cur], bh[j]);
                    mma_bf16(acc[i][j], ah[cur], bl[j]);
                    mma_bf16(acc[i][j], al[cur], bh[j]);
                }
            }
        }
    }

    const int g = lane >> 2;
    const int t = lane & 3;
    #pragma unroll
    for (int j = 0; j < 4; j++) {
        int e = n0 + warp_n * 32 + j * 8 + t * 2;
        float bb0 = bias[e];
        float bb1 = bias[e + 1];
        #pragma unroll
        for (int i = 0; i < 4; i++) {
            int l = m0 + warp_m * 64 + i * 16 + g;
            *(float2*)&C[(size_t)l * DDIM + e] =
                make_float2(acc[i][j][0] + bb0, acc[i][j][1] + bb1);
            *(float2*)&C[(size_t)(l + 8) * DDIM + e] =
                make_float2(acc[i][j][2] + bb0, acc[i][j][3] + bb1);
        }
    }
}

// ---------------------------------------------------------------------------
// FFT: 8192-pt, 512 threads, split re/im padded smem, mixed radix [2,8,8,8,8].
#define FFT_C 0.70710678118654752f

__device__ __forceinline__ void fft_fwd_zp(float* __restrict__ SR, float* __restrict__ SI) {
    #pragma unroll
    for (int jj = 0; jj < 8; jj++) {
        int j  = threadIdx.x + jj * FFT_THREADS;
        int i0 = PADI(j), i1 = PADI(j + 4096);
        float ar = SR[i0], ai = SI[i0];
        float2 w = g_tw[j];
        SR[i1] = ar * w.x - ai * w.y;
        SI[i1] = ar * w.y + ai * w.x;
    }
    __syncthreads();
    #pragma unroll
    for (int s = 0; s < 4; s++) {
        const int lm  = 9 - 3 * s;
        const int m   = 1 << lm;
        const int str = 1024 >> lm;
        #pragma unroll
        for (int jj = 0; jj < 2; jj++) {
            int t = threadIdx.x + jj * FFT_THREADS;
            int q = t & (m - 1);
            int base = ((t >> lm) << (lm + 3)) | q;
            int p0 = PADI(base), p1 = PADI(base + m), p2 = PADI(base + 2 * m),
                p3 = PADI(base + 3 * m), p4 = PADI(base + 4 * m), p5 = PADI(base + 5 * m),
                p6 = PADI(base + 6 * m), p7 = PADI(base + 7 * m);
            float x0r = SR[p0], x0i = SI[p0];
            float x1r = SR[p1], x1i = SI[p1];
            float x2r = SR[p2], x2i = SI[p2];
            float x3r = SR[p3], x3i = SI[p3];
            float x4r = SR[p4], x4i = SI[p4];
            float x5r = SR[p5], x5i = SI[p5];
            float x6r = SR[p6], x6i = SI[p6];
            float x7r = SR[p7], x7i = SI[p7];
            float a0r = x0r + x4r, a0i = x0i + x4i;
            float a1r = x1r + x5r, a1i = x1i + x5i;
            float a2r = x2r + x6r, a2i = x2i + x6i;
            float a3r = x3r + x7r, a3i = x3i + x7i;
            float b0r = x0r - x4r, b0i = x0i - x4i;
            float b1r = x1r - x5r, b1i = x1i - x5i;
            float b2r = x2r - x6r, b2i = x2i - x6i;
            float b3r = x3r - x7r, b3i = x3i - x7i;
            float u1r =  FFT_C * (b1r + b1i), u1i = FFT_C * (b1i - b1r);
            float u2r =  b2i,                 u2i = -b2r;
            float u3r = -FFT_C * (b3r - b3i), u3i = -FFT_C * (b3r + b3i);
            float t0r = a0r + a2r, t0i = a0i + a2i;
            float t1r = a1r + a3r, t1i = a1i + a3i;
            float t2r = a0r - a2r, t2i = a0i - a2i;
            float t3r = a1i - a3i, t3i = a3r - a1r;
            float X0r = t0r + t1r, X0i = t0i + t1i;
            float X2r = t2r + t3r, X2i = t2i + t3i;
            float X4r = t0r - t1r, X4i = t0i - t1i;
            float X6r = t2r - t3r, X6i = t2i - t3i;
            float s0r = b0r + u2r, s0i = b0i + u2i;
            float s1r = u1r + u3r, s1i = u1i + u3i;
            float s2r = b0r - u2r, s2i = b0i - u2i;
            float s3r = u1i - u3i, s3i = u3r - u1r;
            float X1r = s0r + s1r, X1i = s0i + s1i;
            float X3r = s2r + s3r, X3i = s2i + s3i;
            float X5r = s0r - s1r, X5i = s0i - s1i;
            float X7r = s2r - s3r, X7i = s2i - s3i;
            SR[p0] = X0r; SI[p0] = X0i;
            if (lm > 0) {
                int tb = q * str;
                float2 w1 = g_tw[tb],     w2 = g_tw[2 * tb], w3 = g_tw[3 * tb];
                float2 w4 = g_tw[4 * tb], w5 = g_tw[5 * tb], w6 = g_tw[6 * tb];
                float2 w7 = g_tw[7 * tb];
                SR[p1] = X1r * w1.x - X1i * w1.y; SI[p1] = X1r * w1.y + X1i * w1.x;
                SR[p2] = X2r * w2.x - X2i * w2.y; SI[p2] = X2r * w2.y + X2i * w2.x;
                SR[p3] = X3r * w3.x - X3i * w3.y; SI[p3] = X3r * w3.y + X3i * w3.x;
                SR[p4] = X4r * w4.x - X4i * w4.y; SI[p4] = X4r * w4.y + X4i * w4.x;
                SR[p5] = X5r * w5.x - X5i * w5.y; SI[p5] = X5r * w5.y + X5i * w5.x;
                SR[p6] = X6r * w6.x - X6i * w6.y; SI[p6] = X6r * w6.y + X6i * w6.x;
                SR[p7] = X7r * w7.x - X7i * w7.y; SI[p7] = X7r * w7.y + X7i * w7.x;
            } else {
                SR[p1] = X1r; SI[p1] = X1i;
                SR[p2] = X2r; SI[p2] = X2i;
                SR[p3] = X3r; SI[p3] = X3i;
                SR[p4] = X4r; SI[p4] = X4i;
                SR[p5] = X5r; SI[p5] = X5i;
                SR[p6] = X6r; SI[p6] = X6i;
                SR[p7] = X7r; SI[p7] = X7i;
            }
        }
        __syncthreads();
    }
}

__device__ __forceinline__ void fft_inv_half(float* __restrict__ SR, float* __restrict__ SI) {
    #pragma unroll
    for (int s = 0; s < 4; s++) {
        const int lm  = 3 * s;
        const int m   = 1 << lm;
        const int str = 1024 >> lm;
        #pragma unroll
        for (int jj = 0; jj < 2; jj++) {
            int t = threadIdx.x + jj * FFT_THREADS;
            int q = t & (m - 1);
            int base = ((t >> lm) << (lm + 3)) | q;
            int p0 = PADI(base), p1 = PADI(base + m), p2 = PADI(base + 2 * m),
                p3 = PADI(base + 3 * m), p4 = PADI(base + 4 * m), p5 = PADI(base + 5 * m),
                p6 = PADI(base + 6 * m), p7 = PADI(base + 7 * m);
            float y0r = SR[p0], y0i = SI[p0];
            float y1r = SR[p1], y1i = SI[p1];
            float y2r = SR[p2], y2i = SI[p2];
            float y3r = SR[p3], y3i = SI[p3];
            float y4r = SR[p4], y4i = SI[p4];
            float y5r = SR[p5], y5i = SI[p5];
            float y6r = SR[p6], y6i = SI[p6];
            float y7r = SR[p7], y7i = SI[p7];
            if (lm > 0) {
                int tb = q * str;
                float2 w1 = g_tw[tb],     w2 = g_tw[2 * tb], w3 = g_tw[3 * tb];
                float2 w4 = g_tw[4 * tb], w5 = g_tw[5 * tb], w6 = g_tw[6 * tb];
                float2 w7 = g_tw[7 * tb];
                float cr;
                cr = y1r * w1.x + y1i * w1.y; y1i = y1i * w1.x - y1r * w1.y; y1r = cr;
                cr = y2r * w2.x + y2i * w2.y; y2i = y2i * w2.x - y2r * w2.y; y2r = cr;
                cr = y3r * w3.x + y3i * w3.y; y3i = y3i * w3.x - y3r * w3.y; y3r = cr;
                cr = y4r * w4.x + y4i * w4.y; y4i = y4i * w4.x - y4r * w4.y; y4r = cr;
                cr = y5r * w5.x + y5i * w5.y; y5i = y5i * w5.x - y5r * w5.y; y5r = cr;
                cr = y6r * w6.x + y6i * w6.y; y6i = y6i * w6.x - y6r * w6.y; y6r = cr;
                cr = y7r * w7.x + y7i * w7.y; y7i = y7i * w7.x - y7r * w7.y; y7r = cr;
            }
            float t0r = y0r + y4r, t0i = y0i + y4i;
            float t1r = y2r + y6r, t1i = y2i + y6i;
            float t2r = y0r - y4r, t2i = y0i - y4i;
            float t3r = y6i - y2i, t3i = y2r - y6r;
            float a0r = t0r + t1r, a0i = t0i + t1i;
            float a1r = t2r + t3r, a1i = t2i + t3i;
            float a2r = t0r - t1r, a2i = t0i - t1i;
            float a3r = t2r - t3r, a3i = t2i - t3i;
            float s0r = y1r + y5r, s0i = y1i + y5i;
            float s1r = y3r + y7r, s1i = y3i + y7i;
            float s2r = y1r - y5r, s2i = y1i - y5i;
            float s3r = y7i - y3i, s3i = y3r - y7r;
            float d0r = s0r + s1r, d0i = s0i + s1i;
            float d1r = s2r + s3r, d1i = s2i + s3i;
            float d2r = s0r - s1r, d2i = s0i - s1i;
            float d3r = s2r - s3r, d3i = s2i - s3i;
            float e1r =  FFT_C * (d1r - d1i), e1i = FFT_C * (d1r + d1i);
            float e2r = -d2i,                 e2i = d2r;
            float e3r = -FFT_C * (d3r + d3i), e3i = FFT_C * (d3r - d3i);
            SR[p0] = a0r + d0r; SI[p0] = a0i + d0i;
            SR[p4] = a0r - d0r; SI[p4] = a0i - d0i;
            SR[p1] = a1r + e1r; SI[p1] = a1i + e1i;
            SR[p5] = a1r - e1r; SI[p5] = a1i - e1i;
            SR[p2] = a2r + e2r; SI[p2] = a2i + e2i;
            SR[p6] = a2r - e2r; SI[p6] = a2i - e2i;
            SR[p3] = a3r + e3r; SI[p3] = a3i + e3i;
            SR[p7] = a3r - e3r; SI[p7] = a3i - e3i;
        }
        __syncthreads();
    }
    #pragma unroll
    for (int jj = 0; jj < 8; jj++) {
        int j  = threadIdx.x + jj * FFT_THREADS;
        int i0 = PADI(j), i1 = PADI(j + 4096);
        float2 w = g_tw[j];
        float br = SR[i1], bi = SI[i1];
        float tr = br * w.x + bi * w.y;
        float ti = bi * w.x - br * w.y;
        SR[i0] += tr; SI[i0] += ti;
    }
    __syncthreads();
}

// ---------------------------------------------------------------------------
__global__ __launch_bounds__(FFT_THREADS) void hfft_kernel() {
    extern __shared__ float sm[];
    float* SR = sm;
    float* SI = sm + SM_HALF;
    const int c = blockIdx.x;
    const int n = c >> 9;
    const int dpair = c & (NPAIR - 1);
    const float* h0 = g_h + ((size_t)n * DDIM + 2 * dpair)     * LSEQ;
    const float* h1 = g_h + ((size_t)n * DDIM + 2 * dpair + 1) * LSEQ;

    for (int i = threadIdx.x; i < LSEQ; i += FFT_THREADS) {
        SR[PADI(i)] = h0[i]; SI[PADI(i)] = h1[i];
    }
    __syncthreads();
    fft_fwd_zp(SR, SI);

    float2* Ao = g_A + (size_t)c * NK;
    float2* Bo = g_B + (size_t)c * NK;
    for (int k = threadIdx.x; k <= LSEQ; k += FFT_THREADS) {
        int p = freq_to_slot(k);
        int q = freq_to_slot((NF - k) & (NF - 1));
        float zpr = SR[PADI(p)], zpi = SI[PADI(p)];
        float zqr = SR[PADI(q)], zqi = SI[PADI(q)];
        float g0r = 0.5f * (zpr + zqr), g0i = 0.5f * (zpi - zqi);
        float g1r = 0.5f * (zpi + zqi), g1i = 0.5f * (zqr - zpr);
        Ao[k] = make_float2(0.5f * (g0r + g1r), 0.5f * (g0i + g1i));
        Bo[k] = make_float2(0.5f * (g0r - g1r), 0.5f * (g0i - g1i));
    }
}

// ---------------------------------------------------------------------------
__device__ __forceinline__ float conv3_at(const float* __restrict__ r, int l,
                                          float w0, float w1, float w2, float cb) {
    float left  = (l > 0)        ? r[l - 1] : 0.0f;
    float right = (l < LSEQ - 1) ? r[l + 1] : 0.0f;
    return w0 * left + w1 * r[l] + w2 * right + cb;
}

__global__ __launch_bounds__(FFT_THREADS) void fftconv_kernel(
    const float* __restrict__ cw, const float* __restrict__ cbv)
{
    extern __shared__ float sm[];
    float* SR = sm;
    float* SI = sm + SM_HALF;
    const int c = blockIdx.x;
    const int b = c >> 9;
    const int dpair = c & (NPAIR - 1);
    const int ch0 = 2 * dpair, ch1 = ch0 + 1;
    const float inv = 1.0f / (float)NF;

    {
        const float* r2a = g_res + ((size_t)(b * 3 + 2) * DDIM + ch0) * LSEQ;
        const float* r2b = g_res + ((size_t)(b * 3 + 2) * DDIM + ch1) * LSEQ;
        const int oa = 2 * DDIM + ch0, ob = 2 * DDIM + ch1;
        float w0a = cw[oa * 3], w1a = cw[oa * 3 + 1], w2a = cw[oa * 3 + 2], cba = cbv[oa];
        float w0b = cw[ob * 3], w1b = cw[ob * 3 + 1], w2b = cw[ob * 3 + 2], cbb = cbv[ob];
        for (int i = threadIdx.x; i < LSEQ; i += FFT_THREADS) {
            SR[PADI(i)] = conv3_at(r2a, i, w0a, w1a, w2a, cba);
            SI[PADI(i)] = conv3_at(r2b, i, w0b, w1b, w2b, cbb);
        }
    }
    __syncthreads();

    #pragma unroll 1
    for (int n = 0; n < 2; n++) {
        fft_fwd_zp(SR, SI);

        const float2* Ap = g_A + ((size_t)n * NPAIR + dpair) * NK;
        const float2* Bp = g_B + ((size_t)n * NPAIR + dpair) * NK;
        for (int k = threadIdx.x; k <= LSEQ; k += FFT_THREADS) {
            int p = freq_to_slot(k);
            int q = freq_to_slot((NF - k) & (NF - 1));
            int ip = PADI(p), iq = PADI(q);
            float zr = SR[ip], zi = SI[ip];
            float wr = SR[iq], wi = SI[iq];
            float2 a  = Ap[k];
            float2 bb = Bp[k];
            float ypr = a.x * zr - a.y * zi + bb.x * wr + bb.y * wi;
            float ypi = a.x * zi + a.y * zr + bb.y * wr - bb.x * wi;
            SR[ip] = ypr; SI[ip] = ypi;
            if (q != p) {
                float yqr = a.x * wr + a.y * wi + bb.x * zr - bb.y * zi;
                float yqi = a.x * wi - a.y * wr - bb.x * zi - bb.y * zr;
                SR[iq] = yqr; SI[iq] = yqi;
            }
        }
        __syncthreads();

        fft_inv_half(SR, SI);

        const float* rna = g_res + ((size_t)(b * 3 + n) * DDIM + ch0) * LSEQ;
        const float* rnb = g_res + ((size_t)(b * 3 + n) * DDIM + ch1) * LSEQ;
        const int oa = n * DDIM + ch0, ob = n * DDIM + ch1;
        float w0a = cw[oa * 3], w1a = cw[oa * 3 + 1], w2a = cw[oa * 3 + 2], cba = cbv[oa];
        float w0b = cw[ob * 3], w1b = cw[ob * 3 + 1], w2b = cw[ob * 3 + 2], cbb = cbv[ob];

        if (n == 0) {
            for (int l = threadIdx.x; l < LSEQ; l += FFT_THREADS) {
                int ip = PADI(l);
                SR[ip] = SR[ip] * inv * conv3_at(rna, l, w0a, w1a, w2a, cba);
                SI[ip] = SI[ip] * inv * conv3_at(rnb, l, w0b, w1b, w2b, cbb);
            }
            __syncthreads();
        } else {
            uint32_t* vh0 = g_vh + ((size_t)(b * DDIM + ch0)) * (LSEQ / 2);
            uint32_t* vl0 = g_vl + ((size_t)(b * DDIM + ch0)) * (LSEQ / 2);
            uint32_t* vh1 = g_vh + ((size_t)(b * DDIM + ch1)) * (LSEQ / 2);
            uint32_t* vl1 = g_vl + ((size_t)(b * DDIM + ch1)) * (LSEQ / 2);
            for (int l2 = threadIdx.x; l2 < LSEQ / 2; l2 += FFT_THREADS) {
                int l = 2 * l2;
                float y0a = SR[PADI(l)]     * inv * conv3_at(rna, l,     w0a, w1a, w2a, cba);
                float y0b = SR[PADI(l + 1)] * inv * conv3_at(rna, l + 1, w0a, w1a, w2a, cba);
                float y1a = SI[PADI(l)]     * inv * conv3_at(rnb, l,     w0b, w1b, w2b, cbb);
                float y1b = SI[PADI(l + 1)] * inv * conv3_at(rnb, l + 1, w0b, w1b, w2b, cbb);
                vh0[l2] = pack_hi(y0a, y0b); vl0[l2] = pack_lo(y0a, y0b);
                vh1[l2] = pack_hi(y1a, y1b); vl1[l2] = pack_lo(y1a, y1b);
            }
        }
    }
}

// ---------------------------------------------------------------------------
extern "C" void kernel_launch(void* const* d_in, const int* in_sizes, int n_in,
                              void* d_out, int out_size)
{
    const float* u          = (const float*)d_in[0];
    const float* w_in       = (const float*)d_in[1];
    const float* b_in       = (const float*)d_in[2];
    const float* conv_w     = (const float*)d_in[3];
    const float* conv_b     = (const float*)d_in[4];
    const float* w1         = (const float*)d_in[5];
    const float* b1         = (const float*)d_in[6];
    const float* w2         = (const float*)d_in[7];
    const float* b2         = (const float*)d_in[8];
    const float* filt_bias  = (const float*)d_in[9];
    const float* filt_decay = (const float*)d_in[10];
    const float* w_out      = (const float*)d_in[11];
    const float* b_out      = (const float*)d_in[12];
    float* out = (float*)d_out;

    static bool attr_set = false;
    if (!attr_set) {
        cudaFuncSetAttribute(hfft_kernel,    cudaFuncAttributeMaxDynamicSharedMemorySize, FFT_SMEM);
        cudaFuncSetAttribute(fftconv_kernel, cudaFuncAttributeMaxDynamicSharedMemorySize, FFT_SMEM);
        cudaFuncSetAttribute(gemm_in_mma,    cudaFuncAttributeMaxDynamicSharedMemorySize, GI_SMEM);
        cudaFuncSetAttribute(gemm_out_mma,   cudaFuncAttributeMaxDynamicSharedMemorySize, GO_SMEM);
        attr_set = true;
    }

    // 1: prep — all operand conversions + twiddles + sact (grid-partitioned)
    prep_kernel<<<PREP_GRID, 256>>>(w_in, u, w_out, w1, b1);
    // 2: filter_gemm (first 512 CTAs) fused with gemm_in (next 1536 CTAs)
    gemm_in_mma<<<512 + 1536, 256, GI_SMEM>>>(b_in, w2, b2, filt_bias, filt_decay);
    // 3: H spectra
    hfft_kernel<<<2 * NPAIR, FFT_THREADS, FFT_SMEM>>>();
    // 4: fftconv (profiled slot)
    fftconv_kernel<<<BSZ * NPAIR, FFT_THREADS, FFT_SMEM>>>(conv_w, conv_b);
    // 5: output GEMM
    gemm_out_mma<<<dim3(DDIM / 128, LSEQ / 128, BSZ), 256, GO_SMEM>>>(b_out, out);
}

// round 13
// speedup vs baseline: 1.3373x; 1.0937x over previous
#include <cuda_runtime.h>
#include <cuda_bf16.h>
#include <cstdint>
#include <cstddef>

// ---------------------------------------------------------------------------
// Hyena operator: B=2, L=4096, D=1024, ORDER=2, OD=3072
// Round 13: 256-thread FFTs with 3-CTA/SM occupancy (reg-capped), hfft fused
// into the gemm_in launch, filter_gemm standalone. 5 launches.
// ---------------------------------------------------------------------------

#define LSEQ 4096
#define NF   8192
#define DDIM 1024
#define ODIM 3072
#define BSZ  2
#define NPAIR 512
#define NK    4100
#define FFT_THREADS 256
#define FFT_ZP_IT (4096 / FFT_THREADS)
#define FFT_R8_IT (1024 / FFT_THREADS)
#define PADI(i) ((i) + ((i) >> 5))
#define SM_HALF 8448
#define FFT_SMEM (2 * SM_HALF * 4)

// Scratch (device .bss — allocation-free)
__device__ float  g_res[(size_t)BSZ * ODIM * LSEQ];
__device__ float  g_h  [(size_t)2   * DDIM * LSEQ];
__device__ float  g_sact[(size_t)LSEQ * 64];
__device__ float2 g_A  [(size_t)2 * NPAIR * NK];
__device__ float2 g_B  [(size_t)2 * NPAIR * NK];
__device__ float2 g_tw [NF];
// packed bf16 hi/lo operands (uint32 = 2 bf16)
__device__ uint32_t g_wh[(size_t)ODIM * DDIM / 2];
__device__ uint32_t g_wl[(size_t)ODIM * DDIM / 2];
__device__ uint32_t g_uh[(size_t)BSZ * LSEQ * DDIM / 2];
__device__ uint32_t g_ul[(size_t)BSZ * LSEQ * DDIM / 2];
__device__ uint32_t g_oh[(size_t)DDIM * DDIM / 2];
__device__ uint32_t g_ol[(size_t)DDIM * DDIM / 2];
__device__ uint32_t g_vh[(size_t)BSZ * DDIM * LSEQ / 2];
__device__ uint32_t g_vl[(size_t)BSZ * DDIM * LSEQ / 2];

// ---------------------------------------------------------------------------
__device__ __forceinline__ uint32_t smem_u32(const void* p) {
    uint32_t a;
    asm("{ .reg .u64 t; cvta.to.shared.u64 t, %1; cvt.u32.u64 %0, t; }" : "=r"(a) : "l"(p));
    return a;
}

#define LDSM_X4(r0, r1, r2, r3, addr) \
    asm volatile("ldmatrix.sync.aligned.m8n8.x4.shared.b16 {%0,%1,%2,%3}, [%4];" \
                 : "=r"(r0), "=r"(r1), "=r"(r2), "=r"(r3) : "r"(addr))
#define LDSM_X4_T(r0, r1, r2, r3, addr) \
    asm volatile("ldmatrix.sync.aligned.m8n8.x4.trans.shared.b16 {%0,%1,%2,%3}, [%4];" \
                 : "=r"(r0), "=r"(r1), "=r"(r2), "=r"(r3) : "r"(addr))
#define LDSM_X2(r0, r1, addr) \
    asm volatile("ldmatrix.sync.aligned.m8n8.x2.shared.b16 {%0,%1}, [%2];" \
                 : "=r"(r0), "=r"(r1) : "r"(addr))
#define CP_ASYNC16(dst, src) \
    asm volatile("cp.async.cg.shared.global [%0], [%1], 16;" :: "r"(dst), "l"(src))
#define CP_COMMIT() asm volatile("cp.async.commit_group;" ::: "memory")
#define CP_WAIT1()  asm volatile("cp.async.wait_group 1;" ::: "memory")

__device__ __forceinline__ void mma_bf16(float* c, const uint32_t* a, const uint32_t* b) {
    asm volatile(
        "mma.sync.aligned.m16n8k16.row.col.f32.bf16.bf16.f32 "
        "{%0,%1,%2,%3}, {%4,%5,%6,%7}, {%8,%9}, {%0,%1,%2,%3};"
        : "+f"(c[0]), "+f"(c[1]), "+f"(c[2]), "+f"(c[3])
        : "r"(a[0]), "r"(a[1]), "r"(a[2]), "r"(a[3]), "r"(b[0]), "r"(b[1]));
}

__device__ __forceinline__ uint32_t pack_hi(float x, float y) {
    __nv_bfloat16 hx = __float2bfloat16(x);
    __nv_bfloat16 hy = __float2bfloat16(y);
    return (uint32_t)__bfloat16_as_ushort(hx) | ((uint32_t)__bfloat16_as_ushort(hy) << 16);
}
__device__ __forceinline__ uint32_t pack_lo(float x, float y) {
    __nv_bfloat16 hx = __float2bfloat16(x);
    __nv_bfloat16 hy = __float2bfloat16(y);
    __nv_bfloat16 lx = __float2bfloat16(x - __bfloat162float(hx));
    __nv_bfloat16 ly = __float2bfloat16(y - __bfloat162float(hy));
    return (uint32_t)__bfloat16_as_ushort(lx) | ((uint32_t)__bfloat16_as_ushort(ly) << 16);
}

// mixed-radix [2,8,8,8,8] frequency -> slot map
__device__ __forceinline__ int freq_to_slot(int k) {
    return (k & 1) * 4096 + ((k >> 1) & 7) * 512 + ((k >> 4) & 7) * 64
         + ((k >> 7) & 7) * 8 + ((k >> 10) & 7);
}

// ---------------------------------------------------------------------------
// prep_kernel: sact + 3x cvt_split + twiddles, grid-partitioned.
#define PREP_SACT  1024
#define PREP_WIN   6144
#define PREP_U     16384
#define PREP_WOUT  2048
#define PREP_INIT  32
#define PREP_GRID  (PREP_SACT + PREP_WIN + PREP_U + PREP_WOUT + PREP_INIT)

__global__ __launch_bounds__(256) void prep_kernel(
    const float* __restrict__ w_in, const float* __restrict__ u,
    const float* __restrict__ w_out,
    const float* __restrict__ w1, const float* __restrict__ b1)
{
    const int bid = blockIdx.x;
    const int tid = threadIdx.x;
    if (bid < PREP_SACT) {
        int idx = bid * 256 + tid;
        int l = idx >> 6;
        int un = idx & 63;
        float t = (float)l * (1.0f / (float)(LSEQ - 1));
        float z = b1[un];
        #pragma unroll
        for (int j = 0; j < 33; j++) z += sinf(t * (float)j * 10.0f) * w1[un * 33 + j];
        g_sact[idx] = sinf(10.0f * z);
    } else if (bid < PREP_SACT + PREP_WIN) {
        int i = (bid - PREP_SACT) * 256 + tid;
        float2 v = ((const float2*)w_in)[i];
        g_wh[i] = pack_hi(v.x, v.y);
        g_wl[i] = pack_lo(v.x, v.y);
    } else if (bid < PREP_SACT + PREP_WIN + PREP_U) {
        int i = (bid - PREP_SACT - PREP_WIN) * 256 + tid;
        float2 v = ((const float2*)u)[i];
        g_uh[i] = pack_hi(v.x, v.y);
        g_ul[i] = pack_lo(v.x, v.y);
    } else if (bid < PREP_SACT + PREP_WIN + PREP_U + PREP_WOUT) {
        int i = (bid - PREP_SACT - PREP_WIN - PREP_U) * 256 + tid;
        float2 v = ((const float2*)w_out)[i];
        g_oh[i] = pack_hi(v.x, v.y);
        g_ol[i] = pack_lo(v.x, v.y);
    } else {
        int i = (bid - PREP_SACT - PREP_WIN - PREP_U - PREP_WOUT) * 256 + tid;
        double ang = -2.0 * 3.141592653589793238462643 * (double)i / (double)NF;
        g_tw[i] = make_float2((float)cos(ang), (float)sin(ang));
    }
}

// ---------------------------------------------------------------------------
// filter_gemm: g_h[o][l] (standalone launch)
__global__ __launch_bounds__(256) void filter_gemm(
    const float* __restrict__ w2, const float* __restrict__ b2,
    const float* __restrict__ fb, const float* __restrict__ fd)
{
    extern __shared__ float fsm[];
    float (*As)[128] = (float(*)[128])fsm;
    float (*Bs)[128] = (float(*)[128])(fsm + 64 * 128);
    const int l0 = (blockIdx.x & 31) * 128;
    const int o0 = (blockIdx.x >> 5) * 128;
    const int tid = threadIdx.x;
    const int tm = tid >> 4;
    const int tn = tid & 15;
    const int lrow = tid >> 1;
    const int lk   = (tid & 1) * 32;

    #pragma unroll
    for (int f = 0; f < 8; f++) {
        float4 a = *(const float4*)&w2[(size_t)(o0 + lrow) * 64 + lk + f * 4];
        As[lk + f * 4 + 0][lrow] = a.x; As[lk + f * 4 + 1][lrow] = a.y;
        As[lk + f * 4 + 2][lrow] = a.z; As[lk + f * 4 + 3][lrow] = a.w;
        float4 s = *(const float4*)&g_sact[(size_t)(l0 + lrow) * 64 + lk + f * 4];
        Bs[lk + f * 4 + 0][lrow] = s.x; Bs[lk + f * 4 + 1][lrow] = s.y;
        Bs[lk + f * 4 + 2][lrow] = s.z; Bs[lk + f * 4 + 3][lrow] = s.w;
    }
    __syncthreads();

    float acc[8][8];
    #pragma unroll
    for (int i = 0; i < 8; i++)
        #pragma unroll
        for (int j = 0; j < 8; j++) acc[i][j] = 0.0f;

    #pragma unroll
    for (int k = 0; k < 64; k++) {
        float4 ra0 = *(const float4*)&As[k][tm * 8];
        float4 ra1 = *(const float4*)&As[k][tm * 8 + 4];
        float4 rb0 = *(const float4*)&Bs[k][tn * 8];
        float4 rb1 = *(const float4*)&Bs[k][tn * 8 + 4];
        float ra[8] = {ra0.x, ra0.y, ra0.z, ra0.w, ra1.x, ra1.y, ra1.z, ra1.w};
        float rb[8] = {rb0.x, rb0.y, rb0.z, rb0.w, rb1.x, rb1.y, rb1.z, rb1.w};
        #pragma unroll
        for (int i = 0; i < 8; i++)
            #pragma unroll
            for (int j = 0; j < 8; j++) acc[i][j] += ra[i] * rb[j];
    }

    #pragma unroll
    for (int i = 0; i < 8; i++) {
        int o = o0 + tm * 8 + i;
        float ed  = expf(fd[o]);
        float bb  = b2[o];
        float fbo = fb[o];
        float v[8];
        #pragma unroll
        for (int j = 0; j < 8; j++) {
            int l = l0 + tn * 8 + j;
            float t = (float)l * (1.0f / (float)(LSEQ - 1));
            v[j] = ((acc[i][j] + bb) * expf(-ed * t) + fbo) * (1.0f / (float)LSEQ);
        }
        *(float4*)&g_h[(size_t)o * LSEQ + l0 + tn * 8]     = make_float4(v[0], v[1], v[2], v[3]);
        *(float4*)&g_h[(size_t)o * LSEQ + l0 + tn * 8 + 4] = make_float4(v[4], v[5], v[6], v[7]);
    }
}

// ---------------------------------------------------------------------------
// FFT: 8192-pt, FFT_THREADS threads, split re/im padded smem, radix [2,8,8,8,8].
#define FFT_C 0.70710678118654752f

__device__ __forceinline__ void fft_fwd_zp(float* __restrict__ SR, float* __restrict__ SI) {
    #pragma unroll
    for (int jj = 0; jj < FFT_ZP_IT; jj++) {
        int j  = threadIdx.x + jj * FFT_THREADS;
        int i0 = PADI(j), i1 = PADI(j + 4096);
        float ar = SR[i0], ai = SI[i0];
        float2 w = g_tw[j];
        SR[i1] = ar * w.x - ai * w.y;
        SI[i1] = ar * w.y + ai * w.x;
    }
    __syncthreads();
    #pragma unroll
    for (int s = 0; s < 4; s++) {
        const int lm  = 9 - 3 * s;
        const int m   = 1 << lm;
        const int str = 1024 >> lm;
        #pragma unroll
        for (int jj = 0; jj < FFT_R8_IT; jj++) {
            int t = threadIdx.x + jj * FFT_THREADS;
            int q = t & (m - 1);
            int base = ((t >> lm) << (lm + 3)) | q;
            int p0 = PADI(base), p1 = PADI(base + m), p2 = PADI(base + 2 * m),
                p3 = PADI(base + 3 * m), p4 = PADI(base + 4 * m), p5 = PADI(base + 5 * m),
                p6 = PADI(base + 6 * m), p7 = PADI(base + 7 * m);
            float x0r = SR[p0], x0i = SI[p0];
            float x1r = SR[p1], x1i = SI[p1];
            float x2r = SR[p2], x2i = SI[p2];
            float x3r = SR[p3], x3i = SI[p3];
            float x4r = SR[p4], x4i = SI[p4];
            float x5r = SR[p5], x5i = SI[p5];
            float x6r = SR[p6], x6i = SI[p6];
            float x7r = SR[p7], x7i = SI[p7];
            float a0r = x0r + x4r, a0i = x0i + x4i;
            float a1r = x1r + x5r, a1i = x1i + x5i;
            float a2r = x2r + x6r, a2i = x2i + x6i;
            float a3r = x3r + x7r, a3i = x3i + x7i;
            float b0r = x0r - x4r, b0i = x0i - x4i;
            float b1r = x1r - x5r, b1i = x1i - x5i;
            float b2r = x2r - x6r, b2i = x2i - x6i;
            float b3r = x3r - x7r, b3i = x3i - x7i;
            float u1r =  FFT_C * (b1r + b1i), u1i = FFT_C * (b1i - b1r);
            float u2r =  b2i,                 u2i = -b2r;
            float u3r = -FFT_C * (b3r - b3i), u3i = -FFT_C * (b3r + b3i);
            float t0r = a0r + a2r, t0i = a0i + a2i;
            float t1r = a1r + a3r, t1i = a1i + a3i;
            float t2r = a0r - a2r, t2i = a0i - a2i;
            float t3r = a1i - a3i, t3i = a3r - a1r;
            float X0r = t0r + t1r, X0i = t0i + t1i;
            float X2r = t2r + t3r, X2i = t2i + t3i;
            float X4r = t0r - t1r, X4i = t0i - t1i;
            float X6r = t2r - t3r, X6i = t2i - t3i;
            float s0r = b0r + u2r, s0i = b0i + u2i;
            float s1r = u1r + u3r, s1i = u1i + u3i;
            float s2r = b0r - u2r, s2i = b0i - u2i;
            float s3r = u1i - u3i, s3i = u3r - u1r;
            float X1r = s0r + s1r, X1i = s0i + s1i;
            float X3r = s2r + s3r, X3i = s2i + s3i;
            float X5r = s0r - s1r, X5i = s0i - s1i;
            float X7r = s2r - s3r, X7i = s2i - s3i;
            SR[p0] = X0r; SI[p0] = X0i;
            if (lm > 0) {
                int tb = q * str;
                float2 w1 = g_tw[tb],     w2 = g_tw[2 * tb], w3 = g_tw[3 * tb];
                float2 w4 = g_tw[4 * tb], w5 = g_tw[5 * tb], w6 = g_tw[6 * tb];
                float2 w7 = g_tw[7 * tb];
                SR[p1] = X1r * w1.x - X1i * w1.y; SI[p1] = X1r * w1.y + X1i * w1.x;
                SR[p2] = X2r * w2.x - X2i * w2.y; SI[p2] = X2r * w2.y + X2i * w2.x;
                SR[p3] = X3r * w3.x - X3i * w3.y; SI[p3] = X3r * w3.y + X3i * w3.x;
                SR[p4] = X4r * w4.x - X4i * w4.y; SI[p4] = X4r * w4.y + X4i * w4.x;
                SR[p5] = X5r * w5.x - X5i * w5.y; SI[p5] = X5r * w5.y + X5i * w5.x;
                SR[p6] = X6r * w6.x - X6i * w6.y; SI[p6] = X6r * w6.y + X6i * w6.x;
                SR[p7] = X7r * w7.x - X7i * w7.y; SI[p7] = X7r * w7.y + X7i * w7.x;
            } else {
                SR[p1] = X1r; SI[p1] = X1i;
                SR[p2] = X2r; SI[p2] = X2i;
                SR[p3] = X3r; SI[p3] = X3i;
                SR[p4] = X4r; SI[p4] = X4i;
                SR[p5] = X5r; SI[p5] = X5i;
                SR[p6] = X6r; SI[p6] = X6i;
                SR[p7] = X7r; SI[p7] = X7i;
            }
        }
        __syncthreads();
    }
}

__device__ __forceinline__ void fft_inv_half(float* __restrict__ SR, float* __restrict__ SI) {
    #pragma unroll
    for (int s = 0; s < 4; s++) {
        const int lm  = 3 * s;
        const int m   = 1 << lm;
        const int str = 1024 >> lm;
        #pragma unroll
        for (int jj = 0; jj < FFT_R8_IT; jj++) {
            int t = threadIdx.x + jj * FFT_THREADS;
            int q = t & (m - 1);
            int base = ((t >> lm) << (lm + 3)) | q;
            int p0 = PADI(base), p1 = PADI(base + m), p2 = PADI(base + 2 * m),
                p3 = PADI(base + 3 * m), p4 = PADI(base + 4 * m), p5 = PADI(base + 5 * m),
                p6 = PADI(base + 6 * m), p7 = PADI(base + 7 * m);
            float y0r = SR[p0], y0i = SI[p0];
            float y1r = SR[p1], y1i = SI[p1];
            float y2r = SR[p2], y2i = SI[p2];
            float y3r = SR[p3], y3i = SI[p3];
            float y4r = SR[p4], y4i = SI[p4];
            float y5r = SR[p5], y5i = SI[p5];
            float y6r = SR[p6], y6i = SI[p6];
            float y7r = SR[p7], y7i = SI[p7];
            if (lm > 0) {
                int tb = q * str;
                float2 w1 = g_tw[tb],     w2 = g_tw[2 * tb], w3 = g_tw[3 * tb];
                float2 w4 = g_tw[4 * tb], w5 = g_tw[5 * tb], w6 = g_tw[6 * tb];
                float2 w7 = g_tw[7 * tb];
                float cr;
                cr = y1r * w1.x + y1i * w1.y; y1i = y1i * w1.x - y1r * w1.y; y1r = cr;
                cr = y2r * w2.x + y2i * w2.y; y2i = y2i * w2.x - y2r * w2.y; y2r = cr;
                cr = y3r * w3.x + y3i * w3.y; y3i = y3i * w3.x - y3r * w3.y; y3r = cr;
                cr = y4r * w4.x + y4i * w4.y; y4i = y4i * w4.x - y4r * w4.y; y4r = cr;
                cr = y5r * w5.x + y5i * w5.y; y5i = y5i * w5.x - y5r * w5.y; y5r = cr;
                cr = y6r * w6.x + y6i * w6.y; y6i = y6i * w6.x - y6r * w6.y; y6r = cr;
                cr = y7r * w7.x + y7i * w7.y; y7i = y7i * w7.x - y7r * w7.y; y7r = cr;
            }
            float t0r = y0r + y4r, t0i = y0i + y4i;
            float t1r = y2r + y6r, t1i = y2i + y6i;
            float t2r = y0r - y4r, t2i = y0i - y4i;
            float t3r = y6i - y2i, t3i = y2r - y6r;
            float a0r = t0r + t1r, a0i = t0i + t1i;
            float a1r = t2r + t3r, a1i = t2i + t3i;
            float a2r = t0r - t1r, a2i = t0i - t1i;
            float a3r = t2r - t3r, a3i = t2i - t3i;
            float s0r = y1r + y5r, s0i = y1i + y5i;
            float s1r = y3r + y7r, s1i = y3i + y7i;
            float s2r = y1r - y5r, s2i = y1i - y5i;
            float s3r = y7i - y3i, s3i = y3r - y7r;
            float d0r = s0r + s1r, d0i = s0i + s1i;
            float d1r = s2r + s3r, d1i = s2i + s3i;
            float d2r = s0r - s1r, d2i = s0i - s1i;
            float d3r = s2r - s3r, d3i = s2i - s3i;
            float e1r =  FFT_C * (d1r - d1i), e1i = FFT_C * (d1r + d1i);
            float e2r = -d2i,                 e2i = d2r;
            float e3r = -FFT_C * (d3r + d3i), e3i = FFT_C * (d3r - d3i);
            SR[p0] = a0r + d0r; SI[p0] = a0i + d0i;
            SR[p4] = a0r - d0r; SI[p4] = a0i - d0i;
            SR[p1] = a1r + e1r; SI[p1] = a1i + e1i;
            SR[p5] = a1r - e1r; SI[p5] = a1i - e1i;
            SR[p2] = a2r + e2r; SI[p2] = a2i + e2i;
            SR[p6] = a2r - e2r; SI[p6] = a2i - e2i;
            SR[p3] = a3r + e3r; SI[p3] = a3i + e3i;
            SR[p7] = a3r - e3r; SI[p7] = a3i - e3i;
        }
        __syncthreads();
    }
    #pragma unroll
    for (int jj = 0; jj < FFT_ZP_IT; jj++) {
        int j  = threadIdx.x + jj * FFT_THREADS;
        int i0 = PADI(j), i1 = PADI(j + 4096);
        float2 w = g_tw[j];
        float br = SR[i1], bi = SI[i1];
        float tr = br * w.x + bi * w.y;
        float ti = bi * w.x - br * w.y;
        SR[i0] += tr; SI[i0] += ti;
    }
    __syncthreads();
}

// ---------------------------------------------------------------------------
// hfft body: pair-packed H spectra -> A/B tables (k-indexed)
__device__ void hfft_body(float* sm, int c) {
    float* SR = sm;
    float* SI = sm + SM_HALF;
    const int n = c >> 9;
    const int dpair = c & (NPAIR - 1);
    const float* h0 = g_h + ((size_t)n * DDIM + 2 * dpair)     * LSEQ;
    const float* h1 = g_h + ((size_t)n * DDIM + 2 * dpair + 1) * LSEQ;

    for (int i = threadIdx.x; i < LSEQ; i += FFT_THREADS) {
        SR[PADI(i)] = h0[i]; SI[PADI(i)] = h1[i];
    }
    __syncthreads();
    fft_fwd_zp(SR, SI);

    float2* Ao = g_A + (size_t)c * NK;
    float2* Bo = g_B + (size_t)c * NK;
    for (int k = threadIdx.x; k <= LSEQ; k += FFT_THREADS) {
        int p = freq_to_slot(k);
        int q = freq_to_slot((NF - k) & (NF - 1));
        float zpr = SR[PADI(p)], zpi = SI[PADI(p)];
        float zqr = SR[PADI(q)], zqi = SI[PADI(q)];
        float g0r = 0.5f * (zpr + zqr), g0i = 0.5f * (zpi - zqi);
        float g1r = 0.5f * (zpi + zqi), g1i = 0.5f * (zqr - zpr);
        Ao[k] = make_float2(0.5f * (g0r + g1r), 0.5f * (g0i + g1i));
        Bo[k] = make_float2(0.5f * (g0r - g1r), 0.5f * (g0i - g1i));
    }
}

// ---------------------------------------------------------------------------
// Fused launch: hfft (bid < 1024) + gemm_in (bid >= 1024).
#define GI_STAGE 32768
#define GI_SMEM  (3 * GI_STAGE)

__global__ __launch_bounds__(256, 2) void gemm_in_mma(const float* __restrict__ bias)
{
    extern __shared__ char smem[];
    if (blockIdx.x < 2 * NPAIR) {
        hfft_body((float*)smem, blockIdx.x);
        return;
    }
    const int gb = blockIdx.x - 2 * NPAIR;   // 0..1535
    const uint32_t sb = smem_u32(smem);
    const int tid  = threadIdx.x;
    const int lane = tid & 31;
    const int wid  = tid >> 5;
    const int warp_m = wid >> 2;
    const int warp_n = wid & 3;

    const int b   = gb / 768;
    const int rem = gb % 768;
    const int m0  = (rem / 32) * 128;   // od
    const int n0  = (rem % 32) * 128;   // l
    float* C = g_res + (size_t)b * ODIM * LSEQ;

    const int tile = tid >> 6;
    const int tloc = tid & 63;
    const char* gbase;
    if      (tile == 0) gbase = (const char*)g_wh + (size_t)m0 * 2048;
    else if (tile == 1) gbase = (const char*)g_wl + (size_t)m0 * 2048;
    else if (tile == 2) gbase = (const char*)g_uh + (size_t)(b * LSEQ + n0) * 2048;
    else                gbase = (const char*)g_ul + (size_t)(b * LSEQ + n0) * 2048;

    float acc[4][4][4];
    #pragma unroll
    for (int i = 0; i < 4; i++)
        #pragma unroll
        for (int j = 0; j < 4; j++)
            #pragma unroll
            for (int r = 0; r < 4; r++) acc[i][j][r] = 0.0f;

    const int ar  = (lane & 7) + ((lane & 8) ? 8 : 0);
    const int sA  = (ar >> 1) & 3;
    const int a16 = (lane & 16) ? 1 : 0;
    const int br  = lane & 7;
    const int sB  = (br >> 1) & 3;
    const int b16 = (lane & 8) ? 1 : 0;

    #pragma unroll
    for (int p = 0; p < 2; p++) {
        #pragma unroll
        for (int o = 0; o < 8; o++) {
            int idx = tloc + o * 64, row = idx >> 2, c = idx & 3;
            uint32_t dst = sb + p * GI_STAGE + tile * 8192 + row * 64
                         + (((c ^ ((row >> 1) & 3))) << 4);
            CP_ASYNC16(dst, gbase + (size_t)row * 2048 + p * 64 + c * 16);
        }
        CP_COMMIT();
    }

    for (int ch = 0; ch < 32; ch++) {
        CP_WAIT1();
        __syncthreads();
        if (ch + 2 < 32) {
            const int st = (ch + 2) % 3;
            #pragma unroll
            for (int o = 0; o < 8; o++) {
                int idx = tloc + o * 64, row = idx >> 2, c = idx & 3;
                uint32_t dst = sb + st * GI_STAGE + tile * 8192 + row * 64
                             + (((c ^ ((row >> 1) & 3))) << 4);
                CP_ASYNC16(dst, gbase + (size_t)row * 2048 + (ch + 2) * 64 + c * 16);
            }
        }
        CP_COMMIT();

        const uint32_t sbase = sb + (ch % 3) * GI_STAGE;
        #pragma unroll
        for (int k16 = 0; k16 < 2; k16++) {
            uint32_t bh[4][2], bl[4][2];
            #pragma unroll
            for (int j = 0; j < 4; j++) {
                uint32_t rb = sbase + 16384 + (warp_n * 32 + j * 8 + br) * 64
                            + (((k16 * 2 + b16) ^ sB) << 4);
                LDSM_X2(bh[j][0], bh[j][1], rb);
                LDSM_X2(bl[j][0], bl[j][1], rb + 8192);
            }
            uint32_t ah[2][4], al[2][4];
            {
                uint32_t ra = sbase + (warp_m * 64 + ar) * 64
                            + (((k16 * 2 + a16) ^ sA) << 4);
                LDSM_X4(ah[0][0], ah[0][1], ah[0][2], ah[0][3], ra);
                LDSM_X4(al[0][0], al[0][1], al[0][2], al[0][3], ra + 8192);
            }
            #pragma unroll
            for (int i = 0; i < 4; i++) {
                const int cur = i & 1;
                if (i < 3) {
                    const int nxt = cur ^ 1;
                    uint32_t ra = sbase + (warp_m * 64 + (i + 1) * 16 + ar) * 64
                                + (((k16 * 2 + a16) ^ sA) << 4);
                    LDSM_X4(ah[nxt][0], ah[nxt][1], ah[nxt][2], ah[nxt][3], ra);
                    LDSM_X4(al[nxt][0], al[nxt][1], al[nxt][2], al[nxt][3], ra + 8192);
                }
                #pragma unroll
                for (int j = 0; j < 4; j++) {
                    mma_bf16(acc[i][j], ah[cur], bh[j]);
                    mma_bf16(acc[i][j], ah[cur], bl[j]);
                    mma_bf16(acc[i][j], al[cur], bh[j]);
                }
            }
        }
    }

    const int g = lane >> 2;
    const int t = lane & 3;
    #pragma unroll
    for (int i = 0; i < 4; i++) {
        int od0 = m0 + warp_m * 64 + i * 16 + g;
        float bv0 = bias[od0];
        float bv1 = bias[od0 + 8];
        #pragma unroll
        for (int j = 0; j < 4; j++) {
            int l = n0 + warp_n * 32 + j * 8 + t * 2;
            *(float2*)&C[(size_t)od0 * LSEQ + l] =
                make_float2(acc[i][j][0] + bv0, acc[i][j][1] + bv0);
            *(float2*)&C[(size_t)(od0 + 8) * LSEQ + l] =
                make_float2(acc[i][j][2] + bv1, acc[i][j][3] + bv1);
        }
    }
}

// ---------------------------------------------------------------------------
// gemm_out: out[b,l,e] = sum_d v[b,d,l]*w_out[e,d] + b_out[e]
#define GO_STAGE 32768
#define GO_SMEM  (3 * GO_STAGE)

__global__ __launch_bounds__(256, 2) void gemm_out_mma(const float* __restrict__ bias,
                                                       float* __restrict__ O)
{
    extern __shared__ char smem[];
    const uint32_t sb = smem_u32(smem);
    const int tid  = threadIdx.x;
    const int lane = tid & 31;
    const int wid  = tid >> 5;
    const int warp_m = wid >> 2;
    const int warp_n = wid & 3;

    const int b  = blockIdx.z;
    const int m0 = blockIdx.y * 128;   // l
    const int n0 = blockIdx.x * 128;   // e
    float* C = O + (size_t)b * LSEQ * DDIM;

    const int tile = tid >> 6;
    const int tloc = tid & 63;
    const char* gbase;
    if      (tile == 0) gbase = (const char*)g_vh + (size_t)(b * DDIM) * 8192 + (size_t)m0 * 2;
    else if (tile == 1) gbase = (const char*)g_vl + (size_t)(b * DDIM) * 8192 + (size_t)m0 * 2;
    else if (tile == 2) gbase = (const char*)g_oh + (size_t)n0 * 2048;
    else                gbase = (const char*)g_ol + (size_t)n0 * 2048;

    float acc[4][4][4];
    #pragma unroll
    for (int i = 0; i < 4; i++)
        #pragma unroll
        for (int j = 0; j < 4; j++)
            #pragma unroll
            for (int r = 0; r < 4; r++) acc[i][j][r] = 0.0f;

    const int tr  = (lane & 7) + ((lane & 16) ? 8 : 0);
    const int sT  = lane & 7;
    const int t16 = (lane & 8) ? 1 : 0;
    const int br  = lane & 7;
    const int sB  = (br >> 1) & 3;
    const int b16 = (lane & 8) ? 1 : 0;

    #pragma unroll
    for (int p = 0; p < 2; p++) {
        if (tile < 2) {
            #pragma unroll
            for (int o = 0; o < 8; o++) {
                int idx = tloc + o * 64, row = idx >> 4, c16 = idx & 15;
                uint32_t dst = sb + p * GO_STAGE + tile * 8192 + row * 256
                             + (((c16 ^ (row & 7))) << 4);
                CP_ASYNC16(dst, gbase + (size_t)(p * 32 + row) * 8192 + c16 * 16);
            }
        } else {
            #pragma unroll
            for (int o = 0; o < 8; o++) {
                int idx = tloc + o * 64, row = idx >> 2, c = idx & 3;
                uint32_t dst = sb + p * GO_STAGE + (tile - 2) * 8192 + 16384 + row * 64
                             + (((c ^ ((row >> 1) & 3))) << 4);
                CP_ASYNC16(dst, gbase + (size_t)row * 2048 + p * 64 + c * 16);
            }
        }
        CP_COMMIT();
    }

    for (int ch = 0; ch < 32; ch++) {
        CP_WAIT1();
        __syncthreads();
        if (ch + 2 < 32) {
            const int st = (ch + 2) % 3;
            if (tile < 2) {
                #pragma unroll
                for (int o = 0; o < 8; o++) {
                    int idx = tloc + o * 64, row = idx >> 4, c16 = idx & 15;
                    uint32_t dst = sb + st * GO_STAGE + tile * 8192 + row * 256
                                 + (((c16 ^ (row & 7))) << 4);
                    CP_ASYNC16(dst, gbase + (size_t)((ch + 2) * 32 + row) * 8192 + c16 * 16);
                }
            } else {
                #pragma unroll
                for (int o = 0; o < 8; o++) {
                    int idx = tloc + o * 64, row = idx >> 2, c = idx & 3;
                    uint32_t dst = sb + st * GO_STAGE + (tile - 2) * 8192 + 16384 + row * 64
                                 + (((c ^ ((row >> 1) & 3))) << 4);
                    CP_ASYNC16(dst, gbase + (size_t)row * 2048 + (ch + 2) * 64 + c * 16);
                }
            }
        }
        CP_COMMIT();

        const uint32_t sbase = sb + (ch % 3) * GO_STAGE;
        #pragma unroll
        for (int k16 = 0; k16 < 2; k16++) {
            uint32_t bh[4][2], bl[4][2];
            #pragma unroll
            for (int j = 0; j < 4; j++) {
                uint32_t rb = sbase + 16384 + (warp_n * 32 + j * 8 + br) * 64
                            + (((k16 * 2 + b16) ^ sB) << 4);
                LDSM_X2(bh[j][0], bh[j][1], rb);
                LDSM_X2(bl[j][0], bl[j][1], rb + 8192);
            }
            uint32_t ah[2][4], al[2][4];
            {
                int rowd = k16 * 16 + tr;
                uint32_t ra = sbase + rowd * 256 + (((warp_m * 8 + t16) ^ sT) << 4);
                LDSM_X4_T(ah[0][0], ah[0][1], ah[0][2], ah[0][3], ra);
                LDSM_X4_T(al[0][0], al[0][1], al[0][2], al[0][3], ra + 8192);
            }
            #pragma unroll
            for (int i = 0; i < 4; i++) {
                const int cur = i & 1;
                if (i < 3) {
                    const int nxt = cur ^ 1;
                    int rowd = k16 * 16 + tr;
                    uint32_t ra = sbase + rowd * 256
                                + (((warp_m * 8 + (i + 1) * 2 + t16) ^ sT) << 4);
                    LDSM_X4_T(ah[nxt][0], ah[nxt][1], ah[nxt][2], ah[nxt][3], ra);
                    LDSM_X4_T(al[nxt][0], al[nxt][1], al[nxt][2], al[nxt][3], ra + 8192);
                }
                #pragma unroll
                for (int j = 0; j < 4; j++) {
                    mma_bf16(acc[i][j], ah[cur], bh[j]);
                    mma_bf16(acc[i][j], ah[cur], bl[j]);
                    mma_bf16(acc[i][j], al[cur], bh[j]);
                }
            }
        }
    }

    const int g = lane >> 2;
    const int t = lane & 3;
    #pragma unroll
    for (int j = 0; j < 4; j++) {
        int e = n0 + warp_n * 32 + j * 8 + t * 2;
        float bb0 = bias[e];
        float bb1 = bias[e + 1];
        #pragma unroll
        for (int i = 0; i < 4; i++) {
            int l = m0 + warp_m * 64 + i * 16 + g;
            *(float2*)&C[(size_t)l * DDIM + e] =
                make_float2(acc[i][j][0] + bb0, acc[i][j][1] + bb1);
            *(float2*)&C[(size_t)(l + 8) * DDIM + e] =
                make_float2(acc[i][j][2] + bb0, acc[i][j][3] + bb1);
        }
    }
}

// ---------------------------------------------------------------------------
__device__ __forceinline__ float conv3_at(const float* __restrict__ r, int l,
                                          float w0, float w1, float w2, float cb) {
    float left  = (l > 0)        ? r[l - 1] : 0.0f;
    float right = (l < LSEQ - 1) ? r[l + 1] : 0.0f;
    return w0 * left + w1 * r[l] + w2 * right + cb;
}

__global__ __launch_bounds__(FFT_THREADS, 3) void fftconv_kernel(
    const float* __restrict__ cw, const float* __restrict__ cbv)
{
    extern __shared__ float sm[];
    float* SR = sm;
    float* SI = sm + SM_HALF;
    const int c = blockIdx.x;
    const int b = c >> 9;
    const int dpair = c & (NPAIR - 1);
    const int ch0 = 2 * dpair, ch1 = ch0 + 1;
    const float inv = 1.0f / (float)NF;

    {
        const float* r2a = g_res + ((size_t)(b * 3 + 2) * DDIM + ch0) * LSEQ;
        const float* r2b = g_res + ((size_t)(b * 3 + 2) * DDIM + ch1) * LSEQ;
        const int oa = 2 * DDIM + ch0, ob = 2 * DDIM + ch1;
        float w0a = cw[oa * 3], w1a = cw[oa * 3 + 1], w2a = cw[oa * 3 + 2], cba = cbv[oa];
        float w0b = cw[ob * 3], w1b = cw[ob * 3 + 1], w2b = cw[ob * 3 + 2], cbb = cbv[ob];
        for (int i = threadIdx.x; i < LSEQ; i += FFT_THREADS) {
            SR[PADI(i)] = conv3_at(r2a, i, w0a, w1a, w2a, cba);
            SI[PADI(i)] = conv3_at(r2b, i, w0b, w1b, w2b, cbb);
        }
    }
    __syncthreads();

    #pragma unroll 1
    for (int n = 0; n < 2; n++) {
        fft_fwd_zp(SR, SI);

        const float2* Ap = g_A + ((size_t)n * NPAIR + dpair) * NK;
        const float2* Bp = g_B + ((size_t)n * NPAIR + dpair) * NK;
        for (int k = threadIdx.x; k <= LSEQ; k += FFT_THREADS) {
            int p = freq_to_slot(k);
            int q = freq_to_slot((NF - k) & (NF - 1));
            int ip = PADI(p), iq = PADI(q);
            float zr = SR[ip], zi = SI[ip];
            float wr = SR[iq], wi = SI[iq];
            float2 a  = Ap[k];
            float2 bb = Bp[k];
            float ypr = a.x * zr - a.y * zi + bb.x * wr + bb.y * wi;
            float ypi = a.x * zi + a.y * zr + bb.y * wr - bb.x * wi;
            SR[ip] = ypr; SI[ip] = ypi;
            if (q != p) {
                float yqr = a.x * wr + a.y * wi + bb.x * zr - bb.y * zi;
                float yqi = a.x * wi - a.y * wr - bb.x * zi - bb.y * zr;
                SR[iq] = yqr; SI[iq] = yqi;
            }
        }
        __syncthreads();

        fft_inv_half(SR, SI);

        const float* rna = g_res + ((size_t)(b * 3 + n) * DDIM + ch0) * LSEQ;
        const float* rnb = g_res + ((size_t)(b * 3 + n) * DDIM + ch1) * LSEQ;
        const int oa = n * DDIM + ch0, ob = n * DDIM + ch1;
        float w0a = cw[oa * 3], w1a = cw[oa * 3 + 1], w2a = cw[oa * 3 + 2], cba = cbv[oa];
        float w0b = cw[ob * 3], w1b = cw[ob * 3 + 1], w2b = cw[ob * 3 + 2], cbb = cbv[ob];

        if (n == 0) {
            for (int l = threadIdx.x; l < LSEQ; l += FFT_THREADS) {
                int ip = PADI(l);
                SR[ip] = SR[ip] * inv * conv3_at(rna, l, w0a, w1a, w2a, cba);
                SI[ip] = SI[ip] * inv * conv3_at(rnb, l, w0b, w1b, w2b, cbb);
            }
            __syncthreads();
        } else {
            uint32_t* vh0 = g_vh + ((size_t)(b * DDIM + ch0)) * (LSEQ / 2);
            uint32_t* vl0 = g_vl + ((size_t)(b * DDIM + ch0)) * (LSEQ / 2);
            uint32_t* vh1 = g_vh + ((size_t)(b * DDIM + ch1)) * (LSEQ / 2);
            uint32_t* vl1 = g_vl + ((size_t)(b * DDIM + ch1)) * (LSEQ / 2);
            for (int l2 = threadIdx.x; l2 < LSEQ / 2; l2 += FFT_THREADS) {
                int l = 2 * l2;
                float y0a = SR[PADI(l)]     * inv * conv3_at(rna, l,     w0a, w1a, w2a, cba);
                float y0b = SR[PADI(l + 1)] * inv * conv3_at(rna, l + 1, w0a, w1a, w2a, cba);
                float y1a = SI[PADI(l)]     * inv * conv3_at(rnb, l,     w0b, w1b, w2b, cbb);
                float y1b = SI[PADI(l + 1)] * inv * conv3_at(rnb, l + 1, w0b, w1b, w2b, cbb);
                vh0[l2] = pack_hi(y0a, y0b); vl0[l2] = pack_lo(y0a, y0b);
                vh1[l2] = pack_hi(y1a, y1b); vl1[l2] = pack_lo(y1a, y1b);
            }
        }
    }
}

// ---------------------------------------------------------------------------
extern "C" void kernel_launch(void* const* d_in, const int* in_sizes, int n_in,
                              void* d_out, int out_size)
{
    const float* u          = (const float*)d_in[0];
    const float* w_in       = (const float*)d_in[1];
    const float* b_in       = (const float*)d_in[2];
    const float* conv_w     = (const float*)d_in[3];
    const float* conv_b     = (const float*)d_in[4];
    const float* w1         = (const float*)d_in[5];
    const float* b1         = (const float*)d_in[6];
    const float* w2         = (const float*)d_in[7];
    const float* b2         = (const float*)d_in[8];
    const float* filt_bias  = (const float*)d_in[9];
    const float* filt_decay = (const float*)d_in[10];
    const float* w_out      = (const float*)d_in[11];
    const float* b_out      = (const float*)d_in[12];
    float* out = (float*)d_out;

    static bool attr_set = false;
    if (!attr_set) {
        cudaFuncSetAttribute(fftconv_kernel, cudaFuncAttributeMaxDynamicSharedMemorySize, FFT_SMEM);
        cudaFuncSetAttribute(gemm_in_mma,    cudaFuncAttributeMaxDynamicSharedMemorySize, GI_SMEM);
        cudaFuncSetAttribute(gemm_out_mma,   cudaFuncAttributeMaxDynamicSharedMemorySize, GO_SMEM);
        cudaFuncSetAttribute(filter_gemm,    cudaFuncAttributeMaxDynamicSharedMemorySize, 65536);
        attr_set = true;
    }

    // 1: prep — conversions + twiddles + sact
    prep_kernel<<<PREP_GRID, 256>>>(w_in, u, w_out, w1, b1);
    // 2: filter GEMM (produces g_h)
    filter_gemm<<<512, 256, 65536>>>(w2, b2, filt_bias, filt_decay);
    // 3: hfft (1024 CTAs) fused with gemm_in (1536 CTAs)
    gemm_in_mma<<<2 * NPAIR + 1536, 256, GI_SMEM>>>(b_in);
    // 4: fftconv (profiled slot, 3 CTAs/SM)
    fftconv_kernel<<<BSZ * NPAIR, FFT_THREADS, FFT_SMEM>>>(conv_w, conv_b);
    // 5: output GEMM
    gemm_out_mma<<<dim3(DDIM / 128, LSEQ / 128, BSZ), 256, GO_SMEM>>>(b_out, out);
}